// round 1
// baseline (speedup 1.0000x reference)
#include <cuda_runtime.h>
#include <math.h>

// Problem constants
#define B    8
#define C    512
#define HW   1024
#define G    32
#define CPG  16        // channels per group
#define HEADS 8
#define DH   64
#define EPS  1e-5f

// ---------------- scratch (device globals; no runtime allocation) -----------
__device__ float g_xn [B * C * HW];              // 16 MB  group-normed x
__device__ float g_qkv[B * 3 * C * HW];          // 48 MB  [b][3][heads][dh][hw]
__device__ float g_S  [(size_t)B * HEADS * HW * HW]; // 256 MB attention logits/probs
__device__ float g_ao [B * C * HW];              // 16 MB  attention output

// ---------------- GroupNorm ------------------------------------------------
__global__ __launch_bounds__(256) void gn_kernel(const float* __restrict__ x,
                                                 const float* __restrict__ gw,
                                                 const float* __restrict__ gb) {
    int bg = blockIdx.x;          // 0 .. B*G-1
    int bi = bg / G;
    int g  = bg % G;
    const float* xp = x + ((size_t)bi * C + (size_t)g * CPG) * HW;
    float* op = g_xn + ((size_t)bi * C + (size_t)g * CPG) * HW;

    const int N = CPG * HW;       // 16384
    float s = 0.f, s2 = 0.f;
    for (int i = threadIdx.x; i < N; i += 256) {
        float v = xp[i];
        s  += v;
        s2 += v * v;
    }
    __shared__ float sh1[8], sh2[8];
    int lane = threadIdx.x & 31, wid = threadIdx.x >> 5;
    for (int o = 16; o; o >>= 1) {
        s  += __shfl_down_sync(0xffffffffu, s,  o);
        s2 += __shfl_down_sync(0xffffffffu, s2, o);
    }
    if (lane == 0) { sh1[wid] = s; sh2[wid] = s2; }
    __syncthreads();
    if (threadIdx.x < 8) {
        s = sh1[threadIdx.x]; s2 = sh2[threadIdx.x];
        for (int o = 4; o; o >>= 1) {
            s  += __shfl_down_sync(0xffu, s,  o);
            s2 += __shfl_down_sync(0xffu, s2, o);
        }
        if (threadIdx.x == 0) { sh1[0] = s; sh2[0] = s2; }
    }
    __syncthreads();
    float mean = sh1[0] * (1.f / N);
    float var  = sh2[0] * (1.f / N) - mean * mean;
    float inv  = rsqrtf(var + EPS);

    for (int i = threadIdx.x; i < N; i += 256) {
        int ch = g * CPG + (i >> 10);
        op[i] = (xp[i] - mean) * inv * gw[ch] + gb[ch];
    }
}

// ---------------- QKV GEMM: out[b,m,n] = sum_k W[m,k] * xn[b,k,n] + bias[m]
// M=1536, K=512, N=1024
__global__ __launch_bounds__(256) void qkv_kernel(const float* __restrict__ W,
                                                  const float* __restrict__ bias) {
    __shared__ float As[16][64];
    __shared__ float Bs[16][64];
    int n0 = blockIdx.x * 64, m0 = blockIdx.y * 64, bi = blockIdx.z;
    const float* Xb = g_xn + (size_t)bi * C * HW;
    float* Ob       = g_qkv + (size_t)bi * 3 * C * HW;
    int tid = threadIdx.x;
    int tx = tid & 15, ty = tid >> 4;

    float acc[4][4] = {};
    for (int k0 = 0; k0 < C; k0 += 16) {
        { // A tile: As[k][m] = W[(m0+m)*C + k0+k]
            int m = tid >> 2, kq = (tid & 3) << 2;
            float4 a = *(const float4*)&W[(size_t)(m0 + m) * C + k0 + kq];
            As[kq + 0][m] = a.x; As[kq + 1][m] = a.y;
            As[kq + 2][m] = a.z; As[kq + 3][m] = a.w;
        }
        { // B tile: Bs[k][n] = Xb[(k0+k)*HW + n0+n]
            int k = tid >> 4, nq = (tid & 15) << 2;
            *(float4*)&Bs[k][nq] = *(const float4*)&Xb[(size_t)(k0 + k) * HW + n0 + nq];
        }
        __syncthreads();
#pragma unroll
        for (int kk = 0; kk < 16; kk++) {
            float4 a = *(float4*)&As[kk][ty << 2];
            float4 b = *(float4*)&Bs[kk][tx << 2];
            acc[0][0] += a.x * b.x; acc[0][1] += a.x * b.y; acc[0][2] += a.x * b.z; acc[0][3] += a.x * b.w;
            acc[1][0] += a.y * b.x; acc[1][1] += a.y * b.y; acc[1][2] += a.y * b.z; acc[1][3] += a.y * b.w;
            acc[2][0] += a.z * b.x; acc[2][1] += a.z * b.y; acc[2][2] += a.z * b.z; acc[2][3] += a.z * b.w;
            acc[3][0] += a.w * b.x; acc[3][1] += a.w * b.y; acc[3][2] += a.w * b.z; acc[3][3] += a.w * b.w;
        }
        __syncthreads();
    }
#pragma unroll
    for (int i = 0; i < 4; i++) {
        int m = m0 + (ty << 2) + i;
        float bm = bias[m];
        float4 r = make_float4(acc[i][0] + bm, acc[i][1] + bm, acc[i][2] + bm, acc[i][3] + bm);
        *(float4*)&Ob[(size_t)m * HW + n0 + (tx << 2)] = r;
    }
}

// ---------------- S = scale * q^T k  per (b,h).  M=N=1024, K=64 -------------
__global__ __launch_bounds__(256) void sgemm_kernel() {
    __shared__ float As[16][64];
    __shared__ float Bs[16][64];
    int n0 = blockIdx.x * 64, m0 = blockIdx.y * 64;
    int bh = blockIdx.z;                 // b*HEADS + h
    int bi = bh >> 3, h = bh & 7;
    const float* q = g_qkv + ((((size_t)bi * 3 + 0) * HEADS + h) * DH) * HW;
    const float* k = g_qkv + ((((size_t)bi * 3 + 1) * HEADS + h) * DH) * HW;
    float* Sp = g_S + (size_t)bh * HW * HW;
    int tid = threadIdx.x;
    int tx = tid & 15, ty = tid >> 4;

    float acc[4][4] = {};
    for (int k0 = 0; k0 < DH; k0 += 16) {
        { // A tile: As[kk][m] = q[(k0+kk)*HW + m0+m]   (contiguous in m)
            int kk = tid >> 4, mq = (tid & 15) << 2;
            *(float4*)&As[kk][mq] = *(const float4*)&q[(size_t)(k0 + kk) * HW + m0 + mq];
        }
        { // B tile: Bs[kk][n] = k[(k0+kk)*HW + n0+n]
            int kk = tid >> 4, nq = (tid & 15) << 2;
            *(float4*)&Bs[kk][nq] = *(const float4*)&k[(size_t)(k0 + kk) * HW + n0 + nq];
        }
        __syncthreads();
#pragma unroll
        for (int kk = 0; kk < 16; kk++) {
            float4 a = *(float4*)&As[kk][ty << 2];
            float4 b = *(float4*)&Bs[kk][tx << 2];
            acc[0][0] += a.x * b.x; acc[0][1] += a.x * b.y; acc[0][2] += a.x * b.z; acc[0][3] += a.x * b.w;
            acc[1][0] += a.y * b.x; acc[1][1] += a.y * b.y; acc[1][2] += a.y * b.z; acc[1][3] += a.y * b.w;
            acc[2][0] += a.z * b.x; acc[2][1] += a.z * b.y; acc[2][2] += a.z * b.z; acc[2][3] += a.z * b.w;
            acc[3][0] += a.w * b.x; acc[3][1] += a.w * b.y; acc[3][2] += a.w * b.z; acc[3][3] += a.w * b.w;
        }
        __syncthreads();
    }
    const float scale = 0.125f;  // 1/sqrt(64)
#pragma unroll
    for (int i = 0; i < 4; i++) {
        int m = m0 + (ty << 2) + i;
        float4 r = make_float4(acc[i][0] * scale, acc[i][1] * scale,
                               acc[i][2] * scale, acc[i][3] * scale);
        *(float4*)&Sp[(size_t)m * HW + n0 + (tx << 2)] = r;
    }
}

// ---------------- row softmax over 1024 -------------------------------------
__global__ __launch_bounds__(256) void softmax_kernel() {
    float* row = g_S + (size_t)blockIdx.x * HW;
    float4 v = ((float4*)row)[threadIdx.x];   // 256 threads * 4 = 1024 exactly
    float m = fmaxf(fmaxf(v.x, v.y), fmaxf(v.z, v.w));
    __shared__ float sh[8];
    int lane = threadIdx.x & 31, wid = threadIdx.x >> 5;
    for (int o = 16; o; o >>= 1) m = fmaxf(m, __shfl_down_sync(0xffffffffu, m, o));
    if (lane == 0) sh[wid] = m;
    __syncthreads();
    if (threadIdx.x < 8) {
        m = sh[threadIdx.x];
        for (int o = 4; o; o >>= 1) m = fmaxf(m, __shfl_down_sync(0xffu, m, o));
        if (threadIdx.x == 0) sh[0] = m;
    }
    __syncthreads();
    m = sh[0];
    __syncthreads();

    v.x = expf(v.x - m); v.y = expf(v.y - m);
    v.z = expf(v.z - m); v.w = expf(v.w - m);
    float s = v.x + v.y + v.z + v.w;
    for (int o = 16; o; o >>= 1) s += __shfl_down_sync(0xffffffffu, s, o);
    if (lane == 0) sh[wid] = s;
    __syncthreads();
    if (threadIdx.x < 8) {
        s = sh[threadIdx.x];
        for (int o = 4; o; o >>= 1) s += __shfl_down_sync(0xffu, s, o);
        if (threadIdx.x == 0) sh[0] = s;
    }
    __syncthreads();
    float inv = 1.f / sh[0];
    v.x *= inv; v.y *= inv; v.z *= inv; v.w *= inv;
    ((float4*)row)[threadIdx.x] = v;
}

// ---------------- O[d,i] = sum_j V[d,j] * P[i,j]  per (b,h). M=64,N=1024,K=1024
__global__ __launch_bounds__(256) void av_kernel() {
    __shared__ float As[16][64];
    __shared__ float Bs[16][64];
    int n0 = blockIdx.x * 64;
    int bh = blockIdx.z;
    int bi = bh >> 3, h = bh & 7;
    const float* v  = g_qkv + ((((size_t)bi * 3 + 2) * HEADS + h) * DH) * HW;
    const float* Sp = g_S + (size_t)bh * HW * HW;
    float* Op = g_ao + ((size_t)bi * C + (size_t)h * DH) * HW;
    int tid = threadIdx.x;
    int tx = tid & 15, ty = tid >> 4;

    float acc[4][4] = {};
    for (int k0 = 0; k0 < HW; k0 += 16) {
        { // A tile: As[k][m] = v[m*HW + k0+k]
            int m = tid >> 2, kq = (tid & 3) << 2;
            float4 a = *(const float4*)&v[(size_t)m * HW + k0 + kq];
            As[kq + 0][m] = a.x; As[kq + 1][m] = a.y;
            As[kq + 2][m] = a.z; As[kq + 3][m] = a.w;
        }
        { // B tile: Bs[k][n] = P[(n0+n)*HW + k0+k]  (P row-major over j)
            int n = tid >> 2, kq = (tid & 3) << 2;
            float4 b = *(const float4*)&Sp[(size_t)(n0 + n) * HW + k0 + kq];
            Bs[kq + 0][n] = b.x; Bs[kq + 1][n] = b.y;
            Bs[kq + 2][n] = b.z; Bs[kq + 3][n] = b.w;
        }
        __syncthreads();
#pragma unroll
        for (int kk = 0; kk < 16; kk++) {
            float4 a = *(float4*)&As[kk][ty << 2];
            float4 b = *(float4*)&Bs[kk][tx << 2];
            acc[0][0] += a.x * b.x; acc[0][1] += a.x * b.y; acc[0][2] += a.x * b.z; acc[0][3] += a.x * b.w;
            acc[1][0] += a.y * b.x; acc[1][1] += a.y * b.y; acc[1][2] += a.y * b.z; acc[1][3] += a.y * b.w;
            acc[2][0] += a.z * b.x; acc[2][1] += a.z * b.y; acc[2][2] += a.z * b.z; acc[2][3] += a.z * b.w;
            acc[3][0] += a.w * b.x; acc[3][1] += a.w * b.y; acc[3][2] += a.w * b.z; acc[3][3] += a.w * b.w;
        }
        __syncthreads();
    }
#pragma unroll
    for (int i = 0; i < 4; i++) {
        int m = (ty << 2) + i;     // d within head
        *(float4*)&Op[(size_t)m * HW + n0 + (tx << 2)] =
            make_float4(acc[i][0], acc[i][1], acc[i][2], acc[i][3]);
    }
}

// ---------------- proj + residual: out[b,m,n] = x + sum_k PW[m,k]*ao[b,k,n] + pb[m]
__global__ __launch_bounds__(256) void proj_kernel(const float* __restrict__ PW,
                                                   const float* __restrict__ pb,
                                                   const float* __restrict__ x,
                                                   float* __restrict__ out) {
    __shared__ float As[16][64];
    __shared__ float Bs[16][64];
    int n0 = blockIdx.x * 64, m0 = blockIdx.y * 64, bi = blockIdx.z;
    const float* Xb = g_ao + (size_t)bi * C * HW;
    int tid = threadIdx.x;
    int tx = tid & 15, ty = tid >> 4;

    float acc[4][4] = {};
    for (int k0 = 0; k0 < C; k0 += 16) {
        {
            int m = tid >> 2, kq = (tid & 3) << 2;
            float4 a = *(const float4*)&PW[(size_t)(m0 + m) * C + k0 + kq];
            As[kq + 0][m] = a.x; As[kq + 1][m] = a.y;
            As[kq + 2][m] = a.z; As[kq + 3][m] = a.w;
        }
        {
            int k = tid >> 4, nq = (tid & 15) << 2;
            *(float4*)&Bs[k][nq] = *(const float4*)&Xb[(size_t)(k0 + k) * HW + n0 + nq];
        }
        __syncthreads();
#pragma unroll
        for (int kk = 0; kk < 16; kk++) {
            float4 a = *(float4*)&As[kk][ty << 2];
            float4 b = *(float4*)&Bs[kk][tx << 2];
            acc[0][0] += a.x * b.x; acc[0][1] += a.x * b.y; acc[0][2] += a.x * b.z; acc[0][3] += a.x * b.w;
            acc[1][0] += a.y * b.x; acc[1][1] += a.y * b.y; acc[1][2] += a.y * b.z; acc[1][3] += a.y * b.w;
            acc[2][0] += a.z * b.x; acc[2][1] += a.z * b.y; acc[2][2] += a.z * b.z; acc[2][3] += a.z * b.w;
            acc[3][0] += a.w * b.x; acc[3][1] += a.w * b.y; acc[3][2] += a.w * b.z; acc[3][3] += a.w * b.w;
        }
        __syncthreads();
    }
#pragma unroll
    for (int i = 0; i < 4; i++) {
        int m = m0 + (ty << 2) + i;
        float bm = pb[m];
        size_t off = ((size_t)bi * C + m) * HW + n0 + (tx << 2);
        float4 r = *(const float4*)&x[off];
        r.x += acc[i][0] + bm; r.y += acc[i][1] + bm;
        r.z += acc[i][2] + bm; r.w += acc[i][3] + bm;
        *(float4*)&out[off] = r;
    }
}

// ---------------- launch -----------------------------------------------------
extern "C" void kernel_launch(void* const* d_in, const int* in_sizes, int n_in,
                              void* d_out, int out_size) {
    const float* x      = (const float*)d_in[0];
    const float* gn_w   = (const float*)d_in[1];
    const float* gn_b   = (const float*)d_in[2];
    const float* qkv_w  = (const float*)d_in[3];
    const float* qkv_b  = (const float*)d_in[4];
    const float* proj_w = (const float*)d_in[5];
    const float* proj_b = (const float*)d_in[6];
    float* out = (float*)d_out;

    gn_kernel<<<B * G, 256>>>(x, gn_w, gn_b);
    qkv_kernel<<<dim3(HW / 64, 3 * C / 64, B), 256>>>(qkv_w, qkv_b);
    sgemm_kernel<<<dim3(HW / 64, HW / 64, B * HEADS), 256>>>();
    softmax_kernel<<<B * HEADS * HW, 256>>>();
    av_kernel<<<dim3(HW / 64, 1, B * HEADS), 256>>>();
    proj_kernel<<<dim3(HW / 64, C / 64, B), 256>>>(proj_w, proj_b, x, out);
}

// round 3
// speedup vs baseline: 1.8377x; 1.8377x over previous
#include <cuda_runtime.h>
#include <cuda_bf16.h>
#include <cstdint>
#include <math.h>

#define B    8
#define C    512
#define HW   1024
#define G    32
#define CPG  16
#define HEADS 8
#define DH   64
#define EPS  1e-5f

typedef __nv_bfloat16 bf16;

// ---------------- scratch (device globals) ----------------------------------
__device__ float g_xn [B * C * HW];
__device__ float g_qkv[B * 3 * C * HW];
__device__ float g_S  [(size_t)B * HEADS * HW * HW];
__device__ float g_ao [B * C * HW];

__device__ bf16 g_WhiQ[3 * C * C], g_WloQ[3 * C * C];
__device__ bf16 g_WhiP[C * C],     g_WloP[C * C];
__device__ bf16 g_XTh [B * HW * C], g_XTl [B * HW * C];   // [b][n][c]
__device__ bf16 g_AOTh[B * HW * C], g_AOTl[B * HW * C];
__device__ bf16 g_qTh [B * HEADS * HW * DH], g_qTl[B * HEADS * HW * DH]; // [bh][i][d]
__device__ bf16 g_kTh [B * HEADS * HW * DH], g_kTl[B * HEADS * HW * DH];
__device__ bf16 g_Vh  [B * HEADS * DH * HW], g_Vl [B * HEADS * DH * HW]; // [bh][d][j]
__device__ bf16 g_Ph  [(size_t)B * HEADS * HW * HW];       // softmax probs hi
__device__ bf16 g_Pl  [(size_t)B * HEADS * HW * HW];       // softmax probs lo

// =================== helpers ==================================================
__device__ __forceinline__ uint32_t smem_u32(const void* p) {
    uint32_t r;
    asm("{ .reg .u64 t; cvta.to.shared.u64 t, %1; cvt.u32.u64 %0, t; }"
        : "=r"(r) : "l"(p));
    return r;
}
#define CP_ASYNC16(dst, src) \
    asm volatile("cp.async.cg.shared.global [%0], [%1], 16;" :: "r"(dst), "l"(src) : "memory")
#define CP_COMMIT() asm volatile("cp.async.commit_group;" ::: "memory")
#define CP_WAIT1()  asm volatile("cp.async.wait_group 1;" ::: "memory")
#define CP_WAIT0()  asm volatile("cp.async.wait_group 0;" ::: "memory")

#define LDSM_X4(r, addr) \
    asm volatile("ldmatrix.sync.aligned.m8n8.x4.shared.b16 {%0,%1,%2,%3}, [%4];" \
        : "=r"((r)[0]), "=r"((r)[1]), "=r"((r)[2]), "=r"((r)[3]) : "r"(addr))
#define LDSM_X2(r, addr) \
    asm volatile("ldmatrix.sync.aligned.m8n8.x2.shared.b16 {%0,%1}, [%2];" \
        : "=r"((r)[0]), "=r"((r)[1]) : "r"(addr))

__device__ __forceinline__ void mma_bf16(float* c, const uint32_t* a, const uint32_t* b) {
    asm volatile(
        "mma.sync.aligned.m16n8k16.row.col.f32.bf16.bf16.f32 "
        "{%0,%1,%2,%3}, {%4,%5,%6,%7}, {%8,%9}, {%0,%1,%2,%3};"
        : "+f"(c[0]), "+f"(c[1]), "+f"(c[2]), "+f"(c[3])
        : "r"(a[0]), "r"(a[1]), "r"(a[2]), "r"(a[3]), "r"(b[0]), "r"(b[1]));
}

// =================== GroupNorm ================================================
__global__ __launch_bounds__(256) void gn_kernel(const float* __restrict__ x,
                                                 const float* __restrict__ gw,
                                                 const float* __restrict__ gb) {
    int bg = blockIdx.x;
    int bi = bg / G, g = bg % G;
    const float* xp = x + ((size_t)bi * C + (size_t)g * CPG) * HW;
    float* op = g_xn + ((size_t)bi * C + (size_t)g * CPG) * HW;
    const int N = CPG * HW;
    float s = 0.f, s2 = 0.f;
    for (int i = threadIdx.x; i < N; i += 256) {
        float v = xp[i]; s += v; s2 += v * v;
    }
    __shared__ float sh1[8], sh2[8];
    int lane = threadIdx.x & 31, wid = threadIdx.x >> 5;
    for (int o = 16; o; o >>= 1) {
        s  += __shfl_down_sync(0xffffffffu, s,  o);
        s2 += __shfl_down_sync(0xffffffffu, s2, o);
    }
    if (lane == 0) { sh1[wid] = s; sh2[wid] = s2; }
    __syncthreads();
    if (threadIdx.x < 8) {
        s = sh1[threadIdx.x]; s2 = sh2[threadIdx.x];
        for (int o = 4; o; o >>= 1) {
            s  += __shfl_down_sync(0xffu, s,  o);
            s2 += __shfl_down_sync(0xffu, s2, o);
        }
        if (threadIdx.x == 0) { sh1[0] = s; sh2[0] = s2; }
    }
    __syncthreads();
    float mean = sh1[0] * (1.f / N);
    float var  = sh2[0] * (1.f / N) - mean * mean;
    float inv  = rsqrtf(var + EPS);
    for (int i = threadIdx.x; i < N; i += 256) {
        int ch = g * CPG + (i >> 10);
        op[i] = (xp[i] - mean) * inv * gw[ch] + gb[ch];
    }
}

// =================== weight convert (hi/lo split) =============================
template<int W>
__global__ __launch_bounds__(256) void convW_kernel(const float* __restrict__ src, int n) {
    bf16* hi = (W == 0) ? g_WhiQ : g_WhiP;
    bf16* lo = (W == 0) ? g_WloQ : g_WloP;
    int i = blockIdx.x * 256 + threadIdx.x;
    if (i < n) {
        float v = src[i];
        bf16 h = __float2bfloat16(v);
        hi[i] = h;
        lo[i] = __float2bfloat16(v - __bfloat162float(h));
    }
}

// ======== transpose + convert: [b][c][n] fp32 -> [b][n][c] bf16 hi/lo =========
template<int T>
__global__ __launch_bounds__(256) void convT_kernel() {
    const float* in = (T == 0) ? g_xn : g_ao;
    bf16* oh = (T == 0) ? g_XTh : g_AOTh;
    bf16* ol = (T == 0) ? g_XTl : g_AOTl;
    __shared__ float t[32][33];
    int n0 = blockIdx.x * 32, c0 = blockIdx.y * 32, b = blockIdx.z;
    const float* ip = in + (size_t)b * C * HW;
    int tx = threadIdx.x, ty = threadIdx.y;  // (32,8)
#pragma unroll
    for (int k = 0; k < 4; k++)
        t[ty + k * 8][tx] = ip[(size_t)(c0 + ty + k * 8) * HW + n0 + tx];
    __syncthreads();
#pragma unroll
    for (int k = 0; k < 4; k++) {
        int ni = ty + k * 8;
        float v = t[tx][ni];
        bf16 h = __float2bfloat16(v);
        size_t o = (size_t)b * HW * C + (size_t)(n0 + ni) * C + c0 + tx;
        oh[o] = h;
        ol[o] = __float2bfloat16(v - __bfloat162float(h));
    }
}

// ======== q/k transpose+convert: g_qkv q,k [dh][hw] -> [bh][i][d] hi/lo =======
__global__ __launch_bounds__(256) void convQK_kernel() {
    __shared__ float t[32][33];
    int z = blockIdx.z;            // bh*2 + sel
    int sel = z & 1, bh = z >> 1;
    int bi = bh >> 3, h = bh & 7;
    int i0 = blockIdx.x * 32, d0 = blockIdx.y * 32;
    const float* src = g_qkv + (((size_t)bi * 3 + sel) * C + (size_t)h * DH) * HW;
    bf16* dh_ = sel ? g_kTh : g_qTh;
    bf16* dl_ = sel ? g_kTl : g_qTl;
    int tx = threadIdx.x, ty = threadIdx.y;  // (32,8)
#pragma unroll
    for (int k = 0; k < 4; k++)
        t[ty + k * 8][tx] = src[(size_t)(d0 + ty + k * 8) * HW + i0 + tx];
    __syncthreads();
#pragma unroll
    for (int k = 0; k < 4; k++) {
        int il = ty + k * 8;
        float v = t[tx][il];
        bf16 hh = __float2bfloat16(v);
        size_t o = ((size_t)bh * HW + i0 + il) * DH + d0 + tx;
        dh_[o] = hh;
        dl_[o] = __float2bfloat16(v - __bfloat162float(hh));
    }
}

// ======== V convert (no transpose): [bh][d][j] fp32 -> bf16 hi/lo =============
__global__ __launch_bounds__(256) void convV_kernel() {
    int idx = blockIdx.x * 256 + threadIdx.x;      // over B*HEADS*DH*HW
    if (idx >= B * HEADS * DH * HW) return;
    int bh = idx / (DH * HW);
    int r  = idx % (DH * HW);
    int bi = bh >> 3, h = bh & 7;
    float v = g_qkv[(((size_t)bi * 3 + 2) * C + (size_t)h * DH) * HW + r];
    bf16 hh = __float2bfloat16(v);
    g_Vh[idx] = hh;
    g_Vl[idx] = __float2bfloat16(v - __bfloat162float(hh));
}

// =================== HMMA split-bf16 GEMM =====================================
// D[m,n] = scale * sum_k A[m,k]*B[n,k] (+bias[m]) (+resid)
// A,B: bf16 hi/lo, row-major [rows][K] with ld == K. 256 threads, warps 2x4.
#define KC   32
#define ROWB 80     // bytes per smem row: 32 halves + 8 pad = 40 halves

template<int BM, int BN>
__global__ __launch_bounds__(256) void hmma_gemm(
    const bf16* __restrict__ Ah, const bf16* __restrict__ Al,
    const bf16* __restrict__ Bh, const bf16* __restrict__ Bl,
    float* __restrict__ out,
    const float* __restrict__ bias, const float* __restrict__ resid,
    int K, long long strideA, long long strideB, long long strideO,
    int ldo, float scale)
{
    constexpr int ATILE = BM * ROWB;
    constexpr int BTILE = BN * ROWB;
    constexpr int STAGE = 2 * ATILE + 2 * BTILE;
    constexpr int WMT = BM / 2;      // warp tile m (warps 2 x 4)
    constexpr int WNT = BN / 4;      // = 32
    constexpr int MI = WMT / 16;
    constexpr int NI = WNT / 8;      // = 4
    extern __shared__ char smem[];

    const int tid = threadIdx.x;
    const int lane = tid & 31, wid = tid >> 5;
    const int wm = wid & 1, wn = wid >> 1;
    const int n0 = blockIdx.x * BN, m0 = blockIdx.y * BM;
    const long long z = blockIdx.z;

    const bf16* pAh = Ah + z * strideA + (long long)m0 * K;
    const bf16* pAl = Al + z * strideA + (long long)m0 * K;
    const bf16* pBh = Bh + z * strideB + (long long)n0 * K;
    const bf16* pBl = Bl + z * strideB + (long long)n0 * K;

    auto load_chunk = [&](int stage, int k0) {
        char* sb = smem + stage * STAGE;
        constexpr int OPS = (2 * BM + 2 * BN) * 4;   // 16B ops
#pragma unroll
        for (int it = 0; it < OPS / 256; it++) {
            int idx = tid + it * 256;
            int row = idx >> 2, seg = idx & 3;
            const bf16* src; int toff; int r;
            if (row < BM)              { src = pAh; toff = 0;              r = row; }
            else if (row < 2 * BM)     { src = pAl; toff = ATILE;          r = row - BM; }
            else if (row < 2 * BM + BN){ src = pBh; toff = 2 * ATILE;      r = row - 2 * BM; }
            else                       { src = pBl; toff = 2 * ATILE + BTILE; r = row - 2 * BM - BN; }
            uint32_t dst = smem_u32(sb + toff + r * ROWB + seg * 16);
            CP_ASYNC16(dst, src + (long long)r * K + k0 + seg * 8);
        }
        CP_COMMIT();
    };

    float acc[MI][NI][4];
#pragma unroll
    for (int mi = 0; mi < MI; mi++)
#pragma unroll
        for (int ni = 0; ni < NI; ni++)
#pragma unroll
            for (int j = 0; j < 4; j++) acc[mi][ni][j] = 0.f;

    const int NCH = K / KC;
    load_chunk(0, 0);
#pragma unroll 1
    for (int c = 0; c < NCH; c++) {
        if (c + 1 < NCH) { load_chunk((c + 1) & 1, (c + 1) * KC); CP_WAIT1(); }
        else             { CP_WAIT0(); }
        __syncthreads();
        char* sb = smem + (c & 1) * STAGE;
        uint32_t aH = smem_u32(sb);
        uint32_t aL = aH + ATILE;
        uint32_t bH = aH + 2 * ATILE;
        uint32_t bL = bH + BTILE;
#pragma unroll
        for (int ks = 0; ks < 2; ks++) {
            uint32_t ah[MI][4], al[MI][4], bh[NI][2], bl[NI][2];
            int acol = ks * 16 + (lane >> 4) * 8;
#pragma unroll
            for (int mi = 0; mi < MI; mi++) {
                uint32_t off = (uint32_t)((wm * WMT + mi * 16 + (lane & 15)) * ROWB + acol * 2);
                LDSM_X4(ah[mi], aH + off);
                LDSM_X4(al[mi], aL + off);
            }
            int l = lane & 15;
            int bcol = ks * 16 + (l >> 3) * 8;
#pragma unroll
            for (int ni = 0; ni < NI; ni++) {
                uint32_t off = (uint32_t)((wn * WNT + ni * 8 + (l & 7)) * ROWB + bcol * 2);
                LDSM_X2(bh[ni], bH + off);
                LDSM_X2(bl[ni], bL + off);
            }
#pragma unroll
            for (int mi = 0; mi < MI; mi++)
#pragma unroll
                for (int ni = 0; ni < NI; ni++) {
                    mma_bf16(acc[mi][ni], ah[mi], bh[ni]);
                    mma_bf16(acc[mi][ni], ah[mi], bl[ni]);
                    mma_bf16(acc[mi][ni], al[mi], bh[ni]);
                }
        }
        __syncthreads();
    }

    // epilogue
    float* po = out + z * strideO;
#pragma unroll
    for (int mi = 0; mi < MI; mi++) {
#pragma unroll
        for (int ni = 0; ni < NI; ni++) {
            int col = n0 + wn * WNT + ni * 8 + (lane & 3) * 2;
#pragma unroll
            for (int hrow = 0; hrow < 2; hrow++) {
                int r = m0 + wm * WMT + mi * 16 + (lane >> 2) + hrow * 8;
                float2 v;
                v.x = acc[mi][ni][hrow * 2 + 0] * scale;
                v.y = acc[mi][ni][hrow * 2 + 1] * scale;
                if (bias) { float bm = bias[r]; v.x += bm; v.y += bm; }
                long long off = (long long)r * ldo + col;
                if (resid) {
                    const float2 rx = *(const float2*)&resid[z * strideO + off];
                    v.x += rx.x; v.y += rx.y;
                }
                *(float2*)&po[off] = v;
            }
        }
    }
}

// =================== softmax: fp32 logits -> bf16 hi/lo probs =================
__global__ __launch_bounds__(256) void softmax_kernel() {
    size_t row = blockIdx.x;
    float4 v = ((const float4*)(g_S + row * HW))[threadIdx.x];
    float m = fmaxf(fmaxf(v.x, v.y), fmaxf(v.z, v.w));
    __shared__ float sh[8];
    int lane = threadIdx.x & 31, wid = threadIdx.x >> 5;
    for (int o = 16; o; o >>= 1) m = fmaxf(m, __shfl_down_sync(0xffffffffu, m, o));
    if (lane == 0) sh[wid] = m;
    __syncthreads();
    if (threadIdx.x < 8) {
        m = sh[threadIdx.x];
        for (int o = 4; o; o >>= 1) m = fmaxf(m, __shfl_down_sync(0xffu, m, o));
        if (threadIdx.x == 0) sh[0] = m;
    }
    __syncthreads();
    m = sh[0];
    __syncthreads();
    v.x = expf(v.x - m); v.y = expf(v.y - m);
    v.z = expf(v.z - m); v.w = expf(v.w - m);
    float s = v.x + v.y + v.z + v.w;
    for (int o = 16; o; o >>= 1) s += __shfl_down_sync(0xffffffffu, s, o);
    if (lane == 0) sh[wid] = s;
    __syncthreads();
    if (threadIdx.x < 8) {
        s = sh[threadIdx.x];
        for (int o = 4; o; o >>= 1) s += __shfl_down_sync(0xffu, s, o);
        if (threadIdx.x == 0) sh[0] = s;
    }
    __syncthreads();
    float inv = 1.f / sh[0];
    float p[4] = {v.x * inv, v.y * inv, v.z * inv, v.w * inv};
    bf16 h[4], l[4];
#pragma unroll
    for (int j = 0; j < 4; j++) {
        h[j] = __float2bfloat16(p[j]);
        l[j] = __float2bfloat16(p[j] - __bfloat162float(h[j]));
    }
    __nv_bfloat162 h01, h23, l01, l23;
    h01.x = h[0]; h01.y = h[1]; h23.x = h[2]; h23.y = h[3];
    l01.x = l[0]; l01.y = l[1]; l23.x = l[2]; l23.y = l[3];
    uint2 uh, ul;
    uh.x = *(uint32_t*)&h01; uh.y = *(uint32_t*)&h23;
    ul.x = *(uint32_t*)&l01; ul.y = *(uint32_t*)&l23;
    ((uint2*)(g_Ph + row * HW))[threadIdx.x] = uh;
    ((uint2*)(g_Pl + row * HW))[threadIdx.x] = ul;
}

// =================== launch ===================================================
extern "C" void kernel_launch(void* const* d_in, const int* in_sizes, int n_in,
                              void* d_out, int out_size) {
    const float* x      = (const float*)d_in[0];
    const float* gn_w   = (const float*)d_in[1];
    const float* gn_b   = (const float*)d_in[2];
    const float* qkv_w  = (const float*)d_in[3];
    const float* qkv_b  = (const float*)d_in[4];
    const float* proj_w = (const float*)d_in[5];
    const float* proj_b = (const float*)d_in[6];
    float* out = (float*)d_out;

    static bf16 *qTh, *qTl, *kTh, *kTl, *Vh, *Vl, *Ph, *Pl;
    static bf16 *WhiQ, *WloQ, *WhiP, *WloP, *XTh, *XTl, *AOTh, *AOTl;
    static float *S, *qkv, *ao;
    static bool init = false;
    if (!init) {
        cudaGetSymbolAddress((void**)&qTh, g_qTh);  cudaGetSymbolAddress((void**)&qTl, g_qTl);
        cudaGetSymbolAddress((void**)&kTh, g_kTh);  cudaGetSymbolAddress((void**)&kTl, g_kTl);
        cudaGetSymbolAddress((void**)&Vh,  g_Vh);   cudaGetSymbolAddress((void**)&Vl,  g_Vl);
        cudaGetSymbolAddress((void**)&Ph,  g_Ph);   cudaGetSymbolAddress((void**)&Pl,  g_Pl);
        cudaGetSymbolAddress((void**)&WhiQ, g_WhiQ); cudaGetSymbolAddress((void**)&WloQ, g_WloQ);
        cudaGetSymbolAddress((void**)&WhiP, g_WhiP); cudaGetSymbolAddress((void**)&WloP, g_WloP);
        cudaGetSymbolAddress((void**)&XTh, g_XTh);  cudaGetSymbolAddress((void**)&XTl, g_XTl);
        cudaGetSymbolAddress((void**)&AOTh, g_AOTh);cudaGetSymbolAddress((void**)&AOTl, g_AOTl);
        cudaGetSymbolAddress((void**)&S, g_S);
        cudaGetSymbolAddress((void**)&qkv, g_qkv);
        cudaGetSymbolAddress((void**)&ao, g_ao);
        cudaFuncSetAttribute(hmma_gemm<128,128>, cudaFuncAttributeMaxDynamicSharedMemorySize,
                             2 * (4 * 128 * ROWB));
        cudaFuncSetAttribute(hmma_gemm<64,128>,  cudaFuncAttributeMaxDynamicSharedMemorySize,
                             2 * (2 * 64 * ROWB + 2 * 128 * ROWB));
        init = true;
    }
    constexpr int SM128 = 2 * (4 * 128 * ROWB);
    constexpr int SM64  = 2 * (2 * 64 * ROWB + 2 * 128 * ROWB);

    gn_kernel<<<B * G, 256>>>(x, gn_w, gn_b);
    convW_kernel<0><<<(3 * C * C + 255) / 256, 256>>>(qkv_w, 3 * C * C);
    convW_kernel<1><<<(C * C + 255) / 256, 256>>>(proj_w, C * C);
    convT_kernel<0><<<dim3(HW / 32, C / 32, B), dim3(32, 8)>>>();

    // QKV: M=1536, N=1024, K=512
    hmma_gemm<128,128><<<dim3(HW/128, 3*C/128, B), 256, SM128>>>(
        WhiQ, WloQ, XTh, XTl, qkv, qkv_b, nullptr,
        C, 0LL, (long long)HW * C, (long long)3 * C * HW, HW, 1.0f);

    convQK_kernel<<<dim3(HW / 32, DH / 32, 2 * B * HEADS), dim3(32, 8)>>>();
    convV_kernel<<<(B * HEADS * DH * HW + 255) / 256, 256>>>();

    // S = scale * q k^T: M=N=1024, K=64 per (b,h)
    hmma_gemm<128,128><<<dim3(HW/128, HW/128, B*HEADS), 256, SM128>>>(
        qTh, qTl, kTh, kTl, S, nullptr, nullptr,
        DH, (long long)HW * DH, (long long)HW * DH, (long long)HW * HW, HW, 0.125f);

    softmax_kernel<<<B * HEADS * HW, 256>>>();

    // AV: M=64 (d), N=1024 (i), K=1024 (j) per (b,h)
    hmma_gemm<64,128><<<dim3(HW/128, 1, B*HEADS), 256, SM64>>>(
        Vh, Vl, Ph, Pl, ao, nullptr, nullptr,
        HW, (long long)DH * HW, (long long)HW * HW, (long long)DH * HW, HW, 1.0f);

    convT_kernel<1><<<dim3(HW / 32, C / 32, B), dim3(32, 8)>>>();

    // proj + residual: M=512, N=1024, K=512
    hmma_gemm<128,128><<<dim3(HW/128, C/128, B), 256, SM128>>>(
        WhiP, WloP, AOTh, AOTl, out, proj_b, x,
        C, 0LL, (long long)HW * C, (long long)C * HW, HW, 1.0f);
}

// round 4
// speedup vs baseline: 2.6237x; 1.4278x over previous
#include <cuda_runtime.h>
#include <cuda_bf16.h>
#include <cstdint>
#include <math.h>

#define B    8
#define C    512
#define HW   1024
#define G    32
#define CPG  16
#define HEADS 8
#define DH   64
#define EPS  1e-5f

typedef __nv_bfloat16 bf16;

// ---------------- scratch (device globals) ----------------------------------
__device__ float g_xn [B * C * HW];
__device__ float g_qkv[B * 3 * C * HW];

__device__ bf16 g_WhiQ[3 * C * C], g_WloQ[3 * C * C];
__device__ bf16 g_WhiP[C * C],     g_WloP[C * C];
__device__ bf16 g_XTh [B * HW * C], g_XTl [B * HW * C];   // [b][n][c]
__device__ bf16 g_AOTh[B * HW * C], g_AOTl[B * HW * C];   // [b][i][c] attn out
__device__ bf16 g_qTh [B * HEADS * HW * DH], g_qTl[B * HEADS * HW * DH]; // [bh][i][d] (pre-scaled)
__device__ bf16 g_kTh [B * HEADS * HW * DH], g_kTl[B * HEADS * HW * DH];
__device__ bf16 g_Vh  [B * HEADS * DH * HW], g_Vl [B * HEADS * DH * HW]; // [bh][d][j]

// =================== helpers ==================================================
__device__ __forceinline__ uint32_t smem_u32(const void* p) {
    uint32_t r;
    asm("{ .reg .u64 t; cvta.to.shared.u64 t, %1; cvt.u32.u64 %0, t; }"
        : "=r"(r) : "l"(p));
    return r;
}
#define CP_ASYNC16(dst, src) \
    asm volatile("cp.async.cg.shared.global [%0], [%1], 16;" :: "r"(dst), "l"(src) : "memory")
#define CP_COMMIT() asm volatile("cp.async.commit_group;" ::: "memory")
#define CP_WAIT1()  asm volatile("cp.async.wait_group 1;" ::: "memory")
#define CP_WAIT0()  asm volatile("cp.async.wait_group 0;" ::: "memory")

#define LDSM_X4(r, addr) \
    asm volatile("ldmatrix.sync.aligned.m8n8.x4.shared.b16 {%0,%1,%2,%3}, [%4];" \
        : "=r"((r)[0]), "=r"((r)[1]), "=r"((r)[2]), "=r"((r)[3]) : "r"(addr))
#define LDSM_X2(r, addr) \
    asm volatile("ldmatrix.sync.aligned.m8n8.x2.shared.b16 {%0,%1}, [%2];" \
        : "=r"((r)[0]), "=r"((r)[1]) : "r"(addr))

__device__ __forceinline__ void mma_bf16(float* c, const uint32_t* a, const uint32_t* b) {
    asm volatile(
        "mma.sync.aligned.m16n8k16.row.col.f32.bf16.bf16.f32 "
        "{%0,%1,%2,%3}, {%4,%5,%6,%7}, {%8,%9}, {%0,%1,%2,%3};"
        : "+f"(c[0]), "+f"(c[1]), "+f"(c[2]), "+f"(c[3])
        : "r"(a[0]), "r"(a[1]), "r"(a[2]), "r"(a[3]), "r"(b[0]), "r"(b[1]));
}

__device__ __forceinline__ void pack2(uint32_t& hi, uint32_t& lo, float x, float y) {
    __nv_bfloat162 h = __floats2bfloat162_rn(x, y);
    float hx = __bfloat162float(h.x), hy = __bfloat162float(h.y);
    __nv_bfloat162 l = __floats2bfloat162_rn(x - hx, y - hy);
    hi = *(uint32_t*)&h;
    lo = *(uint32_t*)&l;
}

// =================== GroupNorm ================================================
__global__ __launch_bounds__(256) void gn_kernel(const float* __restrict__ x,
                                                 const float* __restrict__ gw,
                                                 const float* __restrict__ gb) {
    int bg = blockIdx.x;
    int bi = bg / G, g = bg % G;
    const float* xp = x + ((size_t)bi * C + (size_t)g * CPG) * HW;
    float* op = g_xn + ((size_t)bi * C + (size_t)g * CPG) * HW;
    const int N = CPG * HW;
    float s = 0.f, s2 = 0.f;
    for (int i = threadIdx.x; i < N; i += 256) {
        float v = xp[i]; s += v; s2 += v * v;
    }
    __shared__ float sh1[8], sh2[8];
    int lane = threadIdx.x & 31, wid = threadIdx.x >> 5;
    for (int o = 16; o; o >>= 1) {
        s  += __shfl_down_sync(0xffffffffu, s,  o);
        s2 += __shfl_down_sync(0xffffffffu, s2, o);
    }
    if (lane == 0) { sh1[wid] = s; sh2[wid] = s2; }
    __syncthreads();
    if (threadIdx.x < 8) {
        s = sh1[threadIdx.x]; s2 = sh2[threadIdx.x];
        for (int o = 4; o; o >>= 1) {
            s  += __shfl_down_sync(0xffu, s,  o);
            s2 += __shfl_down_sync(0xffu, s2, o);
        }
        if (threadIdx.x == 0) { sh1[0] = s; sh2[0] = s2; }
    }
    __syncthreads();
    float mean = sh1[0] * (1.f / N);
    float var  = sh2[0] * (1.f / N) - mean * mean;
    float inv  = rsqrtf(var + EPS);
    for (int i = threadIdx.x; i < N; i += 256) {
        int ch = g * CPG + (i >> 10);
        op[i] = (xp[i] - mean) * inv * gw[ch] + gb[ch];
    }
}

// =================== weight convert (hi/lo split) =============================
template<int W>
__global__ __launch_bounds__(256) void convW_kernel(const float* __restrict__ src, int n) {
    bf16* hi = (W == 0) ? g_WhiQ : g_WhiP;
    bf16* lo = (W == 0) ? g_WloQ : g_WloP;
    int i = blockIdx.x * 256 + threadIdx.x;
    if (i < n) {
        float v = src[i];
        bf16 h = __float2bfloat16(v);
        hi[i] = h;
        lo[i] = __float2bfloat16(v - __bfloat162float(h));
    }
}

// ======== transpose + convert: [b][c][n] fp32 -> [b][n][c] bf16 hi/lo =========
__global__ __launch_bounds__(256) void convT_kernel() {
    __shared__ float t[32][33];
    int n0 = blockIdx.x * 32, c0 = blockIdx.y * 32, b = blockIdx.z;
    const float* ip = g_xn + (size_t)b * C * HW;
    int tx = threadIdx.x, ty = threadIdx.y;  // (32,8)
#pragma unroll
    for (int k = 0; k < 4; k++)
        t[ty + k * 8][tx] = ip[(size_t)(c0 + ty + k * 8) * HW + n0 + tx];
    __syncthreads();
#pragma unroll
    for (int k = 0; k < 4; k++) {
        int ni = ty + k * 8;
        float v = t[tx][ni];
        bf16 h = __float2bfloat16(v);
        size_t o = (size_t)b * HW * C + (size_t)(n0 + ni) * C + c0 + tx;
        g_XTh[o] = h;
        g_XTl[o] = __float2bfloat16(v - __bfloat162float(h));
    }
}

// ======== q/k transpose+convert: g_qkv q,k [dh][hw] -> [bh][i][d] hi/lo =======
// q gets the 1/sqrt(dh) scale folded in.
__global__ __launch_bounds__(256) void convQK_kernel() {
    __shared__ float t[32][33];
    int z = blockIdx.z;            // bh*2 + sel
    int sel = z & 1, bh = z >> 1;
    int bi = bh >> 3, h = bh & 7;
    int i0 = blockIdx.x * 32, d0 = blockIdx.y * 32;
    const float* src = g_qkv + (((size_t)bi * 3 + sel) * C + (size_t)h * DH) * HW;
    bf16* dh_ = sel ? g_kTh : g_qTh;
    bf16* dl_ = sel ? g_kTl : g_qTl;
    float sc = sel ? 1.0f : 0.125f;
    int tx = threadIdx.x, ty = threadIdx.y;  // (32,8)
#pragma unroll
    for (int k = 0; k < 4; k++)
        t[ty + k * 8][tx] = src[(size_t)(d0 + ty + k * 8) * HW + i0 + tx];
    __syncthreads();
#pragma unroll
    for (int k = 0; k < 4; k++) {
        int il = ty + k * 8;
        float v = t[tx][il] * sc;
        bf16 hh = __float2bfloat16(v);
        size_t o = ((size_t)bh * HW + i0 + il) * DH + d0 + tx;
        dh_[o] = hh;
        dl_[o] = __float2bfloat16(v - __bfloat162float(hh));
    }
}

// ======== V convert (no transpose): [bh][d][j] fp32 -> bf16 hi/lo =============
__global__ __launch_bounds__(256) void convV_kernel() {
    int idx = blockIdx.x * 256 + threadIdx.x;
    if (idx >= B * HEADS * DH * HW) return;
    int bh = idx / (DH * HW);
    int r  = idx % (DH * HW);
    int bi = bh >> 3, h = bh & 7;
    float v = g_qkv[(((size_t)bi * 3 + 2) * C + (size_t)h * DH) * HW + r];
    bf16 hh = __float2bfloat16(v);
    g_Vh[idx] = hh;
    g_Vl[idx] = __float2bfloat16(v - __bfloat162float(hh));
}

// =================== flash attention ==========================================
// Per block: 128 q-rows of one (b,h). 8 warps, each warp 16 rows.
// Q (hi/lo) resident; K/V (hi/lo) streamed in 128-j tiles, double buffered.
#define QROWB   144            // 64 halves + 8 pad
#define VROWB   272            // 128 halves + 8 pad
#define FL_QTILE 18432         // 128 * 144   (also = K tile size)
#define FL_VTILE 17408         // 64 * 272
#define FL_STAGE0 (2 * FL_QTILE)
#define FL_STAGEB (2 * FL_QTILE + 2 * FL_VTILE)
#define FL_SMEM   (FL_STAGE0 + 2 * FL_STAGEB)   // 36864 + 143360 = 180224

__global__ __launch_bounds__(256, 1) void flash_kernel() {
    extern __shared__ char smem[];
    const int tid = threadIdx.x, lane = tid & 31, wid = tid >> 5;
    const int i0 = blockIdx.x * 128;
    const int bh = blockIdx.y;
    const int b = bh >> 3, h = bh & 7;
    const int wr = wid * 16;

    // ---- loaders ----
    auto ld_Q = [&]() {
#pragma unroll
        for (int it = 0; it < 8; it++) {
            int idx = tid + it * 256;
            int tile = idx >> 10, r = (idx >> 3) & 127, seg = idx & 7;
            const bf16* src = (tile ? g_qTl : g_qTh) +
                              ((size_t)bh * HW + i0 + r) * DH + seg * 8;
            CP_ASYNC16(smem_u32(smem + tile * FL_QTILE + r * QROWB + seg * 16), src);
        }
    };
    auto ld_KV = [&](int jt, int st) {
        char* sb = smem + FL_STAGE0 + st * FL_STAGEB;
        int j0 = jt * 128;
#pragma unroll
        for (int it = 0; it < 8; it++) {
            int idx = tid + it * 256;
            int tile = idx >> 10, r = (idx >> 3) & 127, seg = idx & 7;
            const bf16* src = (tile ? g_kTl : g_kTh) +
                              ((size_t)bh * HW + j0 + r) * DH + seg * 8;
            CP_ASYNC16(smem_u32(sb + tile * FL_QTILE + r * QROWB + seg * 16), src);
        }
#pragma unroll
        for (int it = 0; it < 8; it++) {
            int idx = tid + it * 256;
            int tile = idx >> 10, r = (idx >> 4) & 63, seg = idx & 15;
            const bf16* src = (tile ? g_Vl : g_Vh) +
                              ((size_t)bh * DH + r) * HW + j0 + seg * 8;
            CP_ASYNC16(smem_u32(sb + 2 * FL_QTILE + tile * FL_VTILE + r * VROWB + seg * 16), src);
        }
    };

    float acc_o[8][4];
#pragma unroll
    for (int dt = 0; dt < 8; dt++)
#pragma unroll
        for (int j = 0; j < 4; j++) acc_o[dt][j] = 0.f;
    float mrow0 = -INFINITY, mrow1 = -INFINITY;
    float lrow0 = 0.f, lrow1 = 0.f;

    const uint32_t qH = smem_u32(smem);
    const uint32_t qL = qH + FL_QTILE;

    ld_Q(); ld_KV(0, 0); CP_COMMIT();
    ld_KV(1, 1); CP_COMMIT();
    CP_WAIT1();
    __syncthreads();

#pragma unroll 1
    for (int jt = 0; jt < 8; jt++) {
        uint32_t kb = smem_u32(smem + FL_STAGE0 + (jt & 1) * FL_STAGEB);
        uint32_t kH = kb, kL = kb + FL_QTILE;
        uint32_t vH = kb + 2 * FL_QTILE, vL = vH + FL_VTILE;

        // ---- S = q k^T  (scale pre-folded into q) ----
        float s[16][4];
#pragma unroll
        for (int nt = 0; nt < 16; nt++)
#pragma unroll
            for (int j = 0; j < 4; j++) s[nt][j] = 0.f;

#pragma unroll
        for (int ks = 0; ks < 4; ks++) {
            uint32_t ah[4], al[4];
            uint32_t aoff = (uint32_t)((wr + (lane & 15)) * QROWB +
                                       (ks * 16 + (lane >> 4) * 8) * 2);
            LDSM_X4(ah, qH + aoff);
            LDSM_X4(al, qL + aoff);
            int krow_l = ((lane >> 4) << 3) + (lane & 7);
            int kcol = ks * 16 + ((lane >> 3) & 1) * 8;
#pragma unroll
            for (int ntp = 0; ntp < 8; ntp++) {
                uint32_t bh_[4], bl_[4];
                uint32_t boff = (uint32_t)((ntp * 16 + krow_l) * QROWB + kcol * 2);
                LDSM_X4(bh_, kH + boff);
                LDSM_X4(bl_, kL + boff);
                mma_bf16(s[2 * ntp],     ah, bh_);
                mma_bf16(s[2 * ntp],     ah, bl_);
                mma_bf16(s[2 * ntp],     al, bh_);
                mma_bf16(s[2 * ntp + 1], ah, bh_ + 2);
                mma_bf16(s[2 * ntp + 1], ah, bl_ + 2);
                mma_bf16(s[2 * ntp + 1], al, bh_ + 2);
            }
        }

        // ---- online softmax ----
        float mx0 = -INFINITY, mx1 = -INFINITY;
#pragma unroll
        for (int nt = 0; nt < 16; nt++) {
            mx0 = fmaxf(mx0, fmaxf(s[nt][0], s[nt][1]));
            mx1 = fmaxf(mx1, fmaxf(s[nt][2], s[nt][3]));
        }
        mx0 = fmaxf(mx0, __shfl_xor_sync(0xffffffffu, mx0, 1));
        mx0 = fmaxf(mx0, __shfl_xor_sync(0xffffffffu, mx0, 2));
        mx1 = fmaxf(mx1, __shfl_xor_sync(0xffffffffu, mx1, 1));
        mx1 = fmaxf(mx1, __shfl_xor_sync(0xffffffffu, mx1, 2));
        float mn0 = fmaxf(mrow0, mx0), mn1 = fmaxf(mrow1, mx1);
        float al0 = __expf(mrow0 - mn0), al1 = __expf(mrow1 - mn1);
        mrow0 = mn0; mrow1 = mn1;
        lrow0 *= al0; lrow1 *= al1;
#pragma unroll
        for (int dt = 0; dt < 8; dt++) {
            acc_o[dt][0] *= al0; acc_o[dt][1] *= al0;
            acc_o[dt][2] *= al1; acc_o[dt][3] *= al1;
        }
        float ps0 = 0.f, ps1 = 0.f;
#pragma unroll
        for (int nt = 0; nt < 16; nt++) {
            s[nt][0] = __expf(s[nt][0] - mn0);
            s[nt][1] = __expf(s[nt][1] - mn0);
            s[nt][2] = __expf(s[nt][2] - mn1);
            s[nt][3] = __expf(s[nt][3] - mn1);
            ps0 += s[nt][0] + s[nt][1];
            ps1 += s[nt][2] + s[nt][3];
        }
        lrow0 += ps0; lrow1 += ps1;

        // ---- O += P V^T (split) ----
#pragma unroll
        for (int kk = 0; kk < 8; kk++) {
            uint32_t aph[4], apl[4];
            pack2(aph[0], apl[0], s[2 * kk][0],     s[2 * kk][1]);
            pack2(aph[1], apl[1], s[2 * kk][2],     s[2 * kk][3]);
            pack2(aph[2], apl[2], s[2 * kk + 1][0], s[2 * kk + 1][1]);
            pack2(aph[3], apl[3], s[2 * kk + 1][2], s[2 * kk + 1][3]);
            int vrow_l = ((lane >> 4) << 3) + (lane & 7);
            int vcol = kk * 16 + ((lane >> 3) & 1) * 8;
#pragma unroll
            for (int dt = 0; dt < 4; dt++) {
                uint32_t bvh[4], bvl[4];
                uint32_t off = (uint32_t)((dt * 16 + vrow_l) * VROWB + vcol * 2);
                LDSM_X4(bvh, vH + off);
                LDSM_X4(bvl, vL + off);
                mma_bf16(acc_o[2 * dt],     aph, bvh);
                mma_bf16(acc_o[2 * dt],     aph, bvl);
                mma_bf16(acc_o[2 * dt],     apl, bvh);
                mma_bf16(acc_o[2 * dt + 1], aph, bvh + 2);
                mma_bf16(acc_o[2 * dt + 1], aph, bvl + 2);
                mma_bf16(acc_o[2 * dt + 1], apl, bvh + 2);
            }
        }

        __syncthreads();
        if (jt + 2 < 8)      { ld_KV(jt + 2, jt & 1); CP_COMMIT(); CP_WAIT1(); }
        else if (jt + 1 < 8) { CP_WAIT0(); }
        __syncthreads();
    }

    // ---- finalize: divide by l, write bf16 hi/lo to [b][i][h*DH+d] ----
    lrow0 += __shfl_xor_sync(0xffffffffu, lrow0, 1);
    lrow0 += __shfl_xor_sync(0xffffffffu, lrow0, 2);
    lrow1 += __shfl_xor_sync(0xffffffffu, lrow1, 1);
    lrow1 += __shfl_xor_sync(0xffffffffu, lrow1, 2);
    float inv0 = 1.f / lrow0, inv1 = 1.f / lrow1;

    int r0 = i0 + wr + (lane >> 2);
    int cbase = h * DH + (lane & 3) * 2;
#pragma unroll
    for (int dt = 0; dt < 8; dt++) {
        uint32_t uh, ul;
        pack2(uh, ul, acc_o[dt][0] * inv0, acc_o[dt][1] * inv0);
        size_t o0 = ((size_t)b * HW + r0) * C + cbase + dt * 8;
        *(uint32_t*)&g_AOTh[o0] = uh;
        *(uint32_t*)&g_AOTl[o0] = ul;
        pack2(uh, ul, acc_o[dt][2] * inv1, acc_o[dt][3] * inv1);
        size_t o1 = ((size_t)b * HW + r0 + 8) * C + cbase + dt * 8;
        *(uint32_t*)&g_AOTh[o1] = uh;
        *(uint32_t*)&g_AOTl[o1] = ul;
    }
}

// =================== HMMA split-bf16 GEMM (dense layers) ======================
#define KC   32
#define ROWB 80

template<int BM, int BN>
__global__ __launch_bounds__(256) void hmma_gemm(
    const bf16* __restrict__ Ah, const bf16* __restrict__ Al,
    const bf16* __restrict__ Bh, const bf16* __restrict__ Bl,
    float* __restrict__ out,
    const float* __restrict__ bias, const float* __restrict__ resid,
    int K, long long strideA, long long strideB, long long strideO,
    int ldo, float scale)
{
    constexpr int ATILE = BM * ROWB;
    constexpr int BTILE = BN * ROWB;
    constexpr int STAGE = 2 * ATILE + 2 * BTILE;
    constexpr int WMT = BM / 2;
    constexpr int WNT = BN / 4;
    constexpr int MI = WMT / 16;
    constexpr int NI = WNT / 8;
    extern __shared__ char smem[];

    const int tid = threadIdx.x;
    const int lane = tid & 31, wid = tid >> 5;
    const int wm = wid & 1, wn = wid >> 1;
    const int n0 = blockIdx.x * BN, m0 = blockIdx.y * BM;
    const long long z = blockIdx.z;

    const bf16* pAh = Ah + z * strideA + (long long)m0 * K;
    const bf16* pAl = Al + z * strideA + (long long)m0 * K;
    const bf16* pBh = Bh + z * strideB + (long long)n0 * K;
    const bf16* pBl = Bl + z * strideB + (long long)n0 * K;

    auto load_chunk = [&](int stage, int k0) {
        char* sb = smem + stage * STAGE;
        constexpr int OPS = (2 * BM + 2 * BN) * 4;
#pragma unroll
        for (int it = 0; it < OPS / 256; it++) {
            int idx = tid + it * 256;
            int row = idx >> 2, seg = idx & 3;
            const bf16* src; int toff; int r;
            if (row < BM)              { src = pAh; toff = 0;              r = row; }
            else if (row < 2 * BM)     { src = pAl; toff = ATILE;          r = row - BM; }
            else if (row < 2 * BM + BN){ src = pBh; toff = 2 * ATILE;      r = row - 2 * BM; }
            else                       { src = pBl; toff = 2 * ATILE + BTILE; r = row - 2 * BM - BN; }
            uint32_t dst = smem_u32(sb + toff + r * ROWB + seg * 16);
            CP_ASYNC16(dst, src + (long long)r * K + k0 + seg * 8);
        }
        CP_COMMIT();
    };

    float acc[MI][NI][4];
#pragma unroll
    for (int mi = 0; mi < MI; mi++)
#pragma unroll
        for (int ni = 0; ni < NI; ni++)
#pragma unroll
            for (int j = 0; j < 4; j++) acc[mi][ni][j] = 0.f;

    const int NCH = K / KC;
    load_chunk(0, 0);
#pragma unroll 1
    for (int c = 0; c < NCH; c++) {
        if (c + 1 < NCH) { load_chunk((c + 1) & 1, (c + 1) * KC); CP_WAIT1(); }
        else             { CP_WAIT0(); }
        __syncthreads();
        char* sb = smem + (c & 1) * STAGE;
        uint32_t aH = smem_u32(sb);
        uint32_t aL = aH + ATILE;
        uint32_t bH = aH + 2 * ATILE;
        uint32_t bL = bH + BTILE;
#pragma unroll
        for (int ks = 0; ks < 2; ks++) {
            uint32_t ah[MI][4], al[MI][4], bh[NI][2], bl[NI][2];
            int acol = ks * 16 + (lane >> 4) * 8;
#pragma unroll
            for (int mi = 0; mi < MI; mi++) {
                uint32_t off = (uint32_t)((wm * WMT + mi * 16 + (lane & 15)) * ROWB + acol * 2);
                LDSM_X4(ah[mi], aH + off);
                LDSM_X4(al[mi], aL + off);
            }
            int l = lane & 15;
            int bcol = ks * 16 + (l >> 3) * 8;
#pragma unroll
            for (int ni = 0; ni < NI; ni++) {
                uint32_t off = (uint32_t)((wn * WNT + ni * 8 + (l & 7)) * ROWB + bcol * 2);
                LDSM_X2(bh[ni], bH + off);
                LDSM_X2(bl[ni], bL + off);
            }
#pragma unroll
            for (int mi = 0; mi < MI; mi++)
#pragma unroll
                for (int ni = 0; ni < NI; ni++) {
                    mma_bf16(acc[mi][ni], ah[mi], bh[ni]);
                    mma_bf16(acc[mi][ni], ah[mi], bl[ni]);
                    mma_bf16(acc[mi][ni], al[mi], bh[ni]);
                }
        }
        __syncthreads();
    }

    float* po = out + z * strideO;
#pragma unroll
    for (int mi = 0; mi < MI; mi++) {
#pragma unroll
        for (int ni = 0; ni < NI; ni++) {
            int col = n0 + wn * WNT + ni * 8 + (lane & 3) * 2;
#pragma unroll
            for (int hrow = 0; hrow < 2; hrow++) {
                int r = m0 + wm * WMT + mi * 16 + (lane >> 2) + hrow * 8;
                float2 v;
                v.x = acc[mi][ni][hrow * 2 + 0] * scale;
                v.y = acc[mi][ni][hrow * 2 + 1] * scale;
                if (bias) { float bm = bias[r]; v.x += bm; v.y += bm; }
                long long off = (long long)r * ldo + col;
                if (resid) {
                    const float2 rx = *(const float2*)&resid[z * strideO + off];
                    v.x += rx.x; v.y += rx.y;
                }
                *(float2*)&po[off] = v;
            }
        }
    }
}

// =================== launch ===================================================
extern "C" void kernel_launch(void* const* d_in, const int* in_sizes, int n_in,
                              void* d_out, int out_size) {
    const float* x      = (const float*)d_in[0];
    const float* gn_w   = (const float*)d_in[1];
    const float* gn_b   = (const float*)d_in[2];
    const float* qkv_w  = (const float*)d_in[3];
    const float* qkv_b  = (const float*)d_in[4];
    const float* proj_w = (const float*)d_in[5];
    const float* proj_b = (const float*)d_in[6];
    float* out = (float*)d_out;

    static bf16 *WhiQ, *WloQ, *WhiP, *WloP, *XTh, *XTl, *AOTh, *AOTl;
    static float *qkv;
    static bool init = false;
    if (!init) {
        cudaGetSymbolAddress((void**)&WhiQ, g_WhiQ); cudaGetSymbolAddress((void**)&WloQ, g_WloQ);
        cudaGetSymbolAddress((void**)&WhiP, g_WhiP); cudaGetSymbolAddress((void**)&WloP, g_WloP);
        cudaGetSymbolAddress((void**)&XTh, g_XTh);  cudaGetSymbolAddress((void**)&XTl, g_XTl);
        cudaGetSymbolAddress((void**)&AOTh, g_AOTh);cudaGetSymbolAddress((void**)&AOTl, g_AOTl);
        cudaGetSymbolAddress((void**)&qkv, g_qkv);
        cudaFuncSetAttribute(hmma_gemm<128,128>, cudaFuncAttributeMaxDynamicSharedMemorySize,
                             2 * (4 * 128 * ROWB));
        cudaFuncSetAttribute(flash_kernel, cudaFuncAttributeMaxDynamicSharedMemorySize, FL_SMEM);
        init = true;
    }
    constexpr int SM128 = 2 * (4 * 128 * ROWB);

    gn_kernel<<<B * G, 256>>>(x, gn_w, gn_b);
    convW_kernel<0><<<(3 * C * C + 255) / 256, 256>>>(qkv_w, 3 * C * C);
    convW_kernel<1><<<(C * C + 255) / 256, 256>>>(proj_w, C * C);
    convT_kernel<<<dim3(HW / 32, C / 32, B), dim3(32, 8)>>>();

    // QKV: M=1536, N=1024, K=512
    hmma_gemm<128,128><<<dim3(HW/128, 3*C/128, B), 256, SM128>>>(
        WhiQ, WloQ, XTh, XTl, qkv, qkv_b, nullptr,
        C, 0LL, (long long)HW * C, (long long)3 * C * HW, HW, 1.0f);

    convQK_kernel<<<dim3(HW / 32, DH / 32, 2 * B * HEADS), dim3(32, 8)>>>();
    convV_kernel<<<(B * HEADS * DH * HW + 255) / 256, 256>>>();

    // fused attention: writes g_AOTh/g_AOTl in [b][i][c] layout
    flash_kernel<<<dim3(HW / 128, B * HEADS), 256, FL_SMEM>>>();

    // proj + residual: M=512, N=1024, K=512
    hmma_gemm<128,128><<<dim3(HW/128, C/128, B), 256, SM128>>>(
        WhiP, WloP, AOTh, AOTl, out, proj_b, x,
        C, 0LL, (long long)HW * C, (long long)C * HW, HW, 1.0f);
}

// round 5
// speedup vs baseline: 2.7225x; 1.0376x over previous
#include <cuda_runtime.h>
#include <cuda_bf16.h>
#include <cstdint>
#include <math.h>

#define B    8
#define C    512
#define HW   1024
#define G    32
#define CPG  16
#define HEADS 8
#define DH   64
#define EPS  1e-5f

typedef __nv_bfloat16 bf16;

// ---------------- scratch (device globals) ----------------------------------
__device__ float2 g_stats[B * G];                         // mean, inv per group

__device__ bf16 g_WhiQ[3 * C * C], g_WloQ[3 * C * C];
__device__ bf16 g_WhiP[C * C],     g_WloP[C * C];
__device__ bf16 g_XTh [B * HW * C], g_XTl [B * HW * C];   // [b][n][c]
__device__ bf16 g_AOTh[B * HW * C], g_AOTl[B * HW * C];   // [b][i][c] attn out
__device__ bf16 g_qTh [B * HEADS * HW * DH], g_qTl[B * HEADS * HW * DH]; // [bh][i][d] (pre-scaled)
__device__ bf16 g_kTh [B * HEADS * HW * DH], g_kTl[B * HEADS * HW * DH];
__device__ bf16 g_Vh  [B * HEADS * DH * HW], g_Vl [B * HEADS * DH * HW]; // [bh][d][j]

// =================== helpers ==================================================
__device__ __forceinline__ uint32_t smem_u32(const void* p) {
    uint32_t r;
    asm("{ .reg .u64 t; cvta.to.shared.u64 t, %1; cvt.u32.u64 %0, t; }"
        : "=r"(r) : "l"(p));
    return r;
}
#define CP_ASYNC16(dst, src) \
    asm volatile("cp.async.cg.shared.global [%0], [%1], 16;" :: "r"(dst), "l"(src) : "memory")
#define CP_COMMIT() asm volatile("cp.async.commit_group;" ::: "memory")
#define CP_WAIT1()  asm volatile("cp.async.wait_group 1;" ::: "memory")
#define CP_WAIT0()  asm volatile("cp.async.wait_group 0;" ::: "memory")

#define LDSM_X4(r, addr) \
    asm volatile("ldmatrix.sync.aligned.m8n8.x4.shared.b16 {%0,%1,%2,%3}, [%4];" \
        : "=r"((r)[0]), "=r"((r)[1]), "=r"((r)[2]), "=r"((r)[3]) : "r"(addr))
#define LDSM_X2(r, addr) \
    asm volatile("ldmatrix.sync.aligned.m8n8.x2.shared.b16 {%0,%1}, [%2];" \
        : "=r"((r)[0]), "=r"((r)[1]) : "r"(addr))

__device__ __forceinline__ void mma_bf16(float* c, const uint32_t* a, const uint32_t* b) {
    asm volatile(
        "mma.sync.aligned.m16n8k16.row.col.f32.bf16.bf16.f32 "
        "{%0,%1,%2,%3}, {%4,%5,%6,%7}, {%8,%9}, {%0,%1,%2,%3};"
        : "+f"(c[0]), "+f"(c[1]), "+f"(c[2]), "+f"(c[3])
        : "r"(a[0]), "r"(a[1]), "r"(a[2]), "r"(a[3]), "r"(b[0]), "r"(b[1]));
}

__device__ __forceinline__ void pack2(uint32_t& hi, uint32_t& lo, float x, float y) {
    __nv_bfloat162 h = __floats2bfloat162_rn(x, y);
    float hx = __bfloat162float(h.x), hy = __bfloat162float(h.y);
    __nv_bfloat162 l = __floats2bfloat162_rn(x - hx, y - hy);
    hi = *(uint32_t*)&h;
    lo = *(uint32_t*)&l;
}

// =================== GroupNorm stats ==========================================
__global__ __launch_bounds__(256) void gn_stats_kernel(const float* __restrict__ x) {
    int bg = blockIdx.x;
    const float* xp = x + (size_t)bg * CPG * HW;
    const int N = CPG * HW;
    float s = 0.f, s2 = 0.f;
    for (int i = threadIdx.x; i < N; i += 256) {
        float v = xp[i]; s += v; s2 += v * v;
    }
    __shared__ float sh1[8], sh2[8];
    int lane = threadIdx.x & 31, wid = threadIdx.x >> 5;
    for (int o = 16; o; o >>= 1) {
        s  += __shfl_down_sync(0xffffffffu, s,  o);
        s2 += __shfl_down_sync(0xffffffffu, s2, o);
    }
    if (lane == 0) { sh1[wid] = s; sh2[wid] = s2; }
    __syncthreads();
    if (threadIdx.x == 0) {
        for (int i = 1; i < 8; i++) { sh1[0] += sh1[i]; sh2[0] += sh2[i]; }
        float mean = sh1[0] * (1.f / N);
        float var  = sh2[0] * (1.f / N) - mean * mean;
        g_stats[bg] = make_float2(mean, rsqrtf(var + EPS));
    }
}

// =================== weight convert (hi/lo split) =============================
template<int W>
__global__ __launch_bounds__(256) void convW_kernel(const float* __restrict__ src, int n) {
    bf16* hi = (W == 0) ? g_WhiQ : g_WhiP;
    bf16* lo = (W == 0) ? g_WloQ : g_WloP;
    int i = blockIdx.x * 256 + threadIdx.x;
    if (i < n) {
        float v = src[i];
        bf16 h = __float2bfloat16(v);
        hi[i] = h;
        lo[i] = __float2bfloat16(v - __bfloat162float(h));
    }
}

// ===== fused GN-apply + transpose + convert: x [b][c][n] -> XT [b][n][c] ======
__global__ __launch_bounds__(256) void convT_kernel(const float* __restrict__ x,
                                                    const float* __restrict__ gw,
                                                    const float* __restrict__ gb) {
    __shared__ float t[32][33];
    int n0 = blockIdx.x * 32, c0 = blockIdx.y * 32, b = blockIdx.z;
    const float* ip = x + (size_t)b * C * HW;
    int tx = threadIdx.x, ty = threadIdx.y;  // (32,8)
#pragma unroll
    for (int k = 0; k < 4; k++) {
        int ch = c0 + ty + k * 8;
        float2 st = g_stats[b * G + (ch >> 4)];
        float v = ip[(size_t)ch * HW + n0 + tx];
        t[ty + k * 8][tx] = (v - st.x) * st.y * gw[ch] + gb[ch];
    }
    __syncthreads();
#pragma unroll
    for (int k = 0; k < 4; k++) {
        int ni = ty + k * 8;
        float v = t[tx][ni];
        bf16 h = __float2bfloat16(v);
        size_t o = (size_t)b * HW * C + (size_t)(n0 + ni) * C + c0 + tx;
        g_XTh[o] = h;
        g_XTl[o] = __float2bfloat16(v - __bfloat162float(h));
    }
}

// =================== QKV GEMM with fused split/transpose epilogue =============
// A = W (hi/lo, [m][k]), B = XT (hi/lo, [b][n][k]). 128x128 tiles, K=512.
// m in [0,512): q -> [bh][i][d] (x0.125); [512,1024): k -> [bh][i][d];
// [1024,1536): v -> [bh][d][j] (direct orientation).
#define KC   32
#define ROWB 80
#define SM128 (2 * (4 * 128 * ROWB))   // 81920

__global__ __launch_bounds__(256) void qkv_gemm(const float* __restrict__ bias) {
    constexpr int BM = 128, BN = 128;
    constexpr int ATILE = BM * ROWB;
    constexpr int BTILE = BN * ROWB;
    constexpr int STAGE = 2 * ATILE + 2 * BTILE;
    extern __shared__ char smem[];

    const int tid = threadIdx.x;
    const int lane = tid & 31, wid = tid >> 5;
    const int wm = wid & 1, wn = wid >> 1;
    const int n0 = blockIdx.x * BN, m0 = blockIdx.y * BM;
    const int z = blockIdx.z;   // batch

    const bf16* pAh = g_WhiQ + (size_t)m0 * C;
    const bf16* pAl = g_WloQ + (size_t)m0 * C;
    const bf16* pBh = g_XTh + ((size_t)z * HW + n0) * C;
    const bf16* pBl = g_XTl + ((size_t)z * HW + n0) * C;

    auto load_chunk = [&](int stage, int k0) {
        char* sb = smem + stage * STAGE;
#pragma unroll
        for (int it = 0; it < 8; it++) {
            int idx = tid + it * 256;
            int row = idx >> 2, seg = idx & 3;
            const bf16* src; int toff; int r;
            if (row < BM)              { src = pAh; toff = 0;              r = row; }
            else if (row < 2 * BM)     { src = pAl; toff = ATILE;          r = row - BM; }
            else if (row < 2 * BM + BN){ src = pBh; toff = 2 * ATILE;      r = row - 2 * BM; }
            else                       { src = pBl; toff = 2 * ATILE + BTILE; r = row - 2 * BM - BN; }
            CP_ASYNC16(smem_u32(sb + toff + r * ROWB + seg * 16),
                       src + (size_t)r * C + k0 + seg * 8);
        }
        CP_COMMIT();
    };

    float acc[4][4][4];
#pragma unroll
    for (int mi = 0; mi < 4; mi++)
#pragma unroll
        for (int ni = 0; ni < 4; ni++)
#pragma unroll
            for (int j = 0; j < 4; j++) acc[mi][ni][j] = 0.f;

    load_chunk(0, 0);
#pragma unroll 1
    for (int c = 0; c < 16; c++) {
        if (c + 1 < 16) { load_chunk((c + 1) & 1, (c + 1) * KC); CP_WAIT1(); }
        else            { CP_WAIT0(); }
        __syncthreads();
        char* sb = smem + (c & 1) * STAGE;
        uint32_t aH = smem_u32(sb);
        uint32_t aL = aH + ATILE;
        uint32_t bH = aH + 2 * ATILE;
        uint32_t bL = bH + BTILE;
#pragma unroll
        for (int ks = 0; ks < 2; ks++) {
            uint32_t ah[4][4], al[4][4], bh[4][2], bl[4][2];
            int acol = ks * 16 + (lane >> 4) * 8;
#pragma unroll
            for (int mi = 0; mi < 4; mi++) {
                uint32_t off = (uint32_t)((wm * 64 + mi * 16 + (lane & 15)) * ROWB + acol * 2);
                LDSM_X4(ah[mi], aH + off);
                LDSM_X4(al[mi], aL + off);
            }
            int l = lane & 15;
            int bcol = ks * 16 + (l >> 3) * 8;
#pragma unroll
            for (int ni = 0; ni < 4; ni++) {
                uint32_t off = (uint32_t)((wn * 32 + ni * 8 + (l & 7)) * ROWB + bcol * 2);
                LDSM_X2(bh[ni], bH + off);
                LDSM_X2(bl[ni], bL + off);
            }
#pragma unroll
            for (int mi = 0; mi < 4; mi++)
#pragma unroll
                for (int ni = 0; ni < 4; ni++) {
                    mma_bf16(acc[mi][ni], ah[mi], bh[ni]);
                    mma_bf16(acc[mi][ni], ah[mi], bl[ni]);
                    mma_bf16(acc[mi][ni], al[mi], bh[ni]);
                }
        }
        __syncthreads();
    }

    const int sec = m0 >> 9;          // 0=q, 1=k, 2=v
    const float scale = (sec == 0) ? 0.125f : 1.0f;

    if (sec == 2) {
        // v: direct orientation [bh][d][j]
#pragma unroll
        for (int mi = 0; mi < 4; mi++)
#pragma unroll
            for (int ni = 0; ni < 4; ni++) {
                int col = wn * 32 + ni * 8 + (lane & 3) * 2;
#pragma unroll
                for (int hrow = 0; hrow < 2; hrow++) {
                    int r = wm * 64 + mi * 16 + (lane >> 2) + hrow * 8;
                    int mC = (m0 - 1024) + r;          // channel in v section
                    float bm = bias[m0 + r];
                    float vx = acc[mi][ni][hrow * 2 + 0] + bm;
                    float vy = acc[mi][ni][hrow * 2 + 1] + bm;
                    uint32_t uh, ul;
                    pack2(uh, ul, vx, vy);
                    size_t o = ((size_t)(z * HEADS + (mC >> 6)) * DH + (mC & 63)) * HW + n0 + col;
                    *(uint32_t*)&g_Vh[o] = uh;
                    *(uint32_t*)&g_Vl[o] = ul;
                }
            }
    } else {
        // q/k: stage fp32 in smem, transpose to [bh][i][d]
        float* ts = (float*)smem;
        __syncthreads();
#pragma unroll
        for (int mi = 0; mi < 4; mi++)
#pragma unroll
            for (int ni = 0; ni < 4; ni++) {
                int col = wn * 32 + ni * 8 + (lane & 3) * 2;
#pragma unroll
                for (int hrow = 0; hrow < 2; hrow++) {
                    int r = wm * 64 + mi * 16 + (lane >> 2) + hrow * 8;
                    float bm = bias[m0 + r];
                    ts[r * 132 + col]     = (acc[mi][ni][hrow * 2 + 0] + bm) * scale;
                    ts[r * 132 + col + 1] = (acc[mi][ni][hrow * 2 + 1] + bm) * scale;
                }
            }
        __syncthreads();
        bf16* oh = sec ? g_kTh : g_qTh;
        bf16* ol = sec ? g_kTl : g_qTl;
        int h0 = (m0 & 511) >> 6;       // first head in this tile (covers 2)
#pragma unroll
        for (int it = 0; it < 32; it++) {
            int e = tid + it * 256;      // 8192 uint32 stores
            int i = e & 127;
            int rest = e >> 7;           // 0..63
            int hh = rest & 1, dp = rest >> 1;   // dp: 0..31 pairs of d
            float a = ts[(hh * 64 + dp * 2)     * 132 + i];
            float bb = ts[(hh * 64 + dp * 2 + 1) * 132 + i];
            uint32_t uh, ul;
            pack2(uh, ul, a, bb);
            size_t o = ((size_t)(z * HEADS + h0 + hh) * HW + n0 + i) * DH + dp * 2;
            *(uint32_t*)&oh[o] = uh;
            *(uint32_t*)&ol[o] = ul;
        }
    }
}

// =================== flash attention ==========================================
#define QROWB   144
#define VROWB   272
#define FL_QTILE 18432
#define FL_VTILE 17408
#define FL_STAGE0 (2 * FL_QTILE)
#define FL_STAGEB (2 * FL_QTILE + 2 * FL_VTILE)
#define FL_SMEM   (FL_STAGE0 + 2 * FL_STAGEB)

__global__ __launch_bounds__(256, 1) void flash_kernel() {
    extern __shared__ char smem[];
    const int tid = threadIdx.x, lane = tid & 31, wid = tid >> 5;
    const int i0 = blockIdx.x * 128;
    const int bh = blockIdx.y;
    const int b = bh >> 3, h = bh & 7;
    const int wr = wid * 16;

    auto ld_Q = [&]() {
#pragma unroll
        for (int it = 0; it < 8; it++) {
            int idx = tid + it * 256;
            int tile = idx >> 10, r = (idx >> 3) & 127, seg = idx & 7;
            const bf16* src = (tile ? g_qTl : g_qTh) +
                              ((size_t)bh * HW + i0 + r) * DH + seg * 8;
            CP_ASYNC16(smem_u32(smem + tile * FL_QTILE + r * QROWB + seg * 16), src);
        }
    };
    auto ld_KV = [&](int jt, int st) {
        char* sb = smem + FL_STAGE0 + st * FL_STAGEB;
        int j0 = jt * 128;
#pragma unroll
        for (int it = 0; it < 8; it++) {
            int idx = tid + it * 256;
            int tile = idx >> 10, r = (idx >> 3) & 127, seg = idx & 7;
            const bf16* src = (tile ? g_kTl : g_kTh) +
                              ((size_t)bh * HW + j0 + r) * DH + seg * 8;
            CP_ASYNC16(smem_u32(sb + tile * FL_QTILE + r * QROWB + seg * 16), src);
        }
#pragma unroll
        for (int it = 0; it < 8; it++) {
            int idx = tid + it * 256;
            int tile = idx >> 10, r = (idx >> 4) & 63, seg = idx & 15;
            const bf16* src = (tile ? g_Vl : g_Vh) +
                              ((size_t)bh * DH + r) * HW + j0 + seg * 8;
            CP_ASYNC16(smem_u32(sb + 2 * FL_QTILE + tile * FL_VTILE + r * VROWB + seg * 16), src);
        }
    };

    float acc_o[8][4];
#pragma unroll
    for (int dt = 0; dt < 8; dt++)
#pragma unroll
        for (int j = 0; j < 4; j++) acc_o[dt][j] = 0.f;
    float mrow0 = -INFINITY, mrow1 = -INFINITY;
    float lrow0 = 0.f, lrow1 = 0.f;

    const uint32_t qH = smem_u32(smem);
    const uint32_t qL = qH + FL_QTILE;

    ld_Q(); ld_KV(0, 0); CP_COMMIT();
    ld_KV(1, 1); CP_COMMIT();
    CP_WAIT1();
    __syncthreads();

#pragma unroll 1
    for (int jt = 0; jt < 8; jt++) {
        uint32_t kb = smem_u32(smem + FL_STAGE0 + (jt & 1) * FL_STAGEB);
        uint32_t kH = kb, kL = kb + FL_QTILE;
        uint32_t vH = kb + 2 * FL_QTILE, vL = vH + FL_VTILE;

        float s[16][4];
#pragma unroll
        for (int nt = 0; nt < 16; nt++)
#pragma unroll
            for (int j = 0; j < 4; j++) s[nt][j] = 0.f;

#pragma unroll
        for (int ks = 0; ks < 4; ks++) {
            uint32_t ah[4], al[4];
            uint32_t aoff = (uint32_t)((wr + (lane & 15)) * QROWB +
                                       (ks * 16 + (lane >> 4) * 8) * 2);
            LDSM_X4(ah, qH + aoff);
            LDSM_X4(al, qL + aoff);
            int krow_l = ((lane >> 4) << 3) + (lane & 7);
            int kcol = ks * 16 + ((lane >> 3) & 1) * 8;
#pragma unroll
            for (int ntp = 0; ntp < 8; ntp++) {
                uint32_t bh_[4], bl_[4];
                uint32_t boff = (uint32_t)((ntp * 16 + krow_l) * QROWB + kcol * 2);
                LDSM_X4(bh_, kH + boff);
                LDSM_X4(bl_, kL + boff);
                mma_bf16(s[2 * ntp],     ah, bh_);
                mma_bf16(s[2 * ntp],     ah, bl_);
                mma_bf16(s[2 * ntp],     al, bh_);
                mma_bf16(s[2 * ntp + 1], ah, bh_ + 2);
                mma_bf16(s[2 * ntp + 1], ah, bl_ + 2);
                mma_bf16(s[2 * ntp + 1], al, bh_ + 2);
            }
        }

        float mx0 = -INFINITY, mx1 = -INFINITY;
#pragma unroll
        for (int nt = 0; nt < 16; nt++) {
            mx0 = fmaxf(mx0, fmaxf(s[nt][0], s[nt][1]));
            mx1 = fmaxf(mx1, fmaxf(s[nt][2], s[nt][3]));
        }
        mx0 = fmaxf(mx0, __shfl_xor_sync(0xffffffffu, mx0, 1));
        mx0 = fmaxf(mx0, __shfl_xor_sync(0xffffffffu, mx0, 2));
        mx1 = fmaxf(mx1, __shfl_xor_sync(0xffffffffu, mx1, 1));
        mx1 = fmaxf(mx1, __shfl_xor_sync(0xffffffffu, mx1, 2));
        float mn0 = fmaxf(mrow0, mx0), mn1 = fmaxf(mrow1, mx1);
        float al0 = __expf(mrow0 - mn0), al1 = __expf(mrow1 - mn1);
        mrow0 = mn0; mrow1 = mn1;
        lrow0 *= al0; lrow1 *= al1;
#pragma unroll
        for (int dt = 0; dt < 8; dt++) {
            acc_o[dt][0] *= al0; acc_o[dt][1] *= al0;
            acc_o[dt][2] *= al1; acc_o[dt][3] *= al1;
        }
        float ps0 = 0.f, ps1 = 0.f;
#pragma unroll
        for (int nt = 0; nt < 16; nt++) {
            s[nt][0] = __expf(s[nt][0] - mn0);
            s[nt][1] = __expf(s[nt][1] - mn0);
            s[nt][2] = __expf(s[nt][2] - mn1);
            s[nt][3] = __expf(s[nt][3] - mn1);
            ps0 += s[nt][0] + s[nt][1];
            ps1 += s[nt][2] + s[nt][3];
        }
        lrow0 += ps0; lrow1 += ps1;

#pragma unroll
        for (int kk = 0; kk < 8; kk++) {
            uint32_t aph[4], apl[4];
            pack2(aph[0], apl[0], s[2 * kk][0],     s[2 * kk][1]);
            pack2(aph[1], apl[1], s[2 * kk][2],     s[2 * kk][3]);
            pack2(aph[2], apl[2], s[2 * kk + 1][0], s[2 * kk + 1][1]);
            pack2(aph[3], apl[3], s[2 * kk + 1][2], s[2 * kk + 1][3]);
            int vrow_l = ((lane >> 4) << 3) + (lane & 7);
            int vcol = kk * 16 + ((lane >> 3) & 1) * 8;
#pragma unroll
            for (int dt = 0; dt < 4; dt++) {
                uint32_t bvh[4], bvl[4];
                uint32_t off = (uint32_t)((dt * 16 + vrow_l) * VROWB + vcol * 2);
                LDSM_X4(bvh, vH + off);
                LDSM_X4(bvl, vL + off);
                mma_bf16(acc_o[2 * dt],     aph, bvh);
                mma_bf16(acc_o[2 * dt],     aph, bvl);
                mma_bf16(acc_o[2 * dt],     apl, bvh);
                mma_bf16(acc_o[2 * dt + 1], aph, bvh + 2);
                mma_bf16(acc_o[2 * dt + 1], aph, bvl + 2);
                mma_bf16(acc_o[2 * dt + 1], apl, bvh + 2);
            }
        }

        __syncthreads();
        if (jt + 2 < 8)      { ld_KV(jt + 2, jt & 1); CP_COMMIT(); CP_WAIT1(); }
        else if (jt + 1 < 8) { CP_WAIT0(); }
        __syncthreads();
    }

    lrow0 += __shfl_xor_sync(0xffffffffu, lrow0, 1);
    lrow0 += __shfl_xor_sync(0xffffffffu, lrow0, 2);
    lrow1 += __shfl_xor_sync(0xffffffffu, lrow1, 1);
    lrow1 += __shfl_xor_sync(0xffffffffu, lrow1, 2);
    float inv0 = 1.f / lrow0, inv1 = 1.f / lrow1;

    int r0 = i0 + wr + (lane >> 2);
    int cbase = h * DH + (lane & 3) * 2;
#pragma unroll
    for (int dt = 0; dt < 8; dt++) {
        uint32_t uh, ul;
        pack2(uh, ul, acc_o[dt][0] * inv0, acc_o[dt][1] * inv0);
        size_t o0 = ((size_t)b * HW + r0) * C + cbase + dt * 8;
        *(uint32_t*)&g_AOTh[o0] = uh;
        *(uint32_t*)&g_AOTl[o0] = ul;
        pack2(uh, ul, acc_o[dt][2] * inv1, acc_o[dt][3] * inv1);
        size_t o1 = ((size_t)b * HW + r0 + 8) * C + cbase + dt * 8;
        *(uint32_t*)&g_AOTh[o1] = uh;
        *(uint32_t*)&g_AOTl[o1] = ul;
    }
}

// =================== proj GEMM (+bias +residual) ==============================
__global__ __launch_bounds__(256) void proj_gemm(const float* __restrict__ bias,
                                                 const float* __restrict__ resid,
                                                 float* __restrict__ out) {
    constexpr int BM = 128, BN = 128;
    constexpr int ATILE = BM * ROWB;
    constexpr int BTILE = BN * ROWB;
    constexpr int STAGE = 2 * ATILE + 2 * BTILE;
    extern __shared__ char smem[];

    const int tid = threadIdx.x;
    const int lane = tid & 31, wid = tid >> 5;
    const int wm = wid & 1, wn = wid >> 1;
    const int n0 = blockIdx.x * BN, m0 = blockIdx.y * BM;
    const int z = blockIdx.z;

    const bf16* pAh = g_WhiP + (size_t)m0 * C;
    const bf16* pAl = g_WloP + (size_t)m0 * C;
    const bf16* pBh = g_AOTh + ((size_t)z * HW + n0) * C;
    const bf16* pBl = g_AOTl + ((size_t)z * HW + n0) * C;

    auto load_chunk = [&](int stage, int k0) {
        char* sb = smem + stage * STAGE;
#pragma unroll
        for (int it = 0; it < 8; it++) {
            int idx = tid + it * 256;
            int row = idx >> 2, seg = idx & 3;
            const bf16* src; int toff; int r;
            if (row < BM)              { src = pAh; toff = 0;              r = row; }
            else if (row < 2 * BM)     { src = pAl; toff = ATILE;          r = row - BM; }
            else if (row < 2 * BM + BN){ src = pBh; toff = 2 * ATILE;      r = row - 2 * BM; }
            else                       { src = pBl; toff = 2 * ATILE + BTILE; r = row - 2 * BM - BN; }
            CP_ASYNC16(smem_u32(sb + toff + r * ROWB + seg * 16),
                       src + (size_t)r * C + k0 + seg * 8);
        }
        CP_COMMIT();
    };

    float acc[4][4][4];
#pragma unroll
    for (int mi = 0; mi < 4; mi++)
#pragma unroll
        for (int ni = 0; ni < 4; ni++)
#pragma unroll
            for (int j = 0; j < 4; j++) acc[mi][ni][j] = 0.f;

    load_chunk(0, 0);
#pragma unroll 1
    for (int c = 0; c < 16; c++) {
        if (c + 1 < 16) { load_chunk((c + 1) & 1, (c + 1) * KC); CP_WAIT1(); }
        else            { CP_WAIT0(); }
        __syncthreads();
        char* sb = smem + (c & 1) * STAGE;
        uint32_t aH = smem_u32(sb);
        uint32_t aL = aH + ATILE;
        uint32_t bH = aH + 2 * ATILE;
        uint32_t bL = bH + BTILE;
#pragma unroll
        for (int ks = 0; ks < 2; ks++) {
            uint32_t ah[4][4], al[4][4], bh[4][2], bl[4][2];
            int acol = ks * 16 + (lane >> 4) * 8;
#pragma unroll
            for (int mi = 0; mi < 4; mi++) {
                uint32_t off = (uint32_t)((wm * 64 + mi * 16 + (lane & 15)) * ROWB + acol * 2);
                LDSM_X4(ah[mi], aH + off);
                LDSM_X4(al[mi], aL + off);
            }
            int l = lane & 15;
            int bcol = ks * 16 + (l >> 3) * 8;
#pragma unroll
            for (int ni = 0; ni < 4; ni++) {
                uint32_t off = (uint32_t)((wn * 32 + ni * 8 + (l & 7)) * ROWB + bcol * 2);
                LDSM_X2(bh[ni], bH + off);
                LDSM_X2(bl[ni], bL + off);
            }
#pragma unroll
            for (int mi = 0; mi < 4; mi++)
#pragma unroll
                for (int ni = 0; ni < 4; ni++) {
                    mma_bf16(acc[mi][ni], ah[mi], bh[ni]);
                    mma_bf16(acc[mi][ni], ah[mi], bl[ni]);
                    mma_bf16(acc[mi][ni], al[mi], bh[ni]);
                }
        }
        __syncthreads();
    }

    float* po = out + (size_t)z * C * HW;
#pragma unroll
    for (int mi = 0; mi < 4; mi++)
#pragma unroll
        for (int ni = 0; ni < 4; ni++) {
            int col = n0 + wn * 32 + ni * 8 + (lane & 3) * 2;
#pragma unroll
            for (int hrow = 0; hrow < 2; hrow++) {
                int r = m0 + wm * 64 + mi * 16 + (lane >> 2) + hrow * 8;
                float bm = bias[r];
                size_t off = (size_t)r * HW + col;
                float2 rx = *(const float2*)&resid[(size_t)z * C * HW + off];
                float2 v;
                v.x = acc[mi][ni][hrow * 2 + 0] + bm + rx.x;
                v.y = acc[mi][ni][hrow * 2 + 1] + bm + rx.y;
                *(float2*)&po[off] = v;
            }
        }
}

// =================== launch ===================================================
extern "C" void kernel_launch(void* const* d_in, const int* in_sizes, int n_in,
                              void* d_out, int out_size) {
    const float* x      = (const float*)d_in[0];
    const float* gn_w   = (const float*)d_in[1];
    const float* gn_b   = (const float*)d_in[2];
    const float* qkv_w  = (const float*)d_in[3];
    const float* qkv_b  = (const float*)d_in[4];
    const float* proj_w = (const float*)d_in[5];
    const float* proj_b = (const float*)d_in[6];
    float* out = (float*)d_out;

    static bool init = false;
    if (!init) {
        cudaFuncSetAttribute(qkv_gemm, cudaFuncAttributeMaxDynamicSharedMemorySize, SM128);
        cudaFuncSetAttribute(proj_gemm, cudaFuncAttributeMaxDynamicSharedMemorySize, SM128);
        cudaFuncSetAttribute(flash_kernel, cudaFuncAttributeMaxDynamicSharedMemorySize, FL_SMEM);
        init = true;
    }

    gn_stats_kernel<<<B * G, 256>>>(x);
    convW_kernel<0><<<(3 * C * C + 255) / 256, 256>>>(qkv_w, 3 * C * C);
    convW_kernel<1><<<(C * C + 255) / 256, 256>>>(proj_w, C * C);
    convT_kernel<<<dim3(HW / 32, C / 32, B), dim3(32, 8)>>>(x, gn_w, gn_b);

    qkv_gemm<<<dim3(HW / 128, 3 * C / 128, B), 256, SM128>>>(qkv_b);

    flash_kernel<<<dim3(HW / 128, B * HEADS), 256, FL_SMEM>>>();

    proj_gemm<<<dim3(HW / 128, C / 128, B), 256, SM128>>>(proj_b, x, out);
}

// round 6
// speedup vs baseline: 3.6914x; 1.3559x over previous
#include <cuda_runtime.h>
#include <cuda_fp16.h>
#include <cstdint>
#include <math.h>

#define B    8
#define C    512
#define HW   1024
#define G    32
#define CPG  16
#define HEADS 8
#define DH   64
#define EPS  1e-5f

// ---------------- scratch (device globals) ----------------------------------
__device__ float2 g_stats[B * G];                         // mean, inv per group

__device__ __half g_WhQ[3 * C * C];                        // qkv weights hi
__device__ __half g_WhP[C * C];                            // proj weights hi
__device__ __half g_XTh [B * HW * C], g_XTl [B * HW * C];  // [b][n][c]
__device__ __half g_AOTh[B * HW * C], g_AOTl[B * HW * C];  // [b][i][c] attn out
__device__ __half g_qTh [B * HEADS * HW * DH];             // [bh][i][d] (pre-scaled, hi only)
__device__ __half g_kTh [B * HEADS * HW * DH], g_kTl[B * HEADS * HW * DH];
__device__ __half g_Vh  [B * HEADS * DH * HW], g_Vl [B * HEADS * DH * HW]; // [bh][d][j]

// =================== helpers ==================================================
__device__ __forceinline__ uint32_t smem_u32(const void* p) {
    uint32_t r;
    asm("{ .reg .u64 t; cvta.to.shared.u64 t, %1; cvt.u32.u64 %0, t; }"
        : "=r"(r) : "l"(p));
    return r;
}
#define CP_ASYNC16(dst, src) \
    asm volatile("cp.async.cg.shared.global [%0], [%1], 16;" :: "r"(dst), "l"(src) : "memory")
#define CP_COMMIT() asm volatile("cp.async.commit_group;" ::: "memory")
#define CP_WAIT1()  asm volatile("cp.async.wait_group 1;" ::: "memory")
#define CP_WAIT0()  asm volatile("cp.async.wait_group 0;" ::: "memory")

#define LDSM_X4(r, addr) \
    asm volatile("ldmatrix.sync.aligned.m8n8.x4.shared.b16 {%0,%1,%2,%3}, [%4];" \
        : "=r"((r)[0]), "=r"((r)[1]), "=r"((r)[2]), "=r"((r)[3]) : "r"(addr))
#define LDSM_X2(r, addr) \
    asm volatile("ldmatrix.sync.aligned.m8n8.x2.shared.b16 {%0,%1}, [%2];" \
        : "=r"((r)[0]), "=r"((r)[1]) : "r"(addr))

__device__ __forceinline__ void mma_f16(float* c, const uint32_t* a, const uint32_t* b) {
    asm volatile(
        "mma.sync.aligned.m16n8k16.row.col.f32.f16.f16.f32 "
        "{%0,%1,%2,%3}, {%4,%5,%6,%7}, {%8,%9}, {%0,%1,%2,%3};"
        : "+f"(c[0]), "+f"(c[1]), "+f"(c[2]), "+f"(c[3])
        : "r"(a[0]), "r"(a[1]), "r"(a[2]), "r"(a[3]), "r"(b[0]), "r"(b[1]));
}

__device__ __forceinline__ void pack2h(uint32_t& hi, uint32_t& lo, float x, float y) {
    __half2 h = __floats2half2_rn(x, y);
    float hx = __half2float(__low2half(h)), hy = __half2float(__high2half(h));
    __half2 l = __floats2half2_rn(x - hx, y - hy);
    hi = *(uint32_t*)&h;
    lo = *(uint32_t*)&l;
}
__device__ __forceinline__ uint32_t packh(float x, float y) {
    __half2 h = __floats2half2_rn(x, y);
    return *(uint32_t*)&h;
}

// =================== GroupNorm stats ==========================================
__global__ __launch_bounds__(256) void gn_stats_kernel(const float* __restrict__ x) {
    int bg = blockIdx.x;
    const float4* xp = (const float4*)(x + (size_t)bg * CPG * HW);
    const int N4 = CPG * HW / 4;
    float s = 0.f, s2 = 0.f;
    for (int i = threadIdx.x; i < N4; i += 256) {
        float4 v = xp[i];
        s  += v.x + v.y + v.z + v.w;
        s2 += v.x * v.x + v.y * v.y + v.z * v.z + v.w * v.w;
    }
    __shared__ float sh1[8], sh2[8];
    int lane = threadIdx.x & 31, wid = threadIdx.x >> 5;
    for (int o = 16; o; o >>= 1) {
        s  += __shfl_down_sync(0xffffffffu, s,  o);
        s2 += __shfl_down_sync(0xffffffffu, s2, o);
    }
    if (lane == 0) { sh1[wid] = s; sh2[wid] = s2; }
    __syncthreads();
    if (threadIdx.x == 0) {
        for (int i = 1; i < 8; i++) { sh1[0] += sh1[i]; sh2[0] += sh2[i]; }
        const float N = CPG * HW;
        float mean = sh1[0] * (1.f / N);
        float var  = sh2[0] * (1.f / N) - mean * mean;
        g_stats[bg] = make_float2(mean, rsqrtf(var + EPS));
    }
}

// =================== weight convert (hi only) =================================
template<int W>
__global__ __launch_bounds__(256) void convW_kernel(const float* __restrict__ src, int n) {
    __half* hi = (W == 0) ? g_WhQ : g_WhP;
    int i = blockIdx.x * 256 + threadIdx.x;
    if (i < n) hi[i] = __float2half(src[i]);
}

// ===== fused GN-apply + transpose + convert: x [b][c][n] -> XT [b][n][c] ======
__global__ __launch_bounds__(256) void convT_kernel(const float* __restrict__ x,
                                                    const float* __restrict__ gw,
                                                    const float* __restrict__ gb) {
    __shared__ float t[32][33];
    int n0 = blockIdx.x * 32, c0 = blockIdx.y * 32, b = blockIdx.z;
    const float* ip = x + (size_t)b * C * HW;
    int tx = threadIdx.x, ty = threadIdx.y;  // (32,8)
#pragma unroll
    for (int k = 0; k < 4; k++) {
        int ch = c0 + ty + k * 8;
        float2 st = g_stats[b * G + (ch >> 4)];
        float v = ip[(size_t)ch * HW + n0 + tx];
        t[ty + k * 8][tx] = (v - st.x) * st.y * gw[ch] + gb[ch];
    }
    __syncthreads();
#pragma unroll
    for (int k = 0; k < 4; k++) {
        int ni = ty + k * 8;
        float v = t[tx][ni];
        __half h = __float2half(v);
        size_t o = (size_t)b * HW * C + (size_t)(n0 + ni) * C + c0 + tx;
        g_XTh[o] = h;
        g_XTl[o] = __float2half(v - __half2float(h));
    }
}

// =================== QKV GEMM (2-term fp16) ===================================
// A = Wh [m][k]; B = XT hi/lo [b][n][k].  D = Ah*Bh + Ah*Bl.
// m in [0,512): q -> [bh][i][d] hi only (x0.125); [512,1024): k -> hi/lo;
// [1024,1536): v -> [bh][d][j] hi/lo.
#define KC   32
#define ROWB 80
#define SMQKV 69632    // max(2*3*128*80=61440, epilogue 128*132*4=67584)
#define SMPROJ 61440

__global__ __launch_bounds__(256) void qkv_gemm(const float* __restrict__ bias) {
    constexpr int BM = 128, BN = 128;
    constexpr int TILE = BM * ROWB;          // 10240
    constexpr int STAGE = 3 * TILE;
    extern __shared__ char smem[];

    const int tid = threadIdx.x;
    const int lane = tid & 31, wid = tid >> 5;
    const int wm = wid & 1, wn = wid >> 1;
    const int n0 = blockIdx.x * BN, m0 = blockIdx.y * BM;
    const int z = blockIdx.z;

    const __half* pA  = g_WhQ + (size_t)m0 * C;
    const __half* pBh = g_XTh + ((size_t)z * HW + n0) * C;
    const __half* pBl = g_XTl + ((size_t)z * HW + n0) * C;

    auto load_chunk = [&](int stage, int k0) {
        char* sb = smem + stage * STAGE;
#pragma unroll
        for (int it = 0; it < 6; it++) {
            int idx = tid + it * 256;
            int row = idx >> 2, seg = idx & 3;
            const __half* src; int toff; int r;
            if (row < BM)          { src = pA;  toff = 0;        r = row; }
            else if (row < 2 * BM) { src = pBh; toff = TILE;     r = row - BM; }
            else                   { src = pBl; toff = 2 * TILE; r = row - 2 * BM; }
            CP_ASYNC16(smem_u32(sb + toff + r * ROWB + seg * 16),
                       src + (size_t)r * C + k0 + seg * 8);
        }
        CP_COMMIT();
    };

    float acc[4][4][4];
#pragma unroll
    for (int mi = 0; mi < 4; mi++)
#pragma unroll
        for (int ni = 0; ni < 4; ni++)
#pragma unroll
            for (int j = 0; j < 4; j++) acc[mi][ni][j] = 0.f;

    load_chunk(0, 0);
#pragma unroll 1
    for (int c = 0; c < 16; c++) {
        if (c + 1 < 16) { load_chunk((c + 1) & 1, (c + 1) * KC); CP_WAIT1(); }
        else            { CP_WAIT0(); }
        __syncthreads();
        char* sb = smem + (c & 1) * STAGE;
        uint32_t aH = smem_u32(sb);
        uint32_t bH = aH + TILE;
        uint32_t bL = aH + 2 * TILE;
#pragma unroll
        for (int ks = 0; ks < 2; ks++) {
            uint32_t ah[4][4], bh[4][2], bl[4][2];
            int acol = ks * 16 + (lane >> 4) * 8;
#pragma unroll
            for (int mi = 0; mi < 4; mi++) {
                uint32_t off = (uint32_t)((wm * 64 + mi * 16 + (lane & 15)) * ROWB + acol * 2);
                LDSM_X4(ah[mi], aH + off);
            }
            int l = lane & 15;
            int bcol = ks * 16 + (l >> 3) * 8;
#pragma unroll
            for (int ni = 0; ni < 4; ni++) {
                uint32_t off = (uint32_t)((wn * 32 + ni * 8 + (l & 7)) * ROWB + bcol * 2);
                LDSM_X2(bh[ni], bH + off);
                LDSM_X2(bl[ni], bL + off);
            }
#pragma unroll
            for (int mi = 0; mi < 4; mi++)
#pragma unroll
                for (int ni = 0; ni < 4; ni++) {
                    mma_f16(acc[mi][ni], ah[mi], bh[ni]);
                    mma_f16(acc[mi][ni], ah[mi], bl[ni]);
                }
        }
        __syncthreads();
    }

    const int sec = m0 >> 9;          // 0=q, 1=k, 2=v
    const float scale = (sec == 0) ? 0.125f : 1.0f;

    if (sec == 2) {
        // v: direct orientation [bh][d][j], hi/lo
#pragma unroll
        for (int mi = 0; mi < 4; mi++)
#pragma unroll
            for (int ni = 0; ni < 4; ni++) {
                int col = wn * 32 + ni * 8 + (lane & 3) * 2;
#pragma unroll
                for (int hrow = 0; hrow < 2; hrow++) {
                    int r = wm * 64 + mi * 16 + (lane >> 2) + hrow * 8;
                    int mC = (m0 - 1024) + r;
                    float bm = bias[m0 + r];
                    uint32_t uh, ul;
                    pack2h(uh, ul, acc[mi][ni][hrow * 2 + 0] + bm,
                                   acc[mi][ni][hrow * 2 + 1] + bm);
                    size_t o = ((size_t)(z * HEADS + (mC >> 6)) * DH + (mC & 63)) * HW + n0 + col;
                    *(uint32_t*)&g_Vh[o] = uh;
                    *(uint32_t*)&g_Vl[o] = ul;
                }
            }
    } else {
        // q/k: stage fp32 in smem, transpose to [bh][i][d]
        float* ts = (float*)smem;
        __syncthreads();
#pragma unroll
        for (int mi = 0; mi < 4; mi++)
#pragma unroll
            for (int ni = 0; ni < 4; ni++) {
                int col = wn * 32 + ni * 8 + (lane & 3) * 2;
#pragma unroll
                for (int hrow = 0; hrow < 2; hrow++) {
                    int r = wm * 64 + mi * 16 + (lane >> 2) + hrow * 8;
                    float bm = bias[m0 + r];
                    ts[r * 132 + col]     = (acc[mi][ni][hrow * 2 + 0] + bm) * scale;
                    ts[r * 132 + col + 1] = (acc[mi][ni][hrow * 2 + 1] + bm) * scale;
                }
            }
        __syncthreads();
        int h0 = (m0 & 511) >> 6;
#pragma unroll
        for (int it = 0; it < 32; it++) {
            int e = tid + it * 256;
            int i = e & 127;
            int rest = e >> 7;
            int hh = rest & 1, dp = rest >> 1;
            float a  = ts[(hh * 64 + dp * 2)     * 132 + i];
            float bb = ts[(hh * 64 + dp * 2 + 1) * 132 + i];
            size_t o = ((size_t)(z * HEADS + h0 + hh) * HW + n0 + i) * DH + dp * 2;
            if (sec == 0) {
                *(uint32_t*)&g_qTh[o] = packh(a, bb);
            } else {
                uint32_t uh, ul;
                pack2h(uh, ul, a, bb);
                *(uint32_t*)&g_kTh[o] = uh;
                *(uint32_t*)&g_kTl[o] = ul;
            }
        }
    }
}

// =================== flash attention (fp16, 2-term) ===========================
#define QROWB   144
#define VROWB   272
#define FL_QTILE 18432
#define FL_VTILE 17408
#define FL_STAGE0 FL_QTILE                         // Q hi only
#define FL_STAGEB (2 * FL_QTILE + 2 * FL_VTILE)    // K hi/lo + V hi/lo
#define FL_SMEM   (FL_STAGE0 + 2 * FL_STAGEB)      // 18432 + 143360 = 161792

__global__ __launch_bounds__(256, 1) void flash_kernel() {
    extern __shared__ char smem[];
    const int tid = threadIdx.x, lane = tid & 31, wid = tid >> 5;
    const int i0 = blockIdx.x * 128;
    const int bh = blockIdx.y;
    const int b = bh >> 3, h = bh & 7;
    const int wr = wid * 16;

    auto ld_Q = [&]() {
#pragma unroll
        for (int it = 0; it < 4; it++) {
            int idx = tid + it * 256;
            int r = idx >> 3, seg = idx & 7;
            const __half* src = g_qTh + ((size_t)bh * HW + i0 + r) * DH + seg * 8;
            CP_ASYNC16(smem_u32(smem + r * QROWB + seg * 16), src);
        }
    };
    auto ld_KV = [&](int jt, int st) {
        char* sb = smem + FL_STAGE0 + st * FL_STAGEB;
        int j0 = jt * 128;
#pragma unroll
        for (int it = 0; it < 8; it++) {
            int idx = tid + it * 256;
            int tile = idx >> 10, r = (idx >> 3) & 127, seg = idx & 7;
            const __half* src = (tile ? g_kTl : g_kTh) +
                                ((size_t)bh * HW + j0 + r) * DH + seg * 8;
            CP_ASYNC16(smem_u32(sb + tile * FL_QTILE + r * QROWB + seg * 16), src);
        }
#pragma unroll
        for (int it = 0; it < 8; it++) {
            int idx = tid + it * 256;
            int tile = idx >> 10, r = (idx >> 4) & 63, seg = idx & 15;
            const __half* src = (tile ? g_Vl : g_Vh) +
                                ((size_t)bh * DH + r) * HW + j0 + seg * 8;
            CP_ASYNC16(smem_u32(sb + 2 * FL_QTILE + tile * FL_VTILE + r * VROWB + seg * 16), src);
        }
    };

    float acc_o[8][4];
#pragma unroll
    for (int dt = 0; dt < 8; dt++)
#pragma unroll
        for (int j = 0; j < 4; j++) acc_o[dt][j] = 0.f;
    float mrow0 = -INFINITY, mrow1 = -INFINITY;
    float lrow0 = 0.f, lrow1 = 0.f;

    const uint32_t qH = smem_u32(smem);

    ld_Q(); ld_KV(0, 0); CP_COMMIT();
    ld_KV(1, 1); CP_COMMIT();
    CP_WAIT1();
    __syncthreads();

#pragma unroll 1
    for (int jt = 0; jt < 8; jt++) {
        uint32_t kb = smem_u32(smem + FL_STAGE0 + (jt & 1) * FL_STAGEB);
        uint32_t kH = kb, kL = kb + FL_QTILE;
        uint32_t vH = kb + 2 * FL_QTILE, vL = vH + FL_VTILE;

        float s[16][4];
#pragma unroll
        for (int nt = 0; nt < 16; nt++)
#pragma unroll
            for (int j = 0; j < 4; j++) s[nt][j] = 0.f;

#pragma unroll
        for (int ks = 0; ks < 4; ks++) {
            uint32_t ah[4];
            uint32_t aoff = (uint32_t)((wr + (lane & 15)) * QROWB +
                                       (ks * 16 + (lane >> 4) * 8) * 2);
            LDSM_X4(ah, qH + aoff);
            int krow_l = ((lane >> 4) << 3) + (lane & 7);
            int kcol = ks * 16 + ((lane >> 3) & 1) * 8;
#pragma unroll
            for (int ntp = 0; ntp < 8; ntp++) {
                uint32_t bh_[4], bl_[4];
                uint32_t boff = (uint32_t)((ntp * 16 + krow_l) * QROWB + kcol * 2);
                LDSM_X4(bh_, kH + boff);
                LDSM_X4(bl_, kL + boff);
                mma_f16(s[2 * ntp],     ah, bh_);
                mma_f16(s[2 * ntp],     ah, bl_);
                mma_f16(s[2 * ntp + 1], ah, bh_ + 2);
                mma_f16(s[2 * ntp + 1], ah, bl_ + 2);
            }
        }

        float mx0 = -INFINITY, mx1 = -INFINITY;
#pragma unroll
        for (int nt = 0; nt < 16; nt++) {
            mx0 = fmaxf(mx0, fmaxf(s[nt][0], s[nt][1]));
            mx1 = fmaxf(mx1, fmaxf(s[nt][2], s[nt][3]));
        }
        mx0 = fmaxf(mx0, __shfl_xor_sync(0xffffffffu, mx0, 1));
        mx0 = fmaxf(mx0, __shfl_xor_sync(0xffffffffu, mx0, 2));
        mx1 = fmaxf(mx1, __shfl_xor_sync(0xffffffffu, mx1, 1));
        mx1 = fmaxf(mx1, __shfl_xor_sync(0xffffffffu, mx1, 2));
        float mn0 = fmaxf(mrow0, mx0), mn1 = fmaxf(mrow1, mx1);
        float al0 = __expf(mrow0 - mn0), al1 = __expf(mrow1 - mn1);
        mrow0 = mn0; mrow1 = mn1;
        lrow0 *= al0; lrow1 *= al1;
#pragma unroll
        for (int dt = 0; dt < 8; dt++) {
            acc_o[dt][0] *= al0; acc_o[dt][1] *= al0;
            acc_o[dt][2] *= al1; acc_o[dt][3] *= al1;
        }
        float ps0 = 0.f, ps1 = 0.f;
#pragma unroll
        for (int nt = 0; nt < 16; nt++) {
            s[nt][0] = __expf(s[nt][0] - mn0);
            s[nt][1] = __expf(s[nt][1] - mn0);
            s[nt][2] = __expf(s[nt][2] - mn1);
            s[nt][3] = __expf(s[nt][3] - mn1);
            ps0 += s[nt][0] + s[nt][1];
            ps1 += s[nt][2] + s[nt][3];
        }
        lrow0 += ps0; lrow1 += ps1;

        // ---- O += P V^T : Ph*Vh + Ph*Vl ----
#pragma unroll
        for (int kk = 0; kk < 8; kk++) {
            uint32_t aph[4];
            aph[0] = packh(s[2 * kk][0],     s[2 * kk][1]);
            aph[1] = packh(s[2 * kk][2],     s[2 * kk][3]);
            aph[2] = packh(s[2 * kk + 1][0], s[2 * kk + 1][1]);
            aph[3] = packh(s[2 * kk + 1][2], s[2 * kk + 1][3]);
            int vrow_l = ((lane >> 4) << 3) + (lane & 7);
            int vcol = kk * 16 + ((lane >> 3) & 1) * 8;
#pragma unroll
            for (int dt = 0; dt < 4; dt++) {
                uint32_t bvh[4], bvl[4];
                uint32_t off = (uint32_t)((dt * 16 + vrow_l) * VROWB + vcol * 2);
                LDSM_X4(bvh, vH + off);
                LDSM_X4(bvl, vL + off);
                mma_f16(acc_o[2 * dt],     aph, bvh);
                mma_f16(acc_o[2 * dt],     aph, bvl);
                mma_f16(acc_o[2 * dt + 1], aph, bvh + 2);
                mma_f16(acc_o[2 * dt + 1], aph, bvl + 2);
            }
        }

        __syncthreads();
        if (jt + 2 < 8)      { ld_KV(jt + 2, jt & 1); CP_COMMIT(); CP_WAIT1(); }
        else if (jt + 1 < 8) { CP_WAIT0(); }
        __syncthreads();
    }

    lrow0 += __shfl_xor_sync(0xffffffffu, lrow0, 1);
    lrow0 += __shfl_xor_sync(0xffffffffu, lrow0, 2);
    lrow1 += __shfl_xor_sync(0xffffffffu, lrow1, 1);
    lrow1 += __shfl_xor_sync(0xffffffffu, lrow1, 2);
    float inv0 = 1.f / lrow0, inv1 = 1.f / lrow1;

    int r0 = i0 + wr + (lane >> 2);
    int cbase = h * DH + (lane & 3) * 2;
#pragma unroll
    for (int dt = 0; dt < 8; dt++) {
        uint32_t uh, ul;
        pack2h(uh, ul, acc_o[dt][0] * inv0, acc_o[dt][1] * inv0);
        size_t o0 = ((size_t)b * HW + r0) * C + cbase + dt * 8;
        *(uint32_t*)&g_AOTh[o0] = uh;
        *(uint32_t*)&g_AOTl[o0] = ul;
        pack2h(uh, ul, acc_o[dt][2] * inv1, acc_o[dt][3] * inv1);
        size_t o1 = ((size_t)b * HW + r0 + 8) * C + cbase + dt * 8;
        *(uint32_t*)&g_AOTh[o1] = uh;
        *(uint32_t*)&g_AOTl[o1] = ul;
    }
}

// =================== proj GEMM (2-term, +bias +residual) ======================
__global__ __launch_bounds__(256) void proj_gemm(const float* __restrict__ bias,
                                                 const float* __restrict__ resid,
                                                 float* __restrict__ out) {
    constexpr int BM = 128, BN = 128;
    constexpr int TILE = BM * ROWB;
    constexpr int STAGE = 3 * TILE;
    extern __shared__ char smem[];

    const int tid = threadIdx.x;
    const int lane = tid & 31, wid = tid >> 5;
    const int wm = wid & 1, wn = wid >> 1;
    const int n0 = blockIdx.x * BN, m0 = blockIdx.y * BM;
    const int z = blockIdx.z;

    const __half* pA  = g_WhP + (size_t)m0 * C;
    const __half* pBh = g_AOTh + ((size_t)z * HW + n0) * C;
    const __half* pBl = g_AOTl + ((size_t)z * HW + n0) * C;

    auto load_chunk = [&](int stage, int k0) {
        char* sb = smem + stage * STAGE;
#pragma unroll
        for (int it = 0; it < 6; it++) {
            int idx = tid + it * 256;
            int row = idx >> 2, seg = idx & 3;
            const __half* src; int toff; int r;
            if (row < BM)          { src = pA;  toff = 0;        r = row; }
            else if (row < 2 * BM) { src = pBh; toff = TILE;     r = row - BM; }
            else                   { src = pBl; toff = 2 * TILE; r = row - 2 * BM; }
            CP_ASYNC16(smem_u32(sb + toff + r * ROWB + seg * 16),
                       src + (size_t)r * C + k0 + seg * 8);
        }
        CP_COMMIT();
    };

    float acc[4][4][4];
#pragma unroll
    for (int mi = 0; mi < 4; mi++)
#pragma unroll
        for (int ni = 0; ni < 4; ni++)
#pragma unroll
            for (int j = 0; j < 4; j++) acc[mi][ni][j] = 0.f;

    load_chunk(0, 0);
#pragma unroll 1
    for (int c = 0; c < 16; c++) {
        if (c + 1 < 16) { load_chunk((c + 1) & 1, (c + 1) * KC); CP_WAIT1(); }
        else            { CP_WAIT0(); }
        __syncthreads();
        char* sb = smem + (c & 1) * STAGE;
        uint32_t aH = smem_u32(sb);
        uint32_t bH = aH + TILE;
        uint32_t bL = aH + 2 * TILE;
#pragma unroll
        for (int ks = 0; ks < 2; ks++) {
            uint32_t ah[4][4], bh[4][2], bl[4][2];
            int acol = ks * 16 + (lane >> 4) * 8;
#pragma unroll
            for (int mi = 0; mi < 4; mi++) {
                uint32_t off = (uint32_t)((wm * 64 + mi * 16 + (lane & 15)) * ROWB + acol * 2);
                LDSM_X4(ah[mi], aH + off);
            }
            int l = lane & 15;
            int bcol = ks * 16 + (l >> 3) * 8;
#pragma unroll
            for (int ni = 0; ni < 4; ni++) {
                uint32_t off = (uint32_t)((wn * 32 + ni * 8 + (l & 7)) * ROWB + bcol * 2);
                LDSM_X2(bh[ni], bH + off);
                LDSM_X2(bl[ni], bL + off);
            }
#pragma unroll
            for (int mi = 0; mi < 4; mi++)
#pragma unroll
                for (int ni = 0; ni < 4; ni++) {
                    mma_f16(acc[mi][ni], ah[mi], bh[ni]);
                    mma_f16(acc[mi][ni], ah[mi], bl[ni]);
                }
        }
        __syncthreads();
    }

    float* po = out + (size_t)z * C * HW;
#pragma unroll
    for (int mi = 0; mi < 4; mi++)
#pragma unroll
        for (int ni = 0; ni < 4; ni++) {
            int col = n0 + wn * 32 + ni * 8 + (lane & 3) * 2;
#pragma unroll
            for (int hrow = 0; hrow < 2; hrow++) {
                int r = m0 + wm * 64 + mi * 16 + (lane >> 2) + hrow * 8;
                float bm = bias[r];
                size_t off = (size_t)r * HW + col;
                float2 rx = *(const float2*)&resid[(size_t)z * C * HW + off];
                float2 v;
                v.x = acc[mi][ni][hrow * 2 + 0] + bm + rx.x;
                v.y = acc[mi][ni][hrow * 2 + 1] + bm + rx.y;
                *(float2*)&po[off] = v;
            }
        }
}

// =================== launch ===================================================
extern "C" void kernel_launch(void* const* d_in, const int* in_sizes, int n_in,
                              void* d_out, int out_size) {
    const float* x      = (const float*)d_in[0];
    const float* gn_w   = (const float*)d_in[1];
    const float* gn_b   = (const float*)d_in[2];
    const float* qkv_w  = (const float*)d_in[3];
    const float* qkv_b  = (const float*)d_in[4];
    const float* proj_w = (const float*)d_in[5];
    const float* proj_b = (const float*)d_in[6];
    float* out = (float*)d_out;

    static bool init = false;
    if (!init) {
        cudaFuncSetAttribute(qkv_gemm, cudaFuncAttributeMaxDynamicSharedMemorySize, SMQKV);
        cudaFuncSetAttribute(proj_gemm, cudaFuncAttributeMaxDynamicSharedMemorySize, SMPROJ);
        cudaFuncSetAttribute(flash_kernel, cudaFuncAttributeMaxDynamicSharedMemorySize, FL_SMEM);
        init = true;
    }

    gn_stats_kernel<<<B * G, 256>>>(x);
    convW_kernel<0><<<(3 * C * C + 255) / 256, 256>>>(qkv_w, 3 * C * C);
    convW_kernel<1><<<(C * C + 255) / 256, 256>>>(proj_w, C * C);
    convT_kernel<<<dim3(HW / 32, C / 32, B), dim3(32, 8)>>>(x, gn_w, gn_b);

    qkv_gemm<<<dim3(HW / 128, 3 * C / 128, B), 256, SMQKV>>>(qkv_b);

    flash_kernel<<<dim3(HW / 128, B * HEADS), 256, FL_SMEM>>>();

    proj_gemm<<<dim3(HW / 128, C / 128, B), 256, SMPROJ>>>(proj_b, x, out);
}

// round 7
// speedup vs baseline: 5.6827x; 1.5395x over previous
#include <cuda_runtime.h>
#include <cuda_fp16.h>
#include <cstdint>
#include <math.h>

#define B    8
#define C    512
#define HW   1024
#define G    32
#define CPG  16
#define HEADS 8
#define DH   64
#define EPS  1e-5f

// ---------------- scratch (device globals) ----------------------------------
__device__ float2 g_stats[B * G];                          // mean, inv per group

__device__ __half g_WhQ[3 * C * C];                        // qkv weights
__device__ __half g_WhP[C * C];                            // proj weights
__device__ __half g_XTh [B * HW * C];                      // [b][n][c] normed x
__device__ __half g_AOTh[B * HW * C];                      // [b][i][c] attn out
__device__ __half g_qTh [B * HEADS * HW * DH];             // [bh][i][d] (pre-scaled)
__device__ __half g_kTh [B * HEADS * HW * DH];             // [bh][j][d]
__device__ __half g_Vh  [B * HEADS * DH * HW];             // [bh][d][j]

// =================== helpers ==================================================
__device__ __forceinline__ uint32_t smem_u32(const void* p) {
    uint32_t r;
    asm("{ .reg .u64 t; cvta.to.shared.u64 t, %1; cvt.u32.u64 %0, t; }"
        : "=r"(r) : "l"(p));
    return r;
}
#define CP_ASYNC16(dst, src) \
    asm volatile("cp.async.cg.shared.global [%0], [%1], 16;" :: "r"(dst), "l"(src) : "memory")
#define CP_COMMIT() asm volatile("cp.async.commit_group;" ::: "memory")
#define CP_WAIT1()  asm volatile("cp.async.wait_group 1;" ::: "memory")
#define CP_WAIT0()  asm volatile("cp.async.wait_group 0;" ::: "memory")

#define LDSM_X4(r, addr) \
    asm volatile("ldmatrix.sync.aligned.m8n8.x4.shared.b16 {%0,%1,%2,%3}, [%4];" \
        : "=r"((r)[0]), "=r"((r)[1]), "=r"((r)[2]), "=r"((r)[3]) : "r"(addr))
#define LDSM_X2(r, addr) \
    asm volatile("ldmatrix.sync.aligned.m8n8.x2.shared.b16 {%0,%1}, [%2];" \
        : "=r"((r)[0]), "=r"((r)[1]) : "r"(addr))

__device__ __forceinline__ void mma_f16(float* c, const uint32_t* a, const uint32_t* b) {
    asm volatile(
        "mma.sync.aligned.m16n8k16.row.col.f32.f16.f16.f32 "
        "{%0,%1,%2,%3}, {%4,%5,%6,%7}, {%8,%9}, {%0,%1,%2,%3};"
        : "+f"(c[0]), "+f"(c[1]), "+f"(c[2]), "+f"(c[3])
        : "r"(a[0]), "r"(a[1]), "r"(a[2]), "r"(a[3]), "r"(b[0]), "r"(b[1]));
}
__device__ __forceinline__ uint32_t packh(float x, float y) {
    __half2 h = __floats2half2_rn(x, y);
    return *(uint32_t*)&h;
}

// =================== GroupNorm stats ==========================================
__global__ __launch_bounds__(256) void gn_stats_kernel(const float* __restrict__ x) {
    int bg = blockIdx.x;
    const float4* xp = (const float4*)(x + (size_t)bg * CPG * HW);
    const int N4 = CPG * HW / 4;
    float s = 0.f, s2 = 0.f;
    for (int i = threadIdx.x; i < N4; i += 256) {
        float4 v = xp[i];
        s  += v.x + v.y + v.z + v.w;
        s2 += v.x * v.x + v.y * v.y + v.z * v.z + v.w * v.w;
    }
    __shared__ float sh1[8], sh2[8];
    int lane = threadIdx.x & 31, wid = threadIdx.x >> 5;
    for (int o = 16; o; o >>= 1) {
        s  += __shfl_down_sync(0xffffffffu, s,  o);
        s2 += __shfl_down_sync(0xffffffffu, s2, o);
    }
    if (lane == 0) { sh1[wid] = s; sh2[wid] = s2; }
    __syncthreads();
    if (threadIdx.x == 0) {
        for (int i = 1; i < 8; i++) { sh1[0] += sh1[i]; sh2[0] += sh2[i]; }
        const float N = CPG * HW;
        float mean = sh1[0] * (1.f / N);
        float var  = sh2[0] * (1.f / N) - mean * mean;
        g_stats[bg] = make_float2(mean, rsqrtf(var + EPS));
    }
}

// =================== weight convert ===========================================
template<int W>
__global__ __launch_bounds__(256) void convW_kernel(const float* __restrict__ src, int n) {
    __half* hi = (W == 0) ? g_WhQ : g_WhP;
    int i = blockIdx.x * 256 + threadIdx.x;
    if (i < n) hi[i] = __float2half(src[i]);
}

// ===== fused GN-apply + transpose + convert: x [b][c][n] -> XT [b][n][c] ======
__global__ __launch_bounds__(256) void convT_kernel(const float* __restrict__ x,
                                                    const float* __restrict__ gw,
                                                    const float* __restrict__ gb) {
    __shared__ float t[32][33];
    int n0 = blockIdx.x * 32, c0 = blockIdx.y * 32, b = blockIdx.z;
    const float* ip = x + (size_t)b * C * HW;
    int tx = threadIdx.x, ty = threadIdx.y;  // (32,8)
#pragma unroll
    for (int k = 0; k < 4; k++) {
        int ch = c0 + ty + k * 8;
        float2 st = g_stats[b * G + (ch >> 4)];
        float v = ip[(size_t)ch * HW + n0 + tx];
        t[ty + k * 8][tx] = (v - st.x) * st.y * gw[ch] + gb[ch];
    }
    __syncthreads();
#pragma unroll
    for (int k = 0; k < 4; k++) {
        int ni = ty + k * 8;
        size_t o = (size_t)b * HW * C + (size_t)(n0 + ni) * C + c0 + tx;
        g_XTh[o] = __float2half(t[tx][ni]);
    }
}

// =================== QKV GEMM (pure fp16) =====================================
// A = Wh [m][k]; B = XTh [b][n][k].  D = A*B.
// m in [0,512): q -> [bh][i][d] (x0.125); [512,1024): k -> [bh][j][d];
// [1024,1536): v -> [bh][d][j].
#define KC   32
#define ROWB 80
#define SMQKV 69632    // epilogue transpose staging dominates (128*132*4)
#define SMPROJ 40960

__global__ __launch_bounds__(256) void qkv_gemm(const float* __restrict__ bias) {
    constexpr int BM = 128, BN = 128;
    constexpr int TILE = BM * ROWB;          // 10240
    constexpr int STAGE = 2 * TILE;
    extern __shared__ char smem[];

    const int tid = threadIdx.x;
    const int lane = tid & 31, wid = tid >> 5;
    const int wm = wid & 1, wn = wid >> 1;
    const int n0 = blockIdx.x * BN, m0 = blockIdx.y * BM;
    const int z = blockIdx.z;

    const __half* pA = g_WhQ + (size_t)m0 * C;
    const __half* pB = g_XTh + ((size_t)z * HW + n0) * C;

    auto load_chunk = [&](int stage, int k0) {
        char* sb = smem + stage * STAGE;
#pragma unroll
        for (int it = 0; it < 4; it++) {
            int idx = tid + it * 256;
            int row = idx >> 2, seg = idx & 3;
            const __half* src; int toff; int r;
            if (row < BM) { src = pA; toff = 0;    r = row; }
            else          { src = pB; toff = TILE; r = row - BM; }
            CP_ASYNC16(smem_u32(sb + toff + r * ROWB + seg * 16),
                       src + (size_t)r * C + k0 + seg * 8);
        }
        CP_COMMIT();
    };

    float acc[4][4][4];
#pragma unroll
    for (int mi = 0; mi < 4; mi++)
#pragma unroll
        for (int ni = 0; ni < 4; ni++)
#pragma unroll
            for (int j = 0; j < 4; j++) acc[mi][ni][j] = 0.f;

    load_chunk(0, 0);
#pragma unroll 1
    for (int c = 0; c < 16; c++) {
        if (c + 1 < 16) { load_chunk((c + 1) & 1, (c + 1) * KC); CP_WAIT1(); }
        else            { CP_WAIT0(); }
        __syncthreads();
        char* sb = smem + (c & 1) * STAGE;
        uint32_t aH = smem_u32(sb);
        uint32_t bH = aH + TILE;
#pragma unroll
        for (int ks = 0; ks < 2; ks++) {
            uint32_t ah[4][4], bh[4][2];
            int acol = ks * 16 + (lane >> 4) * 8;
#pragma unroll
            for (int mi = 0; mi < 4; mi++) {
                uint32_t off = (uint32_t)((wm * 64 + mi * 16 + (lane & 15)) * ROWB + acol * 2);
                LDSM_X4(ah[mi], aH + off);
            }
            int l = lane & 15;
            int bcol = ks * 16 + (l >> 3) * 8;
#pragma unroll
            for (int ni = 0; ni < 4; ni++) {
                uint32_t off = (uint32_t)((wn * 32 + ni * 8 + (l & 7)) * ROWB + bcol * 2);
                LDSM_X2(bh[ni], bH + off);
            }
#pragma unroll
            for (int mi = 0; mi < 4; mi++)
#pragma unroll
                for (int ni = 0; ni < 4; ni++)
                    mma_f16(acc[mi][ni], ah[mi], bh[ni]);
        }
        __syncthreads();
    }

    const int sec = m0 >> 9;          // 0=q, 1=k, 2=v
    const float scale = (sec == 0) ? 0.125f : 1.0f;

    if (sec == 2) {
        // v: direct orientation [bh][d][j]
#pragma unroll
        for (int mi = 0; mi < 4; mi++)
#pragma unroll
            for (int ni = 0; ni < 4; ni++) {
                int col = wn * 32 + ni * 8 + (lane & 3) * 2;
#pragma unroll
                for (int hrow = 0; hrow < 2; hrow++) {
                    int r = wm * 64 + mi * 16 + (lane >> 2) + hrow * 8;
                    int mC = (m0 - 1024) + r;
                    float bm = bias[m0 + r];
                    size_t o = ((size_t)(z * HEADS + (mC >> 6)) * DH + (mC & 63)) * HW + n0 + col;
                    *(uint32_t*)&g_Vh[o] = packh(acc[mi][ni][hrow * 2 + 0] + bm,
                                                 acc[mi][ni][hrow * 2 + 1] + bm);
                }
            }
    } else {
        // q/k: stage fp32 in smem, transpose to [bh][i][d]
        float* ts = (float*)smem;
        __syncthreads();
#pragma unroll
        for (int mi = 0; mi < 4; mi++)
#pragma unroll
            for (int ni = 0; ni < 4; ni++) {
                int col = wn * 32 + ni * 8 + (lane & 3) * 2;
#pragma unroll
                for (int hrow = 0; hrow < 2; hrow++) {
                    int r = wm * 64 + mi * 16 + (lane >> 2) + hrow * 8;
                    float bm = bias[m0 + r];
                    ts[r * 132 + col]     = (acc[mi][ni][hrow * 2 + 0] + bm) * scale;
                    ts[r * 132 + col + 1] = (acc[mi][ni][hrow * 2 + 1] + bm) * scale;
                }
            }
        __syncthreads();
        __half* oh = sec ? g_kTh : g_qTh;
        int h0 = (m0 & 511) >> 6;
#pragma unroll
        for (int it = 0; it < 32; it++) {
            int e = tid + it * 256;
            int i = e & 127;
            int rest = e >> 7;
            int hh = rest & 1, dp = rest >> 1;
            float a  = ts[(hh * 64 + dp * 2)     * 132 + i];
            float bb = ts[(hh * 64 + dp * 2 + 1) * 132 + i];
            size_t o = ((size_t)(z * HEADS + h0 + hh) * HW + n0 + i) * DH + dp * 2;
            *(uint32_t*)&oh[o] = packh(a, bb);
        }
    }
}

// =================== flash attention (pure fp16) ==============================
#define QROWB   144
#define VROWB   272
#define FL_QTILE 18432                        // 128 rows x 144B
#define FL_VTILE 17408                        // 64 rows x 272B
#define FL_STAGE0 FL_QTILE                    // Q
#define FL_STAGEB (FL_QTILE + FL_VTILE)       // K + V
#define FL_SMEM   (FL_STAGE0 + 2 * FL_STAGEB) // 18432 + 71680 = 90112

__global__ __launch_bounds__(256, 1) void flash_kernel() {
    extern __shared__ char smem[];
    const int tid = threadIdx.x, lane = tid & 31, wid = tid >> 5;
    const int i0 = blockIdx.x * 128;
    const int bh = blockIdx.y;
    const int b = bh >> 3, h = bh & 7;
    const int wr = wid * 16;

    auto ld_Q = [&]() {
#pragma unroll
        for (int it = 0; it < 4; it++) {
            int idx = tid + it * 256;
            int r = idx >> 3, seg = idx & 7;
            const __half* src = g_qTh + ((size_t)bh * HW + i0 + r) * DH + seg * 8;
            CP_ASYNC16(smem_u32(smem + r * QROWB + seg * 16), src);
        }
    };
    auto ld_KV = [&](int jt, int st) {
        char* sb = smem + FL_STAGE0 + st * FL_STAGEB;
        int j0 = jt * 128;
#pragma unroll
        for (int it = 0; it < 4; it++) {
            int idx = tid + it * 256;
            int r = idx >> 3, seg = idx & 7;
            const __half* src = g_kTh + ((size_t)bh * HW + j0 + r) * DH + seg * 8;
            CP_ASYNC16(smem_u32(sb + r * QROWB + seg * 16), src);
        }
#pragma unroll
        for (int it = 0; it < 4; it++) {
            int idx = tid + it * 256;
            int r = idx >> 4, seg = idx & 15;
            const __half* src = g_Vh + ((size_t)bh * DH + r) * HW + j0 + seg * 8;
            CP_ASYNC16(smem_u32(sb + FL_QTILE + r * VROWB + seg * 16), src);
        }
    };

    float acc_o[8][4];
#pragma unroll
    for (int dt = 0; dt < 8; dt++)
#pragma unroll
        for (int j = 0; j < 4; j++) acc_o[dt][j] = 0.f;
    float mrow0 = -INFINITY, mrow1 = -INFINITY;
    float lrow0 = 0.f, lrow1 = 0.f;

    const uint32_t qH = smem_u32(smem);

    ld_Q(); ld_KV(0, 0); CP_COMMIT();
    ld_KV(1, 1); CP_COMMIT();
    CP_WAIT1();
    __syncthreads();

#pragma unroll 1
    for (int jt = 0; jt < 8; jt++) {
        uint32_t kb = smem_u32(smem + FL_STAGE0 + (jt & 1) * FL_STAGEB);
        uint32_t kH = kb;
        uint32_t vH = kb + FL_QTILE;

        float s[16][4];
#pragma unroll
        for (int nt = 0; nt < 16; nt++)
#pragma unroll
            for (int j = 0; j < 4; j++) s[nt][j] = 0.f;

#pragma unroll
        for (int ks = 0; ks < 4; ks++) {
            uint32_t ah[4];
            uint32_t aoff = (uint32_t)((wr + (lane & 15)) * QROWB +
                                       (ks * 16 + (lane >> 4) * 8) * 2);
            LDSM_X4(ah, qH + aoff);
            int krow_l = ((lane >> 4) << 3) + (lane & 7);
            int kcol = ks * 16 + ((lane >> 3) & 1) * 8;
#pragma unroll
            for (int ntp = 0; ntp < 8; ntp++) {
                uint32_t bh_[4];
                uint32_t boff = (uint32_t)((ntp * 16 + krow_l) * QROWB + kcol * 2);
                LDSM_X4(bh_, kH + boff);
                mma_f16(s[2 * ntp],     ah, bh_);
                mma_f16(s[2 * ntp + 1], ah, bh_ + 2);
            }
        }

        float mx0 = -INFINITY, mx1 = -INFINITY;
#pragma unroll
        for (int nt = 0; nt < 16; nt++) {
            mx0 = fmaxf(mx0, fmaxf(s[nt][0], s[nt][1]));
            mx1 = fmaxf(mx1, fmaxf(s[nt][2], s[nt][3]));
        }
        mx0 = fmaxf(mx0, __shfl_xor_sync(0xffffffffu, mx0, 1));
        mx0 = fmaxf(mx0, __shfl_xor_sync(0xffffffffu, mx0, 2));
        mx1 = fmaxf(mx1, __shfl_xor_sync(0xffffffffu, mx1, 1));
        mx1 = fmaxf(mx1, __shfl_xor_sync(0xffffffffu, mx1, 2));
        float mn0 = fmaxf(mrow0, mx0), mn1 = fmaxf(mrow1, mx1);
        float al0 = __expf(mrow0 - mn0), al1 = __expf(mrow1 - mn1);
        mrow0 = mn0; mrow1 = mn1;
        lrow0 *= al0; lrow1 *= al1;
#pragma unroll
        for (int dt = 0; dt < 8; dt++) {
            acc_o[dt][0] *= al0; acc_o[dt][1] *= al0;
            acc_o[dt][2] *= al1; acc_o[dt][3] *= al1;
        }
        float ps0 = 0.f, ps1 = 0.f;
#pragma unroll
        for (int nt = 0; nt < 16; nt++) {
            s[nt][0] = __expf(s[nt][0] - mn0);
            s[nt][1] = __expf(s[nt][1] - mn0);
            s[nt][2] = __expf(s[nt][2] - mn1);
            s[nt][3] = __expf(s[nt][3] - mn1);
            ps0 += s[nt][0] + s[nt][1];
            ps1 += s[nt][2] + s[nt][3];
        }
        lrow0 += ps0; lrow1 += ps1;

        // ---- O += P V^T ----
#pragma unroll
        for (int kk = 0; kk < 8; kk++) {
            uint32_t aph[4];
            aph[0] = packh(s[2 * kk][0],     s[2 * kk][1]);
            aph[1] = packh(s[2 * kk][2],     s[2 * kk][3]);
            aph[2] = packh(s[2 * kk + 1][0], s[2 * kk + 1][1]);
            aph[3] = packh(s[2 * kk + 1][2], s[2 * kk + 1][3]);
            int vrow_l = ((lane >> 4) << 3) + (lane & 7);
            int vcol = kk * 16 + ((lane >> 3) & 1) * 8;
#pragma unroll
            for (int dt = 0; dt < 4; dt++) {
                uint32_t bvh[4];
                uint32_t off = (uint32_t)((dt * 16 + vrow_l) * VROWB + vcol * 2);
                LDSM_X4(bvh, vH + off);
                mma_f16(acc_o[2 * dt],     aph, bvh);
                mma_f16(acc_o[2 * dt + 1], aph, bvh + 2);
            }
        }

        __syncthreads();
        if (jt + 2 < 8)      { ld_KV(jt + 2, jt & 1); CP_COMMIT(); CP_WAIT1(); }
        else if (jt + 1 < 8) { CP_WAIT0(); }
        __syncthreads();
    }

    lrow0 += __shfl_xor_sync(0xffffffffu, lrow0, 1);
    lrow0 += __shfl_xor_sync(0xffffffffu, lrow0, 2);
    lrow1 += __shfl_xor_sync(0xffffffffu, lrow1, 1);
    lrow1 += __shfl_xor_sync(0xffffffffu, lrow1, 2);
    float inv0 = 1.f / lrow0, inv1 = 1.f / lrow1;

    int r0 = i0 + wr + (lane >> 2);
    int cbase = h * DH + (lane & 3) * 2;
#pragma unroll
    for (int dt = 0; dt < 8; dt++) {
        size_t o0 = ((size_t)b * HW + r0) * C + cbase + dt * 8;
        *(uint32_t*)&g_AOTh[o0] = packh(acc_o[dt][0] * inv0, acc_o[dt][1] * inv0);
        size_t o1 = ((size_t)b * HW + r0 + 8) * C + cbase + dt * 8;
        *(uint32_t*)&g_AOTh[o1] = packh(acc_o[dt][2] * inv1, acc_o[dt][3] * inv1);
    }
}

// =================== proj GEMM (+bias +residual) ==============================
__global__ __launch_bounds__(256) void proj_gemm(const float* __restrict__ bias,
                                                 const float* __restrict__ resid,
                                                 float* __restrict__ out) {
    constexpr int BM = 128, BN = 128;
    constexpr int TILE = BM * ROWB;
    constexpr int STAGE = 2 * TILE;
    extern __shared__ char smem[];

    const int tid = threadIdx.x;
    const int lane = tid & 31, wid = tid >> 5;
    const int wm = wid & 1, wn = wid >> 1;
    const int n0 = blockIdx.x * BN, m0 = blockIdx.y * BM;
    const int z = blockIdx.z;

    const __half* pA = g_WhP + (size_t)m0 * C;
    const __half* pB = g_AOTh + ((size_t)z * HW + n0) * C;

    auto load_chunk = [&](int stage, int k0) {
        char* sb = smem + stage * STAGE;
#pragma unroll
        for (int it = 0; it < 4; it++) {
            int idx = tid + it * 256;
            int row = idx >> 2, seg = idx & 3;
            const __half* src; int toff; int r;
            if (row < BM) { src = pA; toff = 0;    r = row; }
            else          { src = pB; toff = TILE; r = row - BM; }
            CP_ASYNC16(smem_u32(sb + toff + r * ROWB + seg * 16),
                       src + (size_t)r * C + k0 + seg * 8);
        }
        CP_COMMIT();
    };

    float acc[4][4][4];
#pragma unroll
    for (int mi = 0; mi < 4; mi++)
#pragma unroll
        for (int ni = 0; ni < 4; ni++)
#pragma unroll
            for (int j = 0; j < 4; j++) acc[mi][ni][j] = 0.f;

    load_chunk(0, 0);
#pragma unroll 1
    for (int c = 0; c < 16; c++) {
        if (c + 1 < 16) { load_chunk((c + 1) & 1, (c + 1) * KC); CP_WAIT1(); }
        else            { CP_WAIT0(); }
        __syncthreads();
        char* sb = smem + (c & 1) * STAGE;
        uint32_t aH = smem_u32(sb);
        uint32_t bH = aH + TILE;
#pragma unroll
        for (int ks = 0; ks < 2; ks++) {
            uint32_t ah[4][4], bh[4][2];
            int acol = ks * 16 + (lane >> 4) * 8;
#pragma unroll
            for (int mi = 0; mi < 4; mi++) {
                uint32_t off = (uint32_t)((wm * 64 + mi * 16 + (lane & 15)) * ROWB + acol * 2);
                LDSM_X4(ah[mi], aH + off);
            }
            int l = lane & 15;
            int bcol = ks * 16 + (l >> 3) * 8;
#pragma unroll
            for (int ni = 0; ni < 4; ni++) {
                uint32_t off = (uint32_t)((wn * 32 + ni * 8 + (l & 7)) * ROWB + bcol * 2);
                LDSM_X2(bh[ni], bH + off);
            }
#pragma unroll
            for (int mi = 0; mi < 4; mi++)
#pragma unroll
                for (int ni = 0; ni < 4; ni++)
                    mma_f16(acc[mi][ni], ah[mi], bh[ni]);
        }
        __syncthreads();
    }

    float* po = out + (size_t)z * C * HW;
#pragma unroll
    for (int mi = 0; mi < 4; mi++)
#pragma unroll
        for (int ni = 0; ni < 4; ni++) {
            int col = n0 + wn * 32 + ni * 8 + (lane & 3) * 2;
#pragma unroll
            for (int hrow = 0; hrow < 2; hrow++) {
                int r = m0 + wm * 64 + mi * 16 + (lane >> 2) + hrow * 8;
                float bm = bias[r];
                size_t off = (size_t)r * HW + col;
                float2 rx = *(const float2*)&resid[(size_t)z * C * HW + off];
                float2 v;
                v.x = acc[mi][ni][hrow * 2 + 0] + bm + rx.x;
                v.y = acc[mi][ni][hrow * 2 + 1] + bm + rx.y;
                *(float2*)&po[off] = v;
            }
        }
}

// =================== launch ===================================================
extern "C" void kernel_launch(void* const* d_in, const int* in_sizes, int n_in,
                              void* d_out, int out_size) {
    const float* x      = (const float*)d_in[0];
    const float* gn_w   = (const float*)d_in[1];
    const float* gn_b   = (const float*)d_in[2];
    const float* qkv_w  = (const float*)d_in[3];
    const float* qkv_b  = (const float*)d_in[4];
    const float* proj_w = (const float*)d_in[5];
    const float* proj_b = (const float*)d_in[6];
    float* out = (float*)d_out;

    static bool init = false;
    if (!init) {
        cudaFuncSetAttribute(qkv_gemm, cudaFuncAttributeMaxDynamicSharedMemorySize, SMQKV);
        cudaFuncSetAttribute(proj_gemm, cudaFuncAttributeMaxDynamicSharedMemorySize, SMPROJ);
        cudaFuncSetAttribute(flash_kernel, cudaFuncAttributeMaxDynamicSharedMemorySize, FL_SMEM);
        init = true;
    }

    gn_stats_kernel<<<B * G, 256>>>(x);
    convW_kernel<0><<<(3 * C * C + 255) / 256, 256>>>(qkv_w, 3 * C * C);
    convW_kernel<1><<<(C * C + 255) / 256, 256>>>(proj_w, C * C);
    convT_kernel<<<dim3(HW / 32, C / 32, B), dim3(32, 8)>>>(x, gn_w, gn_b);

    qkv_gemm<<<dim3(HW / 128, 3 * C / 128, B), 256, SMQKV>>>(qkv_b);

    flash_kernel<<<dim3(HW / 128, B * HEADS), 256, FL_SMEM>>>();

    proj_gemm<<<dim3(HW / 128, C / 128, B), 256, SMPROJ>>>(proj_b, x, out);
}

// round 8
// speedup vs baseline: 6.0439x; 1.0636x over previous
#include <cuda_runtime.h>
#include <cuda_fp16.h>
#include <cstdint>
#include <math.h>

#define B    8
#define C    512
#define HW   1024
#define G    32
#define CPG  16
#define HEADS 8
#define DH   64
#define EPS  1e-5f
#define QSCALE 0.1803368867f   // 0.125 * log2(e)

// ---------------- scratch (device globals) ----------------------------------
__device__ float2 g_stats[B * G];

__device__ __half g_WhQ[3 * C * C];
__device__ __half g_WhP[C * C];
__device__ __half g_XTh [B * HW * C];          // [b][n][c]
__device__ __half g_AOTh[B * HW * C];          // [b][i][c]
__device__ __half g_qTh [B * HEADS * HW * DH]; // [bh][i][d] (log2-scaled)
__device__ __half g_kTh [B * HEADS * HW * DH]; // [bh][j][d]
__device__ __half g_Vh  [B * HEADS * DH * HW]; // [bh][d][j]

// =================== helpers ==================================================
__device__ __forceinline__ uint32_t smem_u32(const void* p) {
    uint32_t r;
    asm("{ .reg .u64 t; cvta.to.shared.u64 t, %1; cvt.u32.u64 %0, t; }"
        : "=r"(r) : "l"(p));
    return r;
}
#define CP_ASYNC16(dst, src) \
    asm volatile("cp.async.cg.shared.global [%0], [%1], 16;" :: "r"(dst), "l"(src) : "memory")
#define CP_COMMIT() asm volatile("cp.async.commit_group;" ::: "memory")
#define CP_WAIT1()  asm volatile("cp.async.wait_group 1;" ::: "memory")
#define CP_WAIT0()  asm volatile("cp.async.wait_group 0;" ::: "memory")

#define LDSM_X4(r, addr) \
    asm volatile("ldmatrix.sync.aligned.m8n8.x4.shared.b16 {%0,%1,%2,%3}, [%4];" \
        : "=r"((r)[0]), "=r"((r)[1]), "=r"((r)[2]), "=r"((r)[3]) : "r"(addr))
#define LDSM_X2(r, addr) \
    asm volatile("ldmatrix.sync.aligned.m8n8.x2.shared.b16 {%0,%1}, [%2];" \
        : "=r"((r)[0]), "=r"((r)[1]) : "r"(addr))

__device__ __forceinline__ void mma_f16(float* c, const uint32_t* a, const uint32_t* b) {
    asm volatile(
        "mma.sync.aligned.m16n8k16.row.col.f32.f16.f16.f32 "
        "{%0,%1,%2,%3}, {%4,%5,%6,%7}, {%8,%9}, {%0,%1,%2,%3};"
        : "+f"(c[0]), "+f"(c[1]), "+f"(c[2]), "+f"(c[3])
        : "r"(a[0]), "r"(a[1]), "r"(a[2]), "r"(a[3]), "r"(b[0]), "r"(b[1]));
}
__device__ __forceinline__ uint32_t packh(float x, float y) {
    __half2 h = __floats2half2_rn(x, y);
    return *(uint32_t*)&h;
}
__device__ __forceinline__ float ex2f(float x) {
    float y;
    asm("ex2.approx.f32 %0, %1;" : "=f"(y) : "f"(x));
    return y;
}

// =========== fused prologue: gn stats + both weight converts ==================
// blocks [0,256): gn stats; [256,1024): convW qkv (f4); [1024,1280): convW proj
__global__ __launch_bounds__(256) void prep_kernel(const float* __restrict__ x,
                                                   const float* __restrict__ qkv_w,
                                                   const float* __restrict__ proj_w) {
    int blk = blockIdx.x;
    if (blk < 256) {
        const float4* xp = (const float4*)(x + (size_t)blk * CPG * HW);
        const int N4 = CPG * HW / 4;
        float s = 0.f, s2 = 0.f;
        for (int i = threadIdx.x; i < N4; i += 256) {
            float4 v = xp[i];
            s  += v.x + v.y + v.z + v.w;
            s2 += v.x * v.x + v.y * v.y + v.z * v.z + v.w * v.w;
        }
        __shared__ float sh1[8], sh2[8];
        int lane = threadIdx.x & 31, wid = threadIdx.x >> 5;
        for (int o = 16; o; o >>= 1) {
            s  += __shfl_down_sync(0xffffffffu, s,  o);
            s2 += __shfl_down_sync(0xffffffffu, s2, o);
        }
        if (lane == 0) { sh1[wid] = s; sh2[wid] = s2; }
        __syncthreads();
        if (threadIdx.x == 0) {
            for (int i = 1; i < 8; i++) { sh1[0] += sh1[i]; sh2[0] += sh2[i]; }
            const float N = CPG * HW;
            float mean = sh1[0] * (1.f / N);
            float var  = sh2[0] * (1.f / N) - mean * mean;
            g_stats[blk] = make_float2(mean, rsqrtf(var + EPS));
        }
    } else if (blk < 1024) {
        int i = (blk - 256) * 1024 + threadIdx.x * 4;   // over 3*C*C = 786432
        float4 v = *(const float4*)&qkv_w[i];
        *(uint32_t*)&g_WhQ[i]     = packh(v.x, v.y);
        *(uint32_t*)&g_WhQ[i + 2] = packh(v.z, v.w);
    } else {
        int i = (blk - 1024) * 1024 + threadIdx.x * 4;  // over C*C = 262144
        float4 v = *(const float4*)&proj_w[i];
        *(uint32_t*)&g_WhP[i]     = packh(v.x, v.y);
        *(uint32_t*)&g_WhP[i + 2] = packh(v.z, v.w);
    }
}

// ===== fused GN-apply + transpose + convert: x [b][c][n] -> XT [b][n][c] ======
__global__ __launch_bounds__(256) void convT_kernel(const float* __restrict__ x,
                                                    const float* __restrict__ gw,
                                                    const float* __restrict__ gb) {
    __shared__ float t[32][33];
    int n0 = blockIdx.x * 32, c0 = blockIdx.y * 32, b = blockIdx.z;
    const float* ip = x + (size_t)b * C * HW;
    int tx = threadIdx.x, ty = threadIdx.y;  // (32,8)
#pragma unroll
    for (int k = 0; k < 4; k++) {
        int ch = c0 + ty + k * 8;
        float2 st = g_stats[b * G + (ch >> 4)];
        float v = ip[(size_t)ch * HW + n0 + tx];
        t[ty + k * 8][tx] = (v - st.x) * st.y * gw[ch] + gb[ch];
    }
    __syncthreads();
#pragma unroll
    for (int k = 0; k < 4; k++) {
        int ni = ty + k * 8;
        size_t o = (size_t)b * HW * C + (size_t)(n0 + ni) * C + c0 + tx;
        g_XTh[o] = __float2half(t[tx][ni]);
    }
}

// =================== dense GEMM config ========================================
#define KC    64
#define ROWB  144                      // 64 halves + 8 pad
#define DTILE (128 * ROWB)             // 18432
#define DSTG  (2 * DTILE)              // 36864 per stage (A + B)
#define SMQKV (3 * DSTG)               // 110592 (epilogue 67584 fits inside)
#define SMPROJ (3 * DSTG)

// =================== QKV GEMM (pure fp16, 3-stage pipeline) ===================
__global__ __launch_bounds__(256) void qkv_gemm(const float* __restrict__ bias) {
    constexpr int BM = 128, BN = 128;
    extern __shared__ char smem[];

    const int tid = threadIdx.x;
    const int lane = tid & 31, wid = tid >> 5;
    const int wm = wid & 1, wn = wid >> 1;
    const int n0 = blockIdx.x * BN, m0 = blockIdx.y * BM;
    const int z = blockIdx.z;

    const __half* pA = g_WhQ + (size_t)m0 * C;
    const __half* pB = g_XTh + ((size_t)z * HW + n0) * C;

    auto load_chunk = [&](int stage, int k0) {
        char* sb = smem + stage * DSTG;
#pragma unroll
        for (int it = 0; it < 8; it++) {
            int idx = tid + it * 256;
            int row = idx >> 3, seg = idx & 7;
            const __half* src; int toff; int r;
            if (row < BM) { src = pA; toff = 0;     r = row; }
            else          { src = pB; toff = DTILE; r = row - BM; }
            CP_ASYNC16(smem_u32(sb + toff + r * ROWB + seg * 16),
                       src + (size_t)r * C + k0 + seg * 8);
        }
        CP_COMMIT();
    };

    float acc[4][4][4];
#pragma unroll
    for (int mi = 0; mi < 4; mi++)
#pragma unroll
        for (int ni = 0; ni < 4; ni++)
#pragma unroll
            for (int j = 0; j < 4; j++) acc[mi][ni][j] = 0.f;

    const int NCH = C / KC;   // 8
    load_chunk(0, 0);
    load_chunk(1, KC);
#pragma unroll 1
    for (int c = 0; c < NCH; c++) {
        if (c + 1 < NCH) CP_WAIT1(); else CP_WAIT0();
        __syncthreads();
        if (c + 2 < NCH) load_chunk((c + 2) % 3, (c + 2) * KC);
        char* sb = smem + (c % 3) * DSTG;
        uint32_t aH = smem_u32(sb);
        uint32_t bH = aH + DTILE;
#pragma unroll
        for (int ks = 0; ks < 4; ks++) {
            uint32_t ah[4][4], bh[4][2];
            int acol = ks * 16 + (lane >> 4) * 8;
#pragma unroll
            for (int mi = 0; mi < 4; mi++) {
                uint32_t off = (uint32_t)((wm * 64 + mi * 16 + (lane & 15)) * ROWB + acol * 2);
                LDSM_X4(ah[mi], aH + off);
            }
            int l = lane & 15;
            int bcol = ks * 16 + (l >> 3) * 8;
#pragma unroll
            for (int ni = 0; ni < 4; ni++) {
                uint32_t off = (uint32_t)((wn * 32 + ni * 8 + (l & 7)) * ROWB + bcol * 2);
                LDSM_X2(bh[ni], bH + off);
            }
#pragma unroll
            for (int mi = 0; mi < 4; mi++)
#pragma unroll
                for (int ni = 0; ni < 4; ni++)
                    mma_f16(acc[mi][ni], ah[mi], bh[ni]);
        }
    }

    const int sec = m0 >> 9;          // 0=q, 1=k, 2=v
    const float scale = (sec == 0) ? QSCALE : 1.0f;

    __syncthreads();
    if (sec == 2) {
#pragma unroll
        for (int mi = 0; mi < 4; mi++)
#pragma unroll
            for (int ni = 0; ni < 4; ni++) {
                int col = wn * 32 + ni * 8 + (lane & 3) * 2;
#pragma unroll
                for (int hrow = 0; hrow < 2; hrow++) {
                    int r = wm * 64 + mi * 16 + (lane >> 2) + hrow * 8;
                    int mC = (m0 - 1024) + r;
                    float bm = bias[m0 + r];
                    size_t o = ((size_t)(z * HEADS + (mC >> 6)) * DH + (mC & 63)) * HW + n0 + col;
                    *(uint32_t*)&g_Vh[o] = packh(acc[mi][ni][hrow * 2 + 0] + bm,
                                                 acc[mi][ni][hrow * 2 + 1] + bm);
                }
            }
    } else {
        float* ts = (float*)smem;
#pragma unroll
        for (int mi = 0; mi < 4; mi++)
#pragma unroll
            for (int ni = 0; ni < 4; ni++) {
                int col = wn * 32 + ni * 8 + (lane & 3) * 2;
#pragma unroll
                for (int hrow = 0; hrow < 2; hrow++) {
                    int r = wm * 64 + mi * 16 + (lane >> 2) + hrow * 8;
                    float bm = bias[m0 + r];
                    ts[r * 132 + col]     = (acc[mi][ni][hrow * 2 + 0] + bm) * scale;
                    ts[r * 132 + col + 1] = (acc[mi][ni][hrow * 2 + 1] + bm) * scale;
                }
            }
        __syncthreads();
        __half* oh = sec ? g_kTh : g_qTh;
        int h0 = (m0 & 511) >> 6;
#pragma unroll
        for (int it = 0; it < 32; it++) {
            int e = tid + it * 256;
            int i = e & 127;
            int rest = e >> 7;
            int hh = rest & 1, dp = rest >> 1;
            float a  = ts[(hh * 64 + dp * 2)     * 132 + i];
            float bb = ts[(hh * 64 + dp * 2 + 1) * 132 + i];
            size_t o = ((size_t)(z * HEADS + h0 + hh) * HW + n0 + i) * DH + dp * 2;
            *(uint32_t*)&oh[o] = packh(a, bb);
        }
    }
}

// =================== flash attention (pure fp16, exp2 domain) =================
#define QROWB   144
#define VROWB   272
#define FL_QTILE 18432
#define FL_VTILE 17408
#define FL_STAGE0 FL_QTILE
#define FL_STAGEB (FL_QTILE + FL_VTILE)
#define FL_SMEM   (FL_STAGE0 + 2 * FL_STAGEB) // 90112

__global__ __launch_bounds__(256, 1) void flash_kernel() {
    extern __shared__ char smem[];
    const int tid = threadIdx.x, lane = tid & 31, wid = tid >> 5;
    const int i0 = blockIdx.x * 128;
    const int bh = blockIdx.y;
    const int b = bh >> 3, h = bh & 7;
    const int wr = wid * 16;

    auto ld_Q = [&]() {
#pragma unroll
        for (int it = 0; it < 4; it++) {
            int idx = tid + it * 256;
            int r = idx >> 3, seg = idx & 7;
            const __half* src = g_qTh + ((size_t)bh * HW + i0 + r) * DH + seg * 8;
            CP_ASYNC16(smem_u32(smem + r * QROWB + seg * 16), src);
        }
    };
    auto ld_KV = [&](int jt, int st) {
        char* sb = smem + FL_STAGE0 + st * FL_STAGEB;
        int j0 = jt * 128;
#pragma unroll
        for (int it = 0; it < 4; it++) {
            int idx = tid + it * 256;
            int r = idx >> 3, seg = idx & 7;
            const __half* src = g_kTh + ((size_t)bh * HW + j0 + r) * DH + seg * 8;
            CP_ASYNC16(smem_u32(sb + r * QROWB + seg * 16), src);
        }
#pragma unroll
        for (int it = 0; it < 4; it++) {
            int idx = tid + it * 256;
            int r = idx >> 4, seg = idx & 15;
            const __half* src = g_Vh + ((size_t)bh * DH + r) * HW + j0 + seg * 8;
            CP_ASYNC16(smem_u32(sb + FL_QTILE + r * VROWB + seg * 16), src);
        }
    };

    float acc_o[8][4];
#pragma unroll
    for (int dt = 0; dt < 8; dt++)
#pragma unroll
        for (int j = 0; j < 4; j++) acc_o[dt][j] = 0.f;
    float mrow0 = -INFINITY, mrow1 = -INFINITY;
    float lrow0 = 0.f, lrow1 = 0.f;

    const uint32_t qH = smem_u32(smem);

    ld_Q(); ld_KV(0, 0); CP_COMMIT();
    ld_KV(1, 1); CP_COMMIT();
    CP_WAIT1();
    __syncthreads();

#pragma unroll 1
    for (int jt = 0; jt < 8; jt++) {
        uint32_t kb = smem_u32(smem + FL_STAGE0 + (jt & 1) * FL_STAGEB);
        uint32_t kH = kb;
        uint32_t vH = kb + FL_QTILE;

        float s[16][4];
#pragma unroll
        for (int nt = 0; nt < 16; nt++)
#pragma unroll
            for (int j = 0; j < 4; j++) s[nt][j] = 0.f;

#pragma unroll
        for (int ks = 0; ks < 4; ks++) {
            uint32_t ah[4];
            uint32_t aoff = (uint32_t)((wr + (lane & 15)) * QROWB +
                                       (ks * 16 + (lane >> 4) * 8) * 2);
            LDSM_X4(ah, qH + aoff);
            int krow_l = ((lane >> 4) << 3) + (lane & 7);
            int kcol = ks * 16 + ((lane >> 3) & 1) * 8;
#pragma unroll
            for (int ntp = 0; ntp < 8; ntp++) {
                uint32_t bh_[4];
                uint32_t boff = (uint32_t)((ntp * 16 + krow_l) * QROWB + kcol * 2);
                LDSM_X4(bh_, kH + boff);
                mma_f16(s[2 * ntp],     ah, bh_);
                mma_f16(s[2 * ntp + 1], ah, bh_ + 2);
            }
        }

        // online softmax in log2 domain (q pre-scaled by 0.125*log2e)
        float mx0 = -INFINITY, mx1 = -INFINITY;
#pragma unroll
        for (int nt = 0; nt < 16; nt++) {
            mx0 = fmaxf(mx0, fmaxf(s[nt][0], s[nt][1]));
            mx1 = fmaxf(mx1, fmaxf(s[nt][2], s[nt][3]));
        }
        mx0 = fmaxf(mx0, __shfl_xor_sync(0xffffffffu, mx0, 1));
        mx0 = fmaxf(mx0, __shfl_xor_sync(0xffffffffu, mx0, 2));
        mx1 = fmaxf(mx1, __shfl_xor_sync(0xffffffffu, mx1, 1));
        mx1 = fmaxf(mx1, __shfl_xor_sync(0xffffffffu, mx1, 2));
        float mn0 = fmaxf(mrow0, mx0), mn1 = fmaxf(mrow1, mx1);
        float al0 = ex2f(mrow0 - mn0), al1 = ex2f(mrow1 - mn1);
        mrow0 = mn0; mrow1 = mn1;
        lrow0 *= al0; lrow1 *= al1;
#pragma unroll
        for (int dt = 0; dt < 8; dt++) {
            acc_o[dt][0] *= al0; acc_o[dt][1] *= al0;
            acc_o[dt][2] *= al1; acc_o[dt][3] *= al1;
        }
        float ps0 = 0.f, ps1 = 0.f;
#pragma unroll
        for (int nt = 0; nt < 16; nt++) {
            s[nt][0] = ex2f(s[nt][0] - mn0);
            s[nt][1] = ex2f(s[nt][1] - mn0);
            s[nt][2] = ex2f(s[nt][2] - mn1);
            s[nt][3] = ex2f(s[nt][3] - mn1);
            ps0 += s[nt][0] + s[nt][1];
            ps1 += s[nt][2] + s[nt][3];
        }
        lrow0 += ps0; lrow1 += ps1;

        // ---- O += P V^T ----
#pragma unroll
        for (int kk = 0; kk < 8; kk++) {
            uint32_t aph[4];
            aph[0] = packh(s[2 * kk][0],     s[2 * kk][1]);
            aph[1] = packh(s[2 * kk][2],     s[2 * kk][3]);
            aph[2] = packh(s[2 * kk + 1][0], s[2 * kk + 1][1]);
            aph[3] = packh(s[2 * kk + 1][2], s[2 * kk + 1][3]);
            int vrow_l = ((lane >> 4) << 3) + (lane & 7);
            int vcol = kk * 16 + ((lane >> 3) & 1) * 8;
#pragma unroll
            for (int dt = 0; dt < 4; dt++) {
                uint32_t bvh[4];
                uint32_t off = (uint32_t)((dt * 16 + vrow_l) * VROWB + vcol * 2);
                LDSM_X4(bvh, vH + off);
                mma_f16(acc_o[2 * dt],     aph, bvh);
                mma_f16(acc_o[2 * dt + 1], aph, bvh + 2);
            }
        }

        __syncthreads();
        if (jt + 2 < 8)      { ld_KV(jt + 2, jt & 1); CP_COMMIT(); CP_WAIT1(); }
        else if (jt + 1 < 8) { CP_WAIT0(); }
        __syncthreads();
    }

    lrow0 += __shfl_xor_sync(0xffffffffu, lrow0, 1);
    lrow0 += __shfl_xor_sync(0xffffffffu, lrow0, 2);
    lrow1 += __shfl_xor_sync(0xffffffffu, lrow1, 1);
    lrow1 += __shfl_xor_sync(0xffffffffu, lrow1, 2);
    float inv0 = 1.f / lrow0, inv1 = 1.f / lrow1;

    int r0 = i0 + wr + (lane >> 2);
    int cbase = h * DH + (lane & 3) * 2;
#pragma unroll
    for (int dt = 0; dt < 8; dt++) {
        size_t o0 = ((size_t)b * HW + r0) * C + cbase + dt * 8;
        *(uint32_t*)&g_AOTh[o0] = packh(acc_o[dt][0] * inv0, acc_o[dt][1] * inv0);
        size_t o1 = ((size_t)b * HW + r0 + 8) * C + cbase + dt * 8;
        *(uint32_t*)&g_AOTh[o1] = packh(acc_o[dt][2] * inv1, acc_o[dt][3] * inv1);
    }
}

// =================== proj GEMM (3-stage, +bias +residual) =====================
__global__ __launch_bounds__(256) void proj_gemm(const float* __restrict__ bias,
                                                 const float* __restrict__ resid,
                                                 float* __restrict__ out) {
    constexpr int BM = 128, BN = 128;
    extern __shared__ char smem[];

    const int tid = threadIdx.x;
    const int lane = tid & 31, wid = tid >> 5;
    const int wm = wid & 1, wn = wid >> 1;
    const int n0 = blockIdx.x * BN, m0 = blockIdx.y * BM;
    const int z = blockIdx.z;

    const __half* pA = g_WhP + (size_t)m0 * C;
    const __half* pB = g_AOTh + ((size_t)z * HW + n0) * C;

    auto load_chunk = [&](int stage, int k0) {
        char* sb = smem + stage * DSTG;
#pragma unroll
        for (int it = 0; it < 8; it++) {
            int idx = tid + it * 256;
            int row = idx >> 3, seg = idx & 7;
            const __half* src; int toff; int r;
            if (row < BM) { src = pA; toff = 0;     r = row; }
            else          { src = pB; toff = DTILE; r = row - BM; }
            CP_ASYNC16(smem_u32(sb + toff + r * ROWB + seg * 16),
                       src + (size_t)r * C + k0 + seg * 8);
        }
        CP_COMMIT();
    };

    float acc[4][4][4];
#pragma unroll
    for (int mi = 0; mi < 4; mi++)
#pragma unroll
        for (int ni = 0; ni < 4; ni++)
#pragma unroll
            for (int j = 0; j < 4; j++) acc[mi][ni][j] = 0.f;

    const int NCH = C / KC;
    load_chunk(0, 0);
    load_chunk(1, KC);
#pragma unroll 1
    for (int c = 0; c < NCH; c++) {
        if (c + 1 < NCH) CP_WAIT1(); else CP_WAIT0();
        __syncthreads();
        if (c + 2 < NCH) load_chunk((c + 2) % 3, (c + 2) * KC);
        char* sb = smem + (c % 3) * DSTG;
        uint32_t aH = smem_u32(sb);
        uint32_t bH = aH + DTILE;
#pragma unroll
        for (int ks = 0; ks < 4; ks++) {
            uint32_t ah[4][4], bh[4][2];
            int acol = ks * 16 + (lane >> 4) * 8;
#pragma unroll
            for (int mi = 0; mi < 4; mi++) {
                uint32_t off = (uint32_t)((wm * 64 + mi * 16 + (lane & 15)) * ROWB + acol * 2);
                LDSM_X4(ah[mi], aH + off);
            }
            int l = lane & 15;
            int bcol = ks * 16 + (l >> 3) * 8;
#pragma unroll
            for (int ni = 0; ni < 4; ni++) {
                uint32_t off = (uint32_t)((wn * 32 + ni * 8 + (l & 7)) * ROWB + bcol * 2);
                LDSM_X2(bh[ni], bH + off);
            }
#pragma unroll
            for (int mi = 0; mi < 4; mi++)
#pragma unroll
                for (int ni = 0; ni < 4; ni++)
                    mma_f16(acc[mi][ni], ah[mi], bh[ni]);
        }
    }

    float* po = out + (size_t)z * C * HW;
#pragma unroll
    for (int mi = 0; mi < 4; mi++)
#pragma unroll
        for (int ni = 0; ni < 4; ni++) {
            int col = n0 + wn * 32 + ni * 8 + (lane & 3) * 2;
#pragma unroll
            for (int hrow = 0; hrow < 2; hrow++) {
                int r = m0 + wm * 64 + mi * 16 + (lane >> 2) + hrow * 8;
                float bm = bias[r];
                size_t off = (size_t)r * HW + col;
                float2 rx = *(const float2*)&resid[(size_t)z * C * HW + off];
                float2 v;
                v.x = acc[mi][ni][hrow * 2 + 0] + bm + rx.x;
                v.y = acc[mi][ni][hrow * 2 + 1] + bm + rx.y;
                *(float2*)&po[off] = v;
            }
        }
}

// =================== launch ===================================================
extern "C" void kernel_launch(void* const* d_in, const int* in_sizes, int n_in,
                              void* d_out, int out_size) {
    const float* x      = (const float*)d_in[0];
    const float* gn_w   = (const float*)d_in[1];
    const float* gn_b   = (const float*)d_in[2];
    const float* qkv_w  = (const float*)d_in[3];
    const float* qkv_b  = (const float*)d_in[4];
    const float* proj_w = (const float*)d_in[5];
    const float* proj_b = (const float*)d_in[6];
    float* out = (float*)d_out;

    static bool init = false;
    if (!init) {
        cudaFuncSetAttribute(qkv_gemm, cudaFuncAttributeMaxDynamicSharedMemorySize, SMQKV);
        cudaFuncSetAttribute(proj_gemm, cudaFuncAttributeMaxDynamicSharedMemorySize, SMPROJ);
        cudaFuncSetAttribute(flash_kernel, cudaFuncAttributeMaxDynamicSharedMemorySize, FL_SMEM);
        init = true;
    }

    prep_kernel<<<1280, 256>>>(x, qkv_w, proj_w);
    convT_kernel<<<dim3(HW / 32, C / 32, B), dim3(32, 8)>>>(x, gn_w, gn_b);

    qkv_gemm<<<dim3(HW / 128, 3 * C / 128, B), 256, SMQKV>>>(qkv_b);

    flash_kernel<<<dim3(HW / 128, B * HEADS), 256, FL_SMEM>>>();

    proj_gemm<<<dim3(HW / 128, C / 128, B), 256, SMPROJ>>>(proj_b, x, out);
}

// round 9
// speedup vs baseline: 6.1326x; 1.0147x over previous
#include <cuda_runtime.h>
#include <cuda_fp16.h>
#include <cstdint>
#include <math.h>

#define B    8
#define C    512
#define HW   1024
#define G    32
#define CPG  16
#define HEADS 8
#define DH   64
#define EPS  1e-5f
#define QSCALE 0.1803368867f   // 0.125 * log2(e)

// ---------------- scratch (device globals) ----------------------------------
__device__ float2 g_stats[B * G];

__device__ __half g_WhQ[3 * C * C];
__device__ __half g_WhP[C * C];
__device__ __half g_XTh [B * HW * C];          // [b][n][c]
__device__ __half g_AOTh[B * HW * C];          // [b][i][c]
__device__ __half g_qTh [B * HEADS * HW * DH]; // [bh][i][d] (log2-scaled)
__device__ __half g_kTh [B * HEADS * HW * DH]; // [bh][j][d]
__device__ __half g_Vh  [B * HEADS * DH * HW]; // [bh][d][j]

// =================== helpers ==================================================
__device__ __forceinline__ uint32_t smem_u32(const void* p) {
    uint32_t r;
    asm("{ .reg .u64 t; cvta.to.shared.u64 t, %1; cvt.u32.u64 %0, t; }"
        : "=r"(r) : "l"(p));
    return r;
}
#define CP_ASYNC16(dst, src) \
    asm volatile("cp.async.cg.shared.global [%0], [%1], 16;" :: "r"(dst), "l"(src) : "memory")
#define CP_COMMIT() asm volatile("cp.async.commit_group;" ::: "memory")
#define CP_WAIT2()  asm volatile("cp.async.wait_group 2;" ::: "memory")
#define CP_WAIT1()  asm volatile("cp.async.wait_group 1;" ::: "memory")
#define CP_WAIT0()  asm volatile("cp.async.wait_group 0;" ::: "memory")

#define LDSM_X4(r, addr) \
    asm volatile("ldmatrix.sync.aligned.m8n8.x4.shared.b16 {%0,%1,%2,%3}, [%4];" \
        : "=r"((r)[0]), "=r"((r)[1]), "=r"((r)[2]), "=r"((r)[3]) : "r"(addr))
#define LDSM_X2(r, addr) \
    asm volatile("ldmatrix.sync.aligned.m8n8.x2.shared.b16 {%0,%1}, [%2];" \
        : "=r"((r)[0]), "=r"((r)[1]) : "r"(addr))

__device__ __forceinline__ void mma_f16(float* c, const uint32_t* a, const uint32_t* b) {
    asm volatile(
        "mma.sync.aligned.m16n8k16.row.col.f32.f16.f16.f32 "
        "{%0,%1,%2,%3}, {%4,%5,%6,%7}, {%8,%9}, {%0,%1,%2,%3};"
        : "+f"(c[0]), "+f"(c[1]), "+f"(c[2]), "+f"(c[3])
        : "r"(a[0]), "r"(a[1]), "r"(a[2]), "r"(a[3]), "r"(b[0]), "r"(b[1]));
}
__device__ __forceinline__ uint32_t packh(float x, float y) {
    __half2 h = __floats2half2_rn(x, y);
    return *(uint32_t*)&h;
}
__device__ __forceinline__ float ex2f(float x) {
    float y;
    asm("ex2.approx.f32 %0, %1;" : "=f"(y) : "f"(x));
    return y;
}

// =========== fused prologue: gn stats + both weight converts ==================
__global__ __launch_bounds__(256) void prep_kernel(const float* __restrict__ x,
                                                   const float* __restrict__ qkv_w,
                                                   const float* __restrict__ proj_w) {
    int blk = blockIdx.x;
    if (blk < 256) {
        const float4* xp = (const float4*)(x + (size_t)blk * CPG * HW);
        const int N4 = CPG * HW / 4;
        float s = 0.f, s2 = 0.f;
        for (int i = threadIdx.x; i < N4; i += 256) {
            float4 v = xp[i];
            s  += v.x + v.y + v.z + v.w;
            s2 += v.x * v.x + v.y * v.y + v.z * v.z + v.w * v.w;
        }
        __shared__ float sh1[8], sh2[8];
        int lane = threadIdx.x & 31, wid = threadIdx.x >> 5;
        for (int o = 16; o; o >>= 1) {
            s  += __shfl_down_sync(0xffffffffu, s,  o);
            s2 += __shfl_down_sync(0xffffffffu, s2, o);
        }
        if (lane == 0) { sh1[wid] = s; sh2[wid] = s2; }
        __syncthreads();
        if (threadIdx.x == 0) {
            for (int i = 1; i < 8; i++) { sh1[0] += sh1[i]; sh2[0] += sh2[i]; }
            const float N = CPG * HW;
            float mean = sh1[0] * (1.f / N);
            float var  = sh2[0] * (1.f / N) - mean * mean;
            g_stats[blk] = make_float2(mean, rsqrtf(var + EPS));
        }
    } else if (blk < 1024) {
        int i = (blk - 256) * 1024 + threadIdx.x * 4;
        float4 v = *(const float4*)&qkv_w[i];
        *(uint32_t*)&g_WhQ[i]     = packh(v.x, v.y);
        *(uint32_t*)&g_WhQ[i + 2] = packh(v.z, v.w);
    } else {
        int i = (blk - 1024) * 1024 + threadIdx.x * 4;
        float4 v = *(const float4*)&proj_w[i];
        *(uint32_t*)&g_WhP[i]     = packh(v.x, v.y);
        *(uint32_t*)&g_WhP[i + 2] = packh(v.z, v.w);
    }
}

// ===== fused GN-apply + transpose + convert ===================================
__global__ __launch_bounds__(256) void convT_kernel(const float* __restrict__ x,
                                                    const float* __restrict__ gw,
                                                    const float* __restrict__ gb) {
    __shared__ float t[32][33];
    int n0 = blockIdx.x * 32, c0 = blockIdx.y * 32, b = blockIdx.z;
    const float* ip = x + (size_t)b * C * HW;
    int tx = threadIdx.x, ty = threadIdx.y;
#pragma unroll
    for (int k = 0; k < 4; k++) {
        int ch = c0 + ty + k * 8;
        float2 st = g_stats[b * G + (ch >> 4)];
        float v = ip[(size_t)ch * HW + n0 + tx];
        t[ty + k * 8][tx] = (v - st.x) * st.y * gw[ch] + gb[ch];
    }
    __syncthreads();
#pragma unroll
    for (int k = 0; k < 4; k++) {
        int ni = ty + k * 8;
        size_t o = (size_t)b * HW * C + (size_t)(n0 + ni) * C + c0 + tx;
        g_XTh[o] = __float2half(t[tx][ni]);
    }
}

// =================== dense GEMM config (4-stage, 2 CTA/SM) ====================
#define KC    32
#define ROWB  80                       // 32 halves + 8 pad
#define DTILE (128 * ROWB)             // 10240
#define DSTG  (2 * DTILE)              // 20480
#define SMQKV 81920                    // 4 stages (epilogue 67584 fits inside)
#define SMPROJ 81920

// =================== QKV GEMM =================================================
__global__ __launch_bounds__(256, 2) void qkv_gemm(const float* __restrict__ bias) {
    constexpr int BM = 128;
    extern __shared__ char smem[];

    const int tid = threadIdx.x;
    const int lane = tid & 31, wid = tid >> 5;
    const int wm = wid & 1, wn = wid >> 1;
    const int n0 = blockIdx.x * 128, m0 = blockIdx.y * 128;
    const int z = blockIdx.z;

    const __half* pA = g_WhQ + (size_t)m0 * C;
    const __half* pB = g_XTh + ((size_t)z * HW + n0) * C;

    auto load_chunk = [&](int stage, int k0) {
        char* sb = smem + stage * DSTG;
#pragma unroll
        for (int it = 0; it < 4; it++) {
            int idx = tid + it * 256;
            int row = idx >> 2, seg = idx & 3;
            const __half* src; int toff; int r;
            if (row < BM) { src = pA; toff = 0;     r = row; }
            else          { src = pB; toff = DTILE; r = row - BM; }
            CP_ASYNC16(smem_u32(sb + toff + r * ROWB + seg * 16),
                       src + (size_t)r * C + k0 + seg * 8);
        }
        CP_COMMIT();
    };

    float acc[4][4][4];
#pragma unroll
    for (int mi = 0; mi < 4; mi++)
#pragma unroll
        for (int ni = 0; ni < 4; ni++)
#pragma unroll
            for (int j = 0; j < 4; j++) acc[mi][ni][j] = 0.f;

    const int NCH = C / KC;   // 16
    load_chunk(0, 0);
    load_chunk(1, KC);
    load_chunk(2, 2 * KC);
#pragma unroll 1
    for (int c = 0; c < NCH; c++) {
        if (c <= NCH - 3)      CP_WAIT2();
        else if (c == NCH - 2) CP_WAIT1();
        else                   CP_WAIT0();
        __syncthreads();
        if (c + 3 < NCH) load_chunk((c + 3) & 3, (c + 3) * KC);
        char* sb = smem + (c & 3) * DSTG;
        uint32_t aH = smem_u32(sb);
        uint32_t bH = aH + DTILE;
#pragma unroll
        for (int ks = 0; ks < 2; ks++) {
            uint32_t ah[4][4], bh[4][2];
            int acol = ks * 16 + (lane >> 4) * 8;
#pragma unroll
            for (int mi = 0; mi < 4; mi++) {
                uint32_t off = (uint32_t)((wm * 64 + mi * 16 + (lane & 15)) * ROWB + acol * 2);
                LDSM_X4(ah[mi], aH + off);
            }
            int l = lane & 15;
            int bcol = ks * 16 + (l >> 3) * 8;
#pragma unroll
            for (int ni = 0; ni < 4; ni++) {
                uint32_t off = (uint32_t)((wn * 32 + ni * 8 + (l & 7)) * ROWB + bcol * 2);
                LDSM_X2(bh[ni], bH + off);
            }
#pragma unroll
            for (int mi = 0; mi < 4; mi++)
#pragma unroll
                for (int ni = 0; ni < 4; ni++)
                    mma_f16(acc[mi][ni], ah[mi], bh[ni]);
        }
    }

    const int sec = m0 >> 9;          // 0=q, 1=k, 2=v
    const float scale = (sec == 0) ? QSCALE : 1.0f;

    __syncthreads();
    if (sec == 2) {
#pragma unroll
        for (int mi = 0; mi < 4; mi++)
#pragma unroll
            for (int ni = 0; ni < 4; ni++) {
                int col = wn * 32 + ni * 8 + (lane & 3) * 2;
#pragma unroll
                for (int hrow = 0; hrow < 2; hrow++) {
                    int r = wm * 64 + mi * 16 + (lane >> 2) + hrow * 8;
                    int mC = (m0 - 1024) + r;
                    float bm = bias[m0 + r];
                    size_t o = ((size_t)(z * HEADS + (mC >> 6)) * DH + (mC & 63)) * HW + n0 + col;
                    *(uint32_t*)&g_Vh[o] = packh(acc[mi][ni][hrow * 2 + 0] + bm,
                                                 acc[mi][ni][hrow * 2 + 1] + bm);
                }
            }
    } else {
        float* ts = (float*)smem;
#pragma unroll
        for (int mi = 0; mi < 4; mi++)
#pragma unroll
            for (int ni = 0; ni < 4; ni++) {
                int col = wn * 32 + ni * 8 + (lane & 3) * 2;
#pragma unroll
                for (int hrow = 0; hrow < 2; hrow++) {
                    int r = wm * 64 + mi * 16 + (lane >> 2) + hrow * 8;
                    float bm = bias[m0 + r];
                    ts[r * 132 + col]     = (acc[mi][ni][hrow * 2 + 0] + bm) * scale;
                    ts[r * 132 + col + 1] = (acc[mi][ni][hrow * 2 + 1] + bm) * scale;
                }
            }
        __syncthreads();
        __half* oh = sec ? g_kTh : g_qTh;
        int h0 = (m0 & 511) >> 6;
#pragma unroll
        for (int it = 0; it < 32; it++) {
            int e = tid + it * 256;
            int i = e & 127;
            int rest = e >> 7;
            int hh = rest & 1, dp = rest >> 1;
            float a  = ts[(hh * 64 + dp * 2)     * 132 + i];
            float bb = ts[(hh * 64 + dp * 2 + 1) * 132 + i];
            size_t o = ((size_t)(z * HEADS + h0 + hh) * HW + n0 + i) * DH + dp * 2;
            *(uint32_t*)&oh[o] = packh(a, bb);
        }
    }
}

// =================== flash attention (BM=64, j-split warps, 2 CTA/SM) =========
#define QROWB   144
#define VROWB   272
#define FQ_TILE 9216                    // 64 q rows x 144B
#define FK_TILE 18432                   // 128 j rows x 144B
#define FV_TILE 17408                   // 64 d rows x 272B
#define FL_STAGEB (FK_TILE + FV_TILE)   // 35840
#define FL_SMEM (FQ_TILE + 2 * FL_STAGEB) // 80896

__global__ __launch_bounds__(256, 2) void flash_kernel() {
    extern __shared__ char smem[];
    const int tid = threadIdx.x, lane = tid & 31, wid = tid >> 5;
    const int wm = wid & 3;        // m sub-tile (16 rows)
    const int jw = wid >> 2;       // j half (64 cols)
    const int i0 = blockIdx.x * 64;
    const int bh = blockIdx.y;
    const int b = bh >> 3, h = bh & 7;
    const int wr = wm * 16;

    auto ld_Q = [&]() {
#pragma unroll
        for (int it = 0; it < 2; it++) {
            int idx = tid + it * 256;
            int r = idx >> 3, seg = idx & 7;
            const __half* src = g_qTh + ((size_t)bh * HW + i0 + r) * DH + seg * 8;
            CP_ASYNC16(smem_u32(smem + r * QROWB + seg * 16), src);
        }
    };
    auto ld_KV = [&](int jt, int st) {
        char* sb = smem + FQ_TILE + st * FL_STAGEB;
        int j0 = jt * 128;
#pragma unroll
        for (int it = 0; it < 4; it++) {
            int idx = tid + it * 256;
            int r = idx >> 3, seg = idx & 7;
            const __half* src = g_kTh + ((size_t)bh * HW + j0 + r) * DH + seg * 8;
            CP_ASYNC16(smem_u32(sb + r * QROWB + seg * 16), src);
        }
#pragma unroll
        for (int it = 0; it < 4; it++) {
            int idx = tid + it * 256;
            int r = idx >> 4, seg = idx & 15;
            const __half* src = g_Vh + ((size_t)bh * DH + r) * HW + j0 + seg * 8;
            CP_ASYNC16(smem_u32(sb + FK_TILE + r * VROWB + seg * 16), src);
        }
    };

    float acc_o[8][4];
#pragma unroll
    for (int dt = 0; dt < 8; dt++)
#pragma unroll
        for (int j = 0; j < 4; j++) acc_o[dt][j] = 0.f;
    float mrow0 = -INFINITY, mrow1 = -INFINITY;
    float lrow0 = 0.f, lrow1 = 0.f;

    const uint32_t qH = smem_u32(smem);

    ld_Q(); ld_KV(0, 0); CP_COMMIT();
    ld_KV(1, 1); CP_COMMIT();
    CP_WAIT1();
    __syncthreads();

#pragma unroll 1
    for (int jt = 0; jt < 8; jt++) {
        uint32_t kb = smem_u32(smem + FQ_TILE + (jt & 1) * FL_STAGEB);
        uint32_t kH = kb;
        uint32_t vH = kb + FK_TILE;

        float s[8][4];
#pragma unroll
        for (int nt = 0; nt < 8; nt++)
#pragma unroll
            for (int j = 0; j < 4; j++) s[nt][j] = 0.f;

#pragma unroll
        for (int ks = 0; ks < 4; ks++) {
            uint32_t ah[4];
            uint32_t aoff = (uint32_t)((wr + (lane & 15)) * QROWB +
                                       (ks * 16 + (lane >> 4) * 8) * 2);
            LDSM_X4(ah, qH + aoff);
            int krow_l = ((lane >> 4) << 3) + (lane & 7);
            int kcol = ks * 16 + ((lane >> 3) & 1) * 8;
#pragma unroll
            for (int ntp = 0; ntp < 4; ntp++) {
                uint32_t bh_[4];
                uint32_t boff = (uint32_t)((jw * 64 + ntp * 16 + krow_l) * QROWB + kcol * 2);
                LDSM_X4(bh_, kH + boff);
                mma_f16(s[2 * ntp],     ah, bh_);
                mma_f16(s[2 * ntp + 1], ah, bh_ + 2);
            }
        }

        // online softmax over this warp's 64 j-columns (log2 domain)
        float mx0 = -INFINITY, mx1 = -INFINITY;
#pragma unroll
        for (int nt = 0; nt < 8; nt++) {
            mx0 = fmaxf(mx0, fmaxf(s[nt][0], s[nt][1]));
            mx1 = fmaxf(mx1, fmaxf(s[nt][2], s[nt][3]));
        }
        mx0 = fmaxf(mx0, __shfl_xor_sync(0xffffffffu, mx0, 1));
        mx0 = fmaxf(mx0, __shfl_xor_sync(0xffffffffu, mx0, 2));
        mx1 = fmaxf(mx1, __shfl_xor_sync(0xffffffffu, mx1, 1));
        mx1 = fmaxf(mx1, __shfl_xor_sync(0xffffffffu, mx1, 2));
        float mn0 = fmaxf(mrow0, mx0), mn1 = fmaxf(mrow1, mx1);
        float al0 = ex2f(mrow0 - mn0), al1 = ex2f(mrow1 - mn1);
        mrow0 = mn0; mrow1 = mn1;
        lrow0 *= al0; lrow1 *= al1;
#pragma unroll
        for (int dt = 0; dt < 8; dt++) {
            acc_o[dt][0] *= al0; acc_o[dt][1] *= al0;
            acc_o[dt][2] *= al1; acc_o[dt][3] *= al1;
        }
        float ps0 = 0.f, ps1 = 0.f;
#pragma unroll
        for (int nt = 0; nt < 8; nt++) {
            s[nt][0] = ex2f(s[nt][0] - mn0);
            s[nt][1] = ex2f(s[nt][1] - mn0);
            s[nt][2] = ex2f(s[nt][2] - mn1);
            s[nt][3] = ex2f(s[nt][3] - mn1);
            ps0 += s[nt][0] + s[nt][1];
            ps1 += s[nt][2] + s[nt][3];
        }
        lrow0 += ps0; lrow1 += ps1;

        // ---- O += P V^T over this warp's 64 j-columns ----
#pragma unroll
        for (int kk = 0; kk < 4; kk++) {
            uint32_t aph[4];
            aph[0] = packh(s[2 * kk][0],     s[2 * kk][1]);
            aph[1] = packh(s[2 * kk][2],     s[2 * kk][3]);
            aph[2] = packh(s[2 * kk + 1][0], s[2 * kk + 1][1]);
            aph[3] = packh(s[2 * kk + 1][2], s[2 * kk + 1][3]);
            int vrow_l = ((lane >> 4) << 3) + (lane & 7);
            int vcol = jw * 64 + kk * 16 + ((lane >> 3) & 1) * 8;
#pragma unroll
            for (int dt = 0; dt < 4; dt++) {
                uint32_t bvh[4];
                uint32_t off = (uint32_t)((dt * 16 + vrow_l) * VROWB + vcol * 2);
                LDSM_X4(bvh, vH + off);
                mma_f16(acc_o[2 * dt],     aph, bvh);
                mma_f16(acc_o[2 * dt + 1], aph, bvh + 2);
            }
        }

        __syncthreads();
        if (jt + 2 < 8)      { ld_KV(jt + 2, jt & 1); CP_COMMIT(); CP_WAIT1(); }
        else if (jt + 1 < 8) { CP_WAIT0(); }
        __syncthreads();
    }

    // reduce l across the 4-thread quads
    lrow0 += __shfl_xor_sync(0xffffffffu, lrow0, 1);
    lrow0 += __shfl_xor_sync(0xffffffffu, lrow0, 2);
    lrow1 += __shfl_xor_sync(0xffffffffu, lrow1, 1);
    lrow1 += __shfl_xor_sync(0xffffffffu, lrow1, 2);

    // ---- merge the two j-halves via smem ----
    __syncthreads();
    float* mo = (float*)smem;                       // 64 rows x 68 pitch
    float* ml = (float*)(smem + 64 * 68 * 4);       // 64 row maxes
    float* ll = ml + 64;                            // 64 row sums
    int r0 = wr + (lane >> 2);
    int cb = (lane & 3) * 2;

    if (jw == 1) {
#pragma unroll
        for (int dt = 0; dt < 8; dt++) {
            mo[r0 * 68 + dt * 8 + cb]           = acc_o[dt][0];
            mo[r0 * 68 + dt * 8 + cb + 1]       = acc_o[dt][1];
            mo[(r0 + 8) * 68 + dt * 8 + cb]     = acc_o[dt][2];
            mo[(r0 + 8) * 68 + dt * 8 + cb + 1] = acc_o[dt][3];
        }
        if ((lane & 3) == 0) {
            ml[r0] = mrow0; ml[r0 + 8] = mrow1;
            ll[r0] = lrow0; ll[r0 + 8] = lrow1;
        }
    }
    __syncthreads();
    if (jw == 0) {
        float mB0 = ml[r0],     lB0 = ll[r0];
        float mB1 = ml[r0 + 8], lB1 = ll[r0 + 8];
        float m0 = fmaxf(mrow0, mB0), m1 = fmaxf(mrow1, mB1);
        float a0 = ex2f(mrow0 - m0), b0 = ex2f(mB0 - m0);
        float a1 = ex2f(mrow1 - m1), b1 = ex2f(mB1 - m1);
        float inv0 = 1.f / (lrow0 * a0 + lB0 * b0);
        float inv1 = 1.f / (lrow1 * a1 + lB1 * b1);
        int cbase = h * DH + cb;
#pragma unroll
        for (int dt = 0; dt < 8; dt++) {
            float ox = (acc_o[dt][0] * a0 + mo[r0 * 68 + dt * 8 + cb]     * b0) * inv0;
            float oy = (acc_o[dt][1] * a0 + mo[r0 * 68 + dt * 8 + cb + 1] * b0) * inv0;
            size_t o0 = ((size_t)b * HW + i0 + r0) * C + cbase + dt * 8;
            *(uint32_t*)&g_AOTh[o0] = packh(ox, oy);
            ox = (acc_o[dt][2] * a1 + mo[(r0 + 8) * 68 + dt * 8 + cb]     * b1) * inv1;
            oy = (acc_o[dt][3] * a1 + mo[(r0 + 8) * 68 + dt * 8 + cb + 1] * b1) * inv1;
            size_t o1 = ((size_t)b * HW + i0 + r0 + 8) * C + cbase + dt * 8;
            *(uint32_t*)&g_AOTh[o1] = packh(ox, oy);
        }
    }
}

// =================== proj GEMM (4-stage, 2 CTA/SM) ============================
__global__ __launch_bounds__(256, 2) void proj_gemm(const float* __restrict__ bias,
                                                    const float* __restrict__ resid,
                                                    float* __restrict__ out) {
    constexpr int BM = 128;
    extern __shared__ char smem[];

    const int tid = threadIdx.x;
    const int lane = tid & 31, wid = tid >> 5;
    const int wm = wid & 1, wn = wid >> 1;
    const int n0 = blockIdx.x * 128, m0 = blockIdx.y * 128;
    const int z = blockIdx.z;

    const __half* pA = g_WhP + (size_t)m0 * C;
    const __half* pB = g_AOTh + ((size_t)z * HW + n0) * C;

    auto load_chunk = [&](int stage, int k0) {
        char* sb = smem + stage * DSTG;
#pragma unroll
        for (int it = 0; it < 4; it++) {
            int idx = tid + it * 256;
            int row = idx >> 2, seg = idx & 3;
            const __half* src; int toff; int r;
            if (row < BM) { src = pA; toff = 0;     r = row; }
            else          { src = pB; toff = DTILE; r = row - BM; }
            CP_ASYNC16(smem_u32(sb + toff + r * ROWB + seg * 16),
                       src + (size_t)r * C + k0 + seg * 8);
        }
        CP_COMMIT();
    };

    float acc[4][4][4];
#pragma unroll
    for (int mi = 0; mi < 4; mi++)
#pragma unroll
        for (int ni = 0; ni < 4; ni++)
#pragma unroll
            for (int j = 0; j < 4; j++) acc[mi][ni][j] = 0.f;

    const int NCH = C / KC;
    load_chunk(0, 0);
    load_chunk(1, KC);
    load_chunk(2, 2 * KC);
#pragma unroll 1
    for (int c = 0; c < NCH; c++) {
        if (c <= NCH - 3)      CP_WAIT2();
        else if (c == NCH - 2) CP_WAIT1();
        else                   CP_WAIT0();
        __syncthreads();
        if (c + 3 < NCH) load_chunk((c + 3) & 3, (c + 3) * KC);
        char* sb = smem + (c & 3) * DSTG;
        uint32_t aH = smem_u32(sb);
        uint32_t bH = aH + DTILE;
#pragma unroll
        for (int ks = 0; ks < 2; ks++) {
            uint32_t ah[4][4], bh[4][2];
            int acol = ks * 16 + (lane >> 4) * 8;
#pragma unroll
            for (int mi = 0; mi < 4; mi++) {
                uint32_t off = (uint32_t)((wm * 64 + mi * 16 + (lane & 15)) * ROWB + acol * 2);
                LDSM_X4(ah[mi], aH + off);
            }
            int l = lane & 15;
            int bcol = ks * 16 + (l >> 3) * 8;
#pragma unroll
            for (int ni = 0; ni < 4; ni++) {
                uint32_t off = (uint32_t)((wn * 32 + ni * 8 + (l & 7)) * ROWB + bcol * 2);
                LDSM_X2(bh[ni], bH + off);
            }
#pragma unroll
            for (int mi = 0; mi < 4; mi++)
#pragma unroll
                for (int ni = 0; ni < 4; ni++)
                    mma_f16(acc[mi][ni], ah[mi], bh[ni]);
        }
    }

    float* po = out + (size_t)z * C * HW;
#pragma unroll
    for (int mi = 0; mi < 4; mi++)
#pragma unroll
        for (int ni = 0; ni < 4; ni++) {
            int col = n0 + wn * 32 + ni * 8 + (lane & 3) * 2;
#pragma unroll
            for (int hrow = 0; hrow < 2; hrow++) {
                int r = m0 + wm * 64 + mi * 16 + (lane >> 2) + hrow * 8;
                float bm = bias[r];
                size_t off = (size_t)r * HW + col;
                float2 rx = *(const float2*)&resid[(size_t)z * C * HW + off];
                float2 v;
                v.x = acc[mi][ni][hrow * 2 + 0] + bm + rx.x;
                v.y = acc[mi][ni][hrow * 2 + 1] + bm + rx.y;
                *(float2*)&po[off] = v;
            }
        }
}

// =================== launch ===================================================
extern "C" void kernel_launch(void* const* d_in, const int* in_sizes, int n_in,
                              void* d_out, int out_size) {
    const float* x      = (const float*)d_in[0];
    const float* gn_w   = (const float*)d_in[1];
    const float* gn_b   = (const float*)d_in[2];
    const float* qkv_w  = (const float*)d_in[3];
    const float* qkv_b  = (const float*)d_in[4];
    const float* proj_w = (const float*)d_in[5];
    const float* proj_b = (const float*)d_in[6];
    float* out = (float*)d_out;

    static bool init = false;
    if (!init) {
        cudaFuncSetAttribute(qkv_gemm, cudaFuncAttributeMaxDynamicSharedMemorySize, SMQKV);
        cudaFuncSetAttribute(proj_gemm, cudaFuncAttributeMaxDynamicSharedMemorySize, SMPROJ);
        cudaFuncSetAttribute(flash_kernel, cudaFuncAttributeMaxDynamicSharedMemorySize, FL_SMEM);
        init = true;
    }

    prep_kernel<<<1280, 256>>>(x, qkv_w, proj_w);
    convT_kernel<<<dim3(HW / 32, C / 32, B), dim3(32, 8)>>>(x, gn_w, gn_b);

    qkv_gemm<<<dim3(HW / 128, 3 * C / 128, B), 256, SMQKV>>>(qkv_b);

    flash_kernel<<<dim3(HW / 64, B * HEADS), 256, FL_SMEM>>>();

    proj_gemm<<<dim3(HW / 128, C / 128, B), 256, SMPROJ>>>(proj_b, x, out);
}

// round 10
// speedup vs baseline: 6.2194x; 1.0141x over previous
#include <cuda_runtime.h>
#include <cuda_fp16.h>
#include <cstdint>
#include <math.h>

#define B    8
#define C    512
#define HW   1024
#define G    32
#define CPG  16
#define HEADS 8
#define DH   64
#define EPS  1e-5f
#define QSCALE 0.1803368867f   // 0.125 * log2(e)

// ---------------- scratch (device globals) ----------------------------------
__device__ float2 g_stats[B * G];

__device__ __half g_WhQ[3 * C * C];
__device__ __half g_WhP[C * C];
__device__ __half g_XTh [B * HW * C];          // [b][n][c]
__device__ __half g_AOTh[B * HW * C];          // [b][i][c]
__device__ __half g_qTh [B * HEADS * HW * DH]; // [bh][i][d] (log2-scaled)
__device__ __half g_kTh [B * HEADS * HW * DH]; // [bh][j][d]
__device__ __half g_Vh  [B * HEADS * DH * HW]; // [bh][d][j]

// =================== helpers ==================================================
__device__ __forceinline__ uint32_t smem_u32(const void* p) {
    uint32_t r;
    asm("{ .reg .u64 t; cvta.to.shared.u64 t, %1; cvt.u32.u64 %0, t; }"
        : "=r"(r) : "l"(p));
    return r;
}
#define CP_ASYNC16(dst, src) \
    asm volatile("cp.async.cg.shared.global [%0], [%1], 16;" :: "r"(dst), "l"(src) : "memory")
#define CP_COMMIT() asm volatile("cp.async.commit_group;" ::: "memory")
#define CP_WAIT2()  asm volatile("cp.async.wait_group 2;" ::: "memory")
#define CP_WAIT1()  asm volatile("cp.async.wait_group 1;" ::: "memory")
#define CP_WAIT0()  asm volatile("cp.async.wait_group 0;" ::: "memory")

#define LDSM_X4(r, addr) \
    asm volatile("ldmatrix.sync.aligned.m8n8.x4.shared.b16 {%0,%1,%2,%3}, [%4];" \
        : "=r"((r)[0]), "=r"((r)[1]), "=r"((r)[2]), "=r"((r)[3]) : "r"(addr))
#define LDSM_X2(r, addr) \
    asm volatile("ldmatrix.sync.aligned.m8n8.x2.shared.b16 {%0,%1}, [%2];" \
        : "=r"((r)[0]), "=r"((r)[1]) : "r"(addr))

__device__ __forceinline__ void mma_f16(float* c, const uint32_t* a, const uint32_t* b) {
    asm volatile(
        "mma.sync.aligned.m16n8k16.row.col.f32.f16.f16.f32 "
        "{%0,%1,%2,%3}, {%4,%5,%6,%7}, {%8,%9}, {%0,%1,%2,%3};"
        : "+f"(c[0]), "+f"(c[1]), "+f"(c[2]), "+f"(c[3])
        : "r"(a[0]), "r"(a[1]), "r"(a[2]), "r"(a[3]), "r"(b[0]), "r"(b[1]));
}
__device__ __forceinline__ uint32_t packh(float x, float y) {
    __half2 h = __floats2half2_rn(x, y);
    return *(uint32_t*)&h;
}
__device__ __forceinline__ float ex2f(float x) {
    float y;
    asm("ex2.approx.f32 %0, %1;" : "=f"(y) : "f"(x));
    return y;
}
__device__ __forceinline__ uint32_t ex2h2(uint32_t x) {
    uint32_t y;
    asm("ex2.approx.f16x2 %0, %1;" : "=r"(y) : "r"(x));
    return y;
}

// =========== fused prologue: gn stats + both weight converts ==================
__global__ __launch_bounds__(256) void prep_kernel(const float* __restrict__ x,
                                                   const float* __restrict__ qkv_w,
                                                   const float* __restrict__ proj_w) {
    int blk = blockIdx.x;
    if (blk < 256) {
        const float4* xp = (const float4*)(x + (size_t)blk * CPG * HW);
        const int N4 = CPG * HW / 4;
        float s = 0.f, s2 = 0.f;
        for (int i = threadIdx.x; i < N4; i += 256) {
            float4 v = xp[i];
            s  += v.x + v.y + v.z + v.w;
            s2 += v.x * v.x + v.y * v.y + v.z * v.z + v.w * v.w;
        }
        __shared__ float sh1[8], sh2[8];
        int lane = threadIdx.x & 31, wid = threadIdx.x >> 5;
        for (int o = 16; o; o >>= 1) {
            s  += __shfl_down_sync(0xffffffffu, s,  o);
            s2 += __shfl_down_sync(0xffffffffu, s2, o);
        }
        if (lane == 0) { sh1[wid] = s; sh2[wid] = s2; }
        __syncthreads();
        if (threadIdx.x == 0) {
            for (int i = 1; i < 8; i++) { sh1[0] += sh1[i]; sh2[0] += sh2[i]; }
            const float N = CPG * HW;
            float mean = sh1[0] * (1.f / N);
            float var  = sh2[0] * (1.f / N) - mean * mean;
            g_stats[blk] = make_float2(mean, rsqrtf(var + EPS));
        }
    } else if (blk < 1024) {
        int i = (blk - 256) * 1024 + threadIdx.x * 4;
        float4 v = *(const float4*)&qkv_w[i];
        *(uint32_t*)&g_WhQ[i]     = packh(v.x, v.y);
        *(uint32_t*)&g_WhQ[i + 2] = packh(v.z, v.w);
    } else {
        int i = (blk - 1024) * 1024 + threadIdx.x * 4;
        float4 v = *(const float4*)&proj_w[i];
        *(uint32_t*)&g_WhP[i]     = packh(v.x, v.y);
        *(uint32_t*)&g_WhP[i + 2] = packh(v.z, v.w);
    }
}

// ===== fused GN-apply + transpose + convert ===================================
__global__ __launch_bounds__(256) void convT_kernel(const float* __restrict__ x,
                                                    const float* __restrict__ gw,
                                                    const float* __restrict__ gb) {
    __shared__ float t[32][33];
    int n0 = blockIdx.x * 32, c0 = blockIdx.y * 32, b = blockIdx.z;
    const float* ip = x + (size_t)b * C * HW;
    int tx = threadIdx.x, ty = threadIdx.y;
#pragma unroll
    for (int k = 0; k < 4; k++) {
        int ch = c0 + ty + k * 8;
        float2 st = g_stats[b * G + (ch >> 4)];
        float v = ip[(size_t)ch * HW + n0 + tx];
        t[ty + k * 8][tx] = (v - st.x) * st.y * gw[ch] + gb[ch];
    }
    __syncthreads();
#pragma unroll
    for (int k = 0; k < 4; k++) {
        int ni = ty + k * 8;
        size_t o = (size_t)b * HW * C + (size_t)(n0 + ni) * C + c0 + tx;
        g_XTh[o] = __float2half(t[tx][ni]);
    }
}

// =================== dense GEMM config (4-stage, 2 CTA/SM) ====================
#define KC    32
#define ROWB  80
#define DTILE (128 * ROWB)
#define DSTG  (2 * DTILE)
#define SMQKV 81920
#define SMPROJ 81920

// =================== QKV GEMM =================================================
__global__ __launch_bounds__(256, 2) void qkv_gemm(const float* __restrict__ bias) {
    constexpr int BM = 128;
    extern __shared__ char smem[];

    const int tid = threadIdx.x;
    const int lane = tid & 31, wid = tid >> 5;
    const int wm = wid & 1, wn = wid >> 1;
    const int n0 = blockIdx.x * 128, m0 = blockIdx.y * 128;
    const int z = blockIdx.z;

    const __half* pA = g_WhQ + (size_t)m0 * C;
    const __half* pB = g_XTh + ((size_t)z * HW + n0) * C;

    auto load_chunk = [&](int stage, int k0) {
        char* sb = smem + stage * DSTG;
#pragma unroll
        for (int it = 0; it < 4; it++) {
            int idx = tid + it * 256;
            int row = idx >> 2, seg = idx & 3;
            const __half* src; int toff; int r;
            if (row < BM) { src = pA; toff = 0;     r = row; }
            else          { src = pB; toff = DTILE; r = row - BM; }
            CP_ASYNC16(smem_u32(sb + toff + r * ROWB + seg * 16),
                       src + (size_t)r * C + k0 + seg * 8);
        }
        CP_COMMIT();
    };

    float acc[4][4][4];
#pragma unroll
    for (int mi = 0; mi < 4; mi++)
#pragma unroll
        for (int ni = 0; ni < 4; ni++)
#pragma unroll
            for (int j = 0; j < 4; j++) acc[mi][ni][j] = 0.f;

    const int NCH = C / KC;
    load_chunk(0, 0);
    load_chunk(1, KC);
    load_chunk(2, 2 * KC);
#pragma unroll 1
    for (int c = 0; c < NCH; c++) {
        if (c <= NCH - 3)      CP_WAIT2();
        else if (c == NCH - 2) CP_WAIT1();
        else                   CP_WAIT0();
        __syncthreads();
        if (c + 3 < NCH) load_chunk((c + 3) & 3, (c + 3) * KC);
        char* sb = smem + (c & 3) * DSTG;
        uint32_t aH = smem_u32(sb);
        uint32_t bH = aH + DTILE;
#pragma unroll
        for (int ks = 0; ks < 2; ks++) {
            uint32_t ah[4][4], bh[4][2];
            int acol = ks * 16 + (lane >> 4) * 8;
#pragma unroll
            for (int mi = 0; mi < 4; mi++) {
                uint32_t off = (uint32_t)((wm * 64 + mi * 16 + (lane & 15)) * ROWB + acol * 2);
                LDSM_X4(ah[mi], aH + off);
            }
            int l = lane & 15;
            int bcol = ks * 16 + (l >> 3) * 8;
#pragma unroll
            for (int ni = 0; ni < 4; ni++) {
                uint32_t off = (uint32_t)((wn * 32 + ni * 8 + (l & 7)) * ROWB + bcol * 2);
                LDSM_X2(bh[ni], bH + off);
            }
#pragma unroll
            for (int mi = 0; mi < 4; mi++)
#pragma unroll
                for (int ni = 0; ni < 4; ni++)
                    mma_f16(acc[mi][ni], ah[mi], bh[ni]);
        }
    }

    const int sec = m0 >> 9;
    const float scale = (sec == 0) ? QSCALE : 1.0f;

    __syncthreads();
    if (sec == 2) {
#pragma unroll
        for (int mi = 0; mi < 4; mi++)
#pragma unroll
            for (int ni = 0; ni < 4; ni++) {
                int col = wn * 32 + ni * 8 + (lane & 3) * 2;
#pragma unroll
                for (int hrow = 0; hrow < 2; hrow++) {
                    int r = wm * 64 + mi * 16 + (lane >> 2) + hrow * 8;
                    int mC = (m0 - 1024) + r;
                    float bm = bias[m0 + r];
                    size_t o = ((size_t)(z * HEADS + (mC >> 6)) * DH + (mC & 63)) * HW + n0 + col;
                    *(uint32_t*)&g_Vh[o] = packh(acc[mi][ni][hrow * 2 + 0] + bm,
                                                 acc[mi][ni][hrow * 2 + 1] + bm);
                }
            }
    } else {
        float* ts = (float*)smem;
#pragma unroll
        for (int mi = 0; mi < 4; mi++)
#pragma unroll
            for (int ni = 0; ni < 4; ni++) {
                int col = wn * 32 + ni * 8 + (lane & 3) * 2;
#pragma unroll
                for (int hrow = 0; hrow < 2; hrow++) {
                    int r = wm * 64 + mi * 16 + (lane >> 2) + hrow * 8;
                    float bm = bias[m0 + r];
                    ts[r * 132 + col]     = (acc[mi][ni][hrow * 2 + 0] + bm) * scale;
                    ts[r * 132 + col + 1] = (acc[mi][ni][hrow * 2 + 1] + bm) * scale;
                }
            }
        __syncthreads();
        __half* oh = sec ? g_kTh : g_qTh;
        int h0 = (m0 & 511) >> 6;
#pragma unroll
        for (int it = 0; it < 32; it++) {
            int e = tid + it * 256;
            int i = e & 127;
            int rest = e >> 7;
            int hh = rest & 1, dp = rest >> 1;
            float a  = ts[(hh * 64 + dp * 2)     * 132 + i];
            float bb = ts[(hh * 64 + dp * 2 + 1) * 132 + i];
            size_t o = ((size_t)(z * HEADS + h0 + hh) * HW + n0 + i) * DH + dp * 2;
            *(uint32_t*)&oh[o] = packh(a, bb);
        }
    }
}

// =================== flash attention ==========================================
#define QROWB   144
#define VROWB   272
#define FQ_TILE 9216
#define FK_TILE 18432
#define FV_TILE 17408
#define FL_STAGEB (FK_TILE + FV_TILE)
#define FL_SMEM (FQ_TILE + 2 * FL_STAGEB) // 80896

__global__ __launch_bounds__(256, 2) void flash_kernel() {
    extern __shared__ char smem[];
    const int tid = threadIdx.x, lane = tid & 31, wid = tid >> 5;
    const int wm = wid & 3;
    const int jw = wid >> 2;
    const int i0 = blockIdx.x * 64;
    const int bh = blockIdx.y;
    const int b = bh >> 3, h = bh & 7;
    const int wr = wm * 16;
    const uint32_t ONES2[2] = {0x3C003C00u, 0x3C003C00u};   // fp16 1.0 x4

    auto ld_Q = [&]() {
#pragma unroll
        for (int it = 0; it < 2; it++) {
            int idx = tid + it * 256;
            int r = idx >> 3, seg = idx & 7;
            const __half* src = g_qTh + ((size_t)bh * HW + i0 + r) * DH + seg * 8;
            CP_ASYNC16(smem_u32(smem + r * QROWB + seg * 16), src);
        }
    };
    auto ld_KV = [&](int jt, int st) {
        char* sb = smem + FQ_TILE + st * FL_STAGEB;
        int j0 = jt * 128;
#pragma unroll
        for (int it = 0; it < 4; it++) {
            int idx = tid + it * 256;
            int r = idx >> 3, seg = idx & 7;
            const __half* src = g_kTh + ((size_t)bh * HW + j0 + r) * DH + seg * 8;
            CP_ASYNC16(smem_u32(sb + r * QROWB + seg * 16), src);
        }
#pragma unroll
        for (int it = 0; it < 4; it++) {
            int idx = tid + it * 256;
            int r = idx >> 4, seg = idx & 15;
            const __half* src = g_Vh + ((size_t)bh * DH + r) * HW + j0 + seg * 8;
            CP_ASYNC16(smem_u32(sb + FK_TILE + r * VROWB + seg * 16), src);
        }
    };

    float acc_o[8][4];
#pragma unroll
    for (int dt = 0; dt < 8; dt++)
#pragma unroll
        for (int j = 0; j < 4; j++) acc_o[dt][j] = 0.f;
    float lacc[4] = {0.f, 0.f, 0.f, 0.f};          // l row-sums via tensor core
    float mrow0 = -INFINITY, mrow1 = -INFINITY;

    const uint32_t qH = smem_u32(smem);

    ld_Q(); ld_KV(0, 0); CP_COMMIT();
    ld_KV(1, 1); CP_COMMIT();
    CP_WAIT1();
    __syncthreads();

#pragma unroll 1
    for (int jt = 0; jt < 8; jt++) {
        uint32_t kb = smem_u32(smem + FQ_TILE + (jt & 1) * FL_STAGEB);
        uint32_t kH = kb;
        uint32_t vH = kb + FK_TILE;

        float s[8][4];
#pragma unroll
        for (int nt = 0; nt < 8; nt++)
#pragma unroll
            for (int j = 0; j < 4; j++) s[nt][j] = 0.f;

#pragma unroll
        for (int ks = 0; ks < 4; ks++) {
            uint32_t ah[4];
            uint32_t aoff = (uint32_t)((wr + (lane & 15)) * QROWB +
                                       (ks * 16 + (lane >> 4) * 8) * 2);
            LDSM_X4(ah, qH + aoff);
            int krow_l = ((lane >> 4) << 3) + (lane & 7);
            int kcol = ks * 16 + ((lane >> 3) & 1) * 8;
#pragma unroll
            for (int ntp = 0; ntp < 4; ntp++) {
                uint32_t bh_[4];
                uint32_t boff = (uint32_t)((jw * 64 + ntp * 16 + krow_l) * QROWB + kcol * 2);
                LDSM_X4(bh_, kH + boff);
                mma_f16(s[2 * ntp],     ah, bh_);
                mma_f16(s[2 * ntp + 1], ah, bh_ + 2);
            }
        }

        // ---- online softmax (log2 domain) ----
        float mx0 = -INFINITY, mx1 = -INFINITY;
#pragma unroll
        for (int nt = 0; nt < 8; nt++) {
            mx0 = fmaxf(mx0, fmaxf(s[nt][0], s[nt][1]));
            mx1 = fmaxf(mx1, fmaxf(s[nt][2], s[nt][3]));
        }
        mx0 = fmaxf(mx0, __shfl_xor_sync(0xffffffffu, mx0, 1));
        mx0 = fmaxf(mx0, __shfl_xor_sync(0xffffffffu, mx0, 2));
        mx1 = fmaxf(mx1, __shfl_xor_sync(0xffffffffu, mx1, 1));
        mx1 = fmaxf(mx1, __shfl_xor_sync(0xffffffffu, mx1, 2));
        float mn0 = fmaxf(mrow0, mx0), mn1 = fmaxf(mrow1, mx1);
        float al0 = ex2f(mrow0 - mn0), al1 = ex2f(mrow1 - mn1);
        mrow0 = mn0; mrow1 = mn1;
#pragma unroll
        for (int dt = 0; dt < 8; dt++) {
            acc_o[dt][0] *= al0; acc_o[dt][1] *= al0;
            acc_o[dt][2] *= al1; acc_o[dt][3] *= al1;
        }
        lacc[0] *= al0; lacc[1] *= al0;
        lacc[2] *= al1; lacc[3] *= al1;

        // exp in fp16x2: p0 = P rows(lane>>2), p1 = rows+8
        uint32_t p0[8], p1[8];
#pragma unroll
        for (int nt = 0; nt < 8; nt++) {
            p0[nt] = ex2h2(packh(s[nt][0] - mn0, s[nt][1] - mn0));
            p1[nt] = ex2h2(packh(s[nt][2] - mn1, s[nt][3] - mn1));
        }

        // ---- l += P x ones, O += P V^T ----
#pragma unroll
        for (int kk = 0; kk < 4; kk++) {
            uint32_t aph[4];
            aph[0] = p0[2 * kk];     aph[1] = p1[2 * kk];
            aph[2] = p0[2 * kk + 1]; aph[3] = p1[2 * kk + 1];
            mma_f16(lacc, aph, ONES2);
            int vrow_l = ((lane >> 4) << 3) + (lane & 7);
            int vcol = jw * 64 + kk * 16 + ((lane >> 3) & 1) * 8;
#pragma unroll
            for (int dt = 0; dt < 4; dt++) {
                uint32_t bvh[4];
                uint32_t off = (uint32_t)((dt * 16 + vrow_l) * VROWB + vcol * 2);
                LDSM_X4(bvh, vH + off);
                mma_f16(acc_o[2 * dt],     aph, bvh);
                mma_f16(acc_o[2 * dt + 1], aph, bvh + 2);
            }
        }

        __syncthreads();
        if (jt + 2 < 8)      { ld_KV(jt + 2, jt & 1); CP_COMMIT(); CP_WAIT1(); }
        else if (jt + 1 < 8) { CP_WAIT0(); }
        __syncthreads();
    }

    float lrow0 = lacc[0], lrow1 = lacc[2];  // quad-replicated by the ones-MMA

    // ---- merge the two j-halves via smem ----
    __syncthreads();
    float* mo = (float*)smem;                       // 64 rows x 68 pitch
    float* ml = (float*)(smem + 64 * 68 * 4);
    float* ll = ml + 64;
    int r0 = wr + (lane >> 2);
    int cb = (lane & 3) * 2;

    if (jw == 1) {
#pragma unroll
        for (int dt = 0; dt < 8; dt++) {
            mo[r0 * 68 + dt * 8 + cb]           = acc_o[dt][0];
            mo[r0 * 68 + dt * 8 + cb + 1]       = acc_o[dt][1];
            mo[(r0 + 8) * 68 + dt * 8 + cb]     = acc_o[dt][2];
            mo[(r0 + 8) * 68 + dt * 8 + cb + 1] = acc_o[dt][3];
        }
        if ((lane & 3) == 0) {
            ml[r0] = mrow0; ml[r0 + 8] = mrow1;
            ll[r0] = lrow0; ll[r0 + 8] = lrow1;
        }
    }
    __syncthreads();
    if (jw == 0) {
        float mB0 = ml[r0],     lB0 = ll[r0];
        float mB1 = ml[r0 + 8], lB1 = ll[r0 + 8];
        float m0 = fmaxf(mrow0, mB0), m1 = fmaxf(mrow1, mB1);
        float a0 = ex2f(mrow0 - m0), b0 = ex2f(mB0 - m0);
        float a1 = ex2f(mrow1 - m1), b1 = ex2f(mB1 - m1);
        float inv0 = 1.f / (lrow0 * a0 + lB0 * b0);
        float inv1 = 1.f / (lrow1 * a1 + lB1 * b1);
        int cbase = h * DH + cb;
#pragma unroll
        for (int dt = 0; dt < 8; dt++) {
            float ox = (acc_o[dt][0] * a0 + mo[r0 * 68 + dt * 8 + cb]     * b0) * inv0;
            float oy = (acc_o[dt][1] * a0 + mo[r0 * 68 + dt * 8 + cb + 1] * b0) * inv0;
            size_t o0 = ((size_t)b * HW + i0 + r0) * C + cbase + dt * 8;
            *(uint32_t*)&g_AOTh[o0] = packh(ox, oy);
            ox = (acc_o[dt][2] * a1 + mo[(r0 + 8) * 68 + dt * 8 + cb]     * b1) * inv1;
            oy = (acc_o[dt][3] * a1 + mo[(r0 + 8) * 68 + dt * 8 + cb + 1] * b1) * inv1;
            size_t o1 = ((size_t)b * HW + i0 + r0 + 8) * C + cbase + dt * 8;
            *(uint32_t*)&g_AOTh[o1] = packh(ox, oy);
        }
    }
}

// =================== proj GEMM ================================================
__global__ __launch_bounds__(256, 2) void proj_gemm(const float* __restrict__ bias,
                                                    const float* __restrict__ resid,
                                                    float* __restrict__ out) {
    constexpr int BM = 128;
    extern __shared__ char smem[];

    const int tid = threadIdx.x;
    const int lane = tid & 31, wid = tid >> 5;
    const int wm = wid & 1, wn = wid >> 1;
    const int n0 = blockIdx.x * 128, m0 = blockIdx.y * 128;
    const int z = blockIdx.z;

    const __half* pA = g_WhP + (size_t)m0 * C;
    const __half* pB = g_AOTh + ((size_t)z * HW + n0) * C;

    auto load_chunk = [&](int stage, int k0) {
        char* sb = smem + stage * DSTG;
#pragma unroll
        for (int it = 0; it < 4; it++) {
            int idx = tid + it * 256;
            int row = idx >> 2, seg = idx & 3;
            const __half* src; int toff; int r;
            if (row < BM) { src = pA; toff = 0;     r = row; }
            else          { src = pB; toff = DTILE; r = row - BM; }
            CP_ASYNC16(smem_u32(sb + toff + r * ROWB + seg * 16),
                       src + (size_t)r * C + k0 + seg * 8);
        }
        CP_COMMIT();
    };

    float acc[4][4][4];
#pragma unroll
    for (int mi = 0; mi < 4; mi++)
#pragma unroll
        for (int ni = 0; ni < 4; ni++)
#pragma unroll
            for (int j = 0; j < 4; j++) acc[mi][ni][j] = 0.f;

    const int NCH = C / KC;
    load_chunk(0, 0);
    load_chunk(1, KC);
    load_chunk(2, 2 * KC);
#pragma unroll 1
    for (int c = 0; c < NCH; c++) {
        if (c <= NCH - 3)      CP_WAIT2();
        else if (c == NCH - 2) CP_WAIT1();
        else                   CP_WAIT0();
        __syncthreads();
        if (c + 3 < NCH) load_chunk((c + 3) & 3, (c + 3) * KC);
        char* sb = smem + (c & 3) * DSTG;
        uint32_t aH = smem_u32(sb);
        uint32_t bH = aH + DTILE;
#pragma unroll
        for (int ks = 0; ks < 2; ks++) {
            uint32_t ah[4][4], bh[4][2];
            int acol = ks * 16 + (lane >> 4) * 8;
#pragma unroll
            for (int mi = 0; mi < 4; mi++) {
                uint32_t off = (uint32_t)((wm * 64 + mi * 16 + (lane & 15)) * ROWB + acol * 2);
                LDSM_X4(ah[mi], aH + off);
            }
            int l = lane & 15;
            int bcol = ks * 16 + (l >> 3) * 8;
#pragma unroll
            for (int ni = 0; ni < 4; ni++) {
                uint32_t off = (uint32_t)((wn * 32 + ni * 8 + (l & 7)) * ROWB + bcol * 2);
                LDSM_X2(bh[ni], bH + off);
            }
#pragma unroll
            for (int mi = 0; mi < 4; mi++)
#pragma unroll
                for (int ni = 0; ni < 4; ni++)
                    mma_f16(acc[mi][ni], ah[mi], bh[ni]);
        }
    }

    float* po = out + (size_t)z * C * HW;
#pragma unroll
    for (int mi = 0; mi < 4; mi++)
#pragma unroll
        for (int ni = 0; ni < 4; ni++) {
            int col = n0 + wn * 32 + ni * 8 + (lane & 3) * 2;
#pragma unroll
            for (int hrow = 0; hrow < 2; hrow++) {
                int r = m0 + wm * 64 + mi * 16 + (lane >> 2) + hrow * 8;
                float bm = bias[r];
                size_t off = (size_t)r * HW + col;
                float2 rx = *(const float2*)&resid[(size_t)z * C * HW + off];
                float2 v;
                v.x = acc[mi][ni][hrow * 2 + 0] + bm + rx.x;
                v.y = acc[mi][ni][hrow * 2 + 1] + bm + rx.y;
                *(float2*)&po[off] = v;
            }
        }
}

// =================== launch ===================================================
extern "C" void kernel_launch(void* const* d_in, const int* in_sizes, int n_in,
                              void* d_out, int out_size) {
    const float* x      = (const float*)d_in[0];
    const float* gn_w   = (const float*)d_in[1];
    const float* gn_b   = (const float*)d_in[2];
    const float* qkv_w  = (const float*)d_in[3];
    const float* qkv_b  = (const float*)d_in[4];
    const float* proj_w = (const float*)d_in[5];
    const float* proj_b = (const float*)d_in[6];
    float* out = (float*)d_out;

    static bool init = false;
    if (!init) {
        cudaFuncSetAttribute(qkv_gemm, cudaFuncAttributeMaxDynamicSharedMemorySize, SMQKV);
        cudaFuncSetAttribute(proj_gemm, cudaFuncAttributeMaxDynamicSharedMemorySize, SMPROJ);
        cudaFuncSetAttribute(flash_kernel, cudaFuncAttributeMaxDynamicSharedMemorySize, FL_SMEM);
        init = true;
    }

    prep_kernel<<<1280, 256>>>(x, qkv_w, proj_w);
    convT_kernel<<<dim3(HW / 32, C / 32, B), dim3(32, 8)>>>(x, gn_w, gn_b);

    qkv_gemm<<<dim3(HW / 128, 3 * C / 128, B), 256, SMQKV>>>(qkv_b);

    flash_kernel<<<dim3(HW / 64, B * HEADS), 256, FL_SMEM>>>();

    proj_gemm<<<dim3(HW / 128, C / 128, B), 256, SMPROJ>>>(proj_b, x, out);
}

// round 11
// speedup vs baseline: 6.3087x; 1.0144x over previous
#include <cuda_runtime.h>
#include <cuda_fp16.h>
#include <cstdint>
#include <math.h>

#define B    8
#define C    512
#define HW   1024
#define G    32
#define CPG  16
#define HEADS 8
#define DH   64
#define EPS  1e-5f
#define QSCALE 0.1803368867f   // 0.125 * log2(e)

// ---------------- scratch (device globals) ----------------------------------
__device__ float2 g_stats[B * G];

__device__ __half g_WhQ[3 * C * C];
__device__ __half g_WhP[C * C];
__device__ __half g_XTh [B * HW * C];          // [b][n][c]
__device__ __half g_AOTh[B * HW * C];          // [b][i][c]
__device__ __half g_qTh [B * HEADS * HW * DH]; // [bh][i][d] (log2-scaled)
__device__ __half g_kTh [B * HEADS * HW * DH]; // [bh][j][d]
__device__ __half g_Vh  [B * HEADS * DH * HW]; // [bh][d][j]

// =================== helpers ==================================================
__device__ __forceinline__ uint32_t smem_u32(const void* p) {
    uint32_t r;
    asm("{ .reg .u64 t; cvta.to.shared.u64 t, %1; cvt.u32.u64 %0, t; }"
        : "=r"(r) : "l"(p));
    return r;
}
#define CP_ASYNC16(dst, src) \
    asm volatile("cp.async.cg.shared.global [%0], [%1], 16;" :: "r"(dst), "l"(src) : "memory")
#define CP_COMMIT() asm volatile("cp.async.commit_group;" ::: "memory")
#define CP_WAIT2()  asm volatile("cp.async.wait_group 2;" ::: "memory")
#define CP_WAIT1()  asm volatile("cp.async.wait_group 1;" ::: "memory")
#define CP_WAIT0()  asm volatile("cp.async.wait_group 0;" ::: "memory")
#define BAR_GROUP(id) asm volatile("bar.sync %0, %1;" :: "r"(id), "r"(128) : "memory")

#define LDSM_X4(r, addr) \
    asm volatile("ldmatrix.sync.aligned.m8n8.x4.shared.b16 {%0,%1,%2,%3}, [%4];" \
        : "=r"((r)[0]), "=r"((r)[1]), "=r"((r)[2]), "=r"((r)[3]) : "r"(addr))
#define LDSM_X2(r, addr) \
    asm volatile("ldmatrix.sync.aligned.m8n8.x2.shared.b16 {%0,%1}, [%2];" \
        : "=r"((r)[0]), "=r"((r)[1]) : "r"(addr))

__device__ __forceinline__ void mma_f16(float* c, const uint32_t* a, const uint32_t* b) {
    asm volatile(
        "mma.sync.aligned.m16n8k16.row.col.f32.f16.f16.f32 "
        "{%0,%1,%2,%3}, {%4,%5,%6,%7}, {%8,%9}, {%0,%1,%2,%3};"
        : "+f"(c[0]), "+f"(c[1]), "+f"(c[2]), "+f"(c[3])
        : "r"(a[0]), "r"(a[1]), "r"(a[2]), "r"(a[3]), "r"(b[0]), "r"(b[1]));
}
__device__ __forceinline__ uint32_t packh(float x, float y) {
    __half2 h = __floats2half2_rn(x, y);
    return *(uint32_t*)&h;
}
__device__ __forceinline__ float ex2f(float x) {
    float y;
    asm("ex2.approx.f32 %0, %1;" : "=f"(y) : "f"(x));
    return y;
}
__device__ __forceinline__ uint32_t ex2h2(uint32_t x) {
    uint32_t y;
    asm("ex2.approx.f16x2 %0, %1;" : "=r"(y) : "r"(x));
    return y;
}

// =========== fused prologue: gn stats + both weight converts ==================
__global__ __launch_bounds__(256) void prep_kernel(const float* __restrict__ x,
                                                   const float* __restrict__ qkv_w,
                                                   const float* __restrict__ proj_w) {
    int blk = blockIdx.x;
    if (blk < 256) {
        const float4* xp = (const float4*)(x + (size_t)blk * CPG * HW);
        const int N4 = CPG * HW / 4;
        float s = 0.f, s2 = 0.f;
        for (int i = threadIdx.x; i < N4; i += 256) {
            float4 v = xp[i];
            s  += v.x + v.y + v.z + v.w;
            s2 += v.x * v.x + v.y * v.y + v.z * v.z + v.w * v.w;
        }
        __shared__ float sh1[8], sh2[8];
        int lane = threadIdx.x & 31, wid = threadIdx.x >> 5;
        for (int o = 16; o; o >>= 1) {
            s  += __shfl_down_sync(0xffffffffu, s,  o);
            s2 += __shfl_down_sync(0xffffffffu, s2, o);
        }
        if (lane == 0) { sh1[wid] = s; sh2[wid] = s2; }
        __syncthreads();
        if (threadIdx.x == 0) {
            for (int i = 1; i < 8; i++) { sh1[0] += sh1[i]; sh2[0] += sh2[i]; }
            const float N = CPG * HW;
            float mean = sh1[0] * (1.f / N);
            float var  = sh2[0] * (1.f / N) - mean * mean;
            g_stats[blk] = make_float2(mean, rsqrtf(var + EPS));
        }
    } else if (blk < 1024) {
        int i = (blk - 256) * 1024 + threadIdx.x * 4;
        float4 v = *(const float4*)&qkv_w[i];
        *(uint32_t*)&g_WhQ[i]     = packh(v.x, v.y);
        *(uint32_t*)&g_WhQ[i + 2] = packh(v.z, v.w);
    } else {
        int i = (blk - 1024) * 1024 + threadIdx.x * 4;
        float4 v = *(const float4*)&proj_w[i];
        *(uint32_t*)&g_WhP[i]     = packh(v.x, v.y);
        *(uint32_t*)&g_WhP[i + 2] = packh(v.z, v.w);
    }
}

// ===== fused GN-apply + transpose + convert ===================================
__global__ __launch_bounds__(256) void convT_kernel(const float* __restrict__ x,
                                                    const float* __restrict__ gw,
                                                    const float* __restrict__ gb) {
    __shared__ float t[32][33];
    int n0 = blockIdx.x * 32, c0 = blockIdx.y * 32, b = blockIdx.z;
    const float* ip = x + (size_t)b * C * HW;
    int tx = threadIdx.x, ty = threadIdx.y;
#pragma unroll
    for (int k = 0; k < 4; k++) {
        int ch = c0 + ty + k * 8;
        float2 st = g_stats[b * G + (ch >> 4)];
        float v = ip[(size_t)ch * HW + n0 + tx];
        t[ty + k * 8][tx] = (v - st.x) * st.y * gw[ch] + gb[ch];
    }
    __syncthreads();
#pragma unroll
    for (int k = 0; k < 4; k++) {
        int ni = ty + k * 8;
        size_t o = (size_t)b * HW * C + (size_t)(n0 + ni) * C + c0 + tx;
        g_XTh[o] = __float2half(t[tx][ni]);
    }
}

// =================== dense GEMM config (4-stage, 2 CTA/SM) ====================
#define KC    32
#define ROWB  80
#define DTILE (128 * ROWB)
#define DSTG  (2 * DTILE)
#define SMQKV 81920
#define SMPROJ 81920

// =================== QKV GEMM =================================================
__global__ __launch_bounds__(256, 2) void qkv_gemm(const float* __restrict__ bias) {
    constexpr int BM = 128;
    extern __shared__ char smem[];

    const int tid = threadIdx.x;
    const int lane = tid & 31, wid = tid >> 5;
    const int wm = wid & 1, wn = wid >> 1;
    const int n0 = blockIdx.x * 128, m0 = blockIdx.y * 128;
    const int z = blockIdx.z;

    const __half* pA = g_WhQ + (size_t)m0 * C;
    const __half* pB = g_XTh + ((size_t)z * HW + n0) * C;

    auto load_chunk = [&](int stage, int k0) {
        char* sb = smem + stage * DSTG;
#pragma unroll
        for (int it = 0; it < 4; it++) {
            int idx = tid + it * 256;
            int row = idx >> 2, seg = idx & 3;
            const __half* src; int toff; int r;
            if (row < BM) { src = pA; toff = 0;     r = row; }
            else          { src = pB; toff = DTILE; r = row - BM; }
            CP_ASYNC16(smem_u32(sb + toff + r * ROWB + seg * 16),
                       src + (size_t)r * C + k0 + seg * 8);
        }
        CP_COMMIT();
    };

    float acc[4][4][4];
#pragma unroll
    for (int mi = 0; mi < 4; mi++)
#pragma unroll
        for (int ni = 0; ni < 4; ni++)
#pragma unroll
            for (int j = 0; j < 4; j++) acc[mi][ni][j] = 0.f;

    const int NCH = C / KC;
    load_chunk(0, 0);
    load_chunk(1, KC);
    load_chunk(2, 2 * KC);
#pragma unroll 1
    for (int c = 0; c < NCH; c++) {
        if (c <= NCH - 3)      CP_WAIT2();
        else if (c == NCH - 2) CP_WAIT1();
        else                   CP_WAIT0();
        __syncthreads();
        if (c + 3 < NCH) load_chunk((c + 3) & 3, (c + 3) * KC);
        char* sb = smem + (c & 3) * DSTG;
        uint32_t aH = smem_u32(sb);
        uint32_t bH = aH + DTILE;
#pragma unroll
        for (int ks = 0; ks < 2; ks++) {
            uint32_t ah[4][4], bh[4][2];
            int acol = ks * 16 + (lane >> 4) * 8;
#pragma unroll
            for (int mi = 0; mi < 4; mi++) {
                uint32_t off = (uint32_t)((wm * 64 + mi * 16 + (lane & 15)) * ROWB + acol * 2);
                LDSM_X4(ah[mi], aH + off);
            }
            int l = lane & 15;
            int bcol = ks * 16 + (l >> 3) * 8;
#pragma unroll
            for (int ni = 0; ni < 4; ni++) {
                uint32_t off = (uint32_t)((wn * 32 + ni * 8 + (l & 7)) * ROWB + bcol * 2);
                LDSM_X2(bh[ni], bH + off);
            }
#pragma unroll
            for (int mi = 0; mi < 4; mi++)
#pragma unroll
                for (int ni = 0; ni < 4; ni++)
                    mma_f16(acc[mi][ni], ah[mi], bh[ni]);
        }
    }

    const int sec = m0 >> 9;
    const float scale = (sec == 0) ? QSCALE : 1.0f;

    __syncthreads();
    if (sec == 2) {
#pragma unroll
        for (int mi = 0; mi < 4; mi++)
#pragma unroll
            for (int ni = 0; ni < 4; ni++) {
                int col = wn * 32 + ni * 8 + (lane & 3) * 2;
#pragma unroll
                for (int hrow = 0; hrow < 2; hrow++) {
                    int r = wm * 64 + mi * 16 + (lane >> 2) + hrow * 8;
                    int mC = (m0 - 1024) + r;
                    float bm = bias[m0 + r];
                    size_t o = ((size_t)(z * HEADS + (mC >> 6)) * DH + (mC & 63)) * HW + n0 + col;
                    *(uint32_t*)&g_Vh[o] = packh(acc[mi][ni][hrow * 2 + 0] + bm,
                                                 acc[mi][ni][hrow * 2 + 1] + bm);
                }
            }
    } else {
        float* ts = (float*)smem;
#pragma unroll
        for (int mi = 0; mi < 4; mi++)
#pragma unroll
            for (int ni = 0; ni < 4; ni++) {
                int col = wn * 32 + ni * 8 + (lane & 3) * 2;
#pragma unroll
                for (int hrow = 0; hrow < 2; hrow++) {
                    int r = wm * 64 + mi * 16 + (lane >> 2) + hrow * 8;
                    float bm = bias[m0 + r];
                    ts[r * 132 + col]     = (acc[mi][ni][hrow * 2 + 0] + bm) * scale;
                    ts[r * 132 + col + 1] = (acc[mi][ni][hrow * 2 + 1] + bm) * scale;
                }
            }
        __syncthreads();
        __half* oh = sec ? g_kTh : g_qTh;
        int h0 = (m0 & 511) >> 6;
#pragma unroll
        for (int it = 0; it < 32; it++) {
            int e = tid + it * 256;
            int i = e & 127;
            int rest = e >> 7;
            int hh = rest & 1, dp = rest >> 1;
            float a  = ts[(hh * 64 + dp * 2)     * 132 + i];
            float bb = ts[(hh * 64 + dp * 2 + 1) * 132 + i];
            size_t o = ((size_t)(z * HEADS + h0 + hh) * HW + n0 + i) * DH + dp * 2;
            *(uint32_t*)&oh[o] = packh(a, bb);
        }
    }
}

// =================== flash attention ==========================================
// 64 q-rows/CTA; warps = 4(m) x 2(j-groups). Each j-group owns disjoint K rows /
// V column-halves, loads its own half of each stage, and syncs with 128-thread
// named barriers so the two groups drift out of phase (scalar vs tensor overlap).
#define QROWB   144
#define VROWB   272
#define FQ_TILE 9216
#define FK_TILE 18432
#define FV_TILE 17408
#define FL_STAGEB (FK_TILE + FV_TILE)
#define FL_SMEM (FQ_TILE + 2 * FL_STAGEB) // 80896

__global__ __launch_bounds__(256, 2) void flash_kernel() {
    extern __shared__ char smem[];
    const int tid = threadIdx.x, lane = tid & 31, wid = tid >> 5;
    const int wm = wid & 3;
    const int jw = wid >> 2;
    const int gtid = tid & 127;          // tid within j-group
    const int barid = 1 + jw;
    const int i0 = blockIdx.x * 64;
    const int bh = blockIdx.y;
    const int b = bh >> 3, h = bh & 7;
    const int wr = wm * 16;
    const uint32_t ONES2[2] = {0x3C003C00u, 0x3C003C00u};

    auto ld_Q = [&]() {   // full-CTA cooperative
#pragma unroll
        for (int it = 0; it < 2; it++) {
            int idx = tid + it * 256;
            int r = idx >> 3, seg = idx & 7;
            const __half* src = g_qTh + ((size_t)bh * HW + i0 + r) * DH + seg * 8;
            CP_ASYNC16(smem_u32(smem + r * QROWB + seg * 16), src);
        }
    };
    // each j-group loads ONLY its own K rows [jw*64,+64) and V segs [jw*8,+8)
    auto ld_KV = [&](int jt, int st) {
        char* sb = smem + FQ_TILE + st * FL_STAGEB;
        int j0 = jt * 128;
#pragma unroll
        for (int it = 0; it < 4; it++) {
            int idx = gtid + it * 128;           // 0..511
            int r = jw * 64 + (idx >> 3), seg = idx & 7;
            const __half* src = g_kTh + ((size_t)bh * HW + j0 + r) * DH + seg * 8;
            CP_ASYNC16(smem_u32(sb + r * QROWB + seg * 16), src);
        }
#pragma unroll
        for (int it = 0; it < 4; it++) {
            int idx = gtid + it * 128;
            int r = idx >> 3, seg = jw * 8 + (idx & 7);
            const __half* src = g_Vh + ((size_t)bh * DH + r) * HW + j0 + seg * 8;
            CP_ASYNC16(smem_u32(sb + FK_TILE + r * VROWB + seg * 16), src);
        }
        CP_COMMIT();
    };

    float acc_o[8][4];
#pragma unroll
    for (int dt = 0; dt < 8; dt++)
#pragma unroll
        for (int j = 0; j < 4; j++) acc_o[dt][j] = 0.f;
    float lacc[4] = {0.f, 0.f, 0.f, 0.f};
    float mrow0 = -INFINITY, mrow1 = -INFINITY;

    const uint32_t qH = smem_u32(smem);

    ld_Q(); ld_KV(0, 0); CP_COMMIT();    // group 1: Q + tile0 halves
    ld_KV(1, 1);                          // commits inside
    CP_WAIT1();                           // Q + tile0 arrived
    __syncthreads();                      // Q visible to all

    // hoist Q fragments (loop-invariant)
    uint32_t qa[4][4];
#pragma unroll
    for (int ks = 0; ks < 4; ks++) {
        uint32_t aoff = (uint32_t)((wr + (lane & 15)) * QROWB +
                                   (ks * 16 + (lane >> 4) * 8) * 2);
        LDSM_X4(qa[ks], qH + aoff);
    }

    const int krow_l = ((lane >> 4) << 3) + (lane & 7);
    const int kcol_b = ((lane >> 3) & 1) * 8;

#pragma unroll 1
    for (int jt = 0; jt < 8; jt++) {
        uint32_t kb = smem_u32(smem + FQ_TILE + (jt & 1) * FL_STAGEB);
        uint32_t kH = kb;
        uint32_t vH = kb + FK_TILE;

        float s[8][4];
#pragma unroll
        for (int nt = 0; nt < 8; nt++)
#pragma unroll
            for (int j = 0; j < 4; j++) s[nt][j] = 0.f;

#pragma unroll
        for (int ks = 0; ks < 4; ks++) {
            int kcol = ks * 16 + kcol_b;
#pragma unroll
            for (int ntp = 0; ntp < 4; ntp++) {
                uint32_t bh_[4];
                uint32_t boff = (uint32_t)((jw * 64 + ntp * 16 + krow_l) * QROWB + kcol * 2);
                LDSM_X4(bh_, kH + boff);
                mma_f16(s[2 * ntp],     qa[ks], bh_);
                mma_f16(s[2 * ntp + 1], qa[ks], bh_ + 2);
            }
        }

        // ---- online softmax (log2 domain) ----
        float mx0 = -INFINITY, mx1 = -INFINITY;
#pragma unroll
        for (int nt = 0; nt < 8; nt++) {
            mx0 = fmaxf(mx0, fmaxf(s[nt][0], s[nt][1]));
            mx1 = fmaxf(mx1, fmaxf(s[nt][2], s[nt][3]));
        }
        mx0 = fmaxf(mx0, __shfl_xor_sync(0xffffffffu, mx0, 1));
        mx0 = fmaxf(mx0, __shfl_xor_sync(0xffffffffu, mx0, 2));
        mx1 = fmaxf(mx1, __shfl_xor_sync(0xffffffffu, mx1, 1));
        mx1 = fmaxf(mx1, __shfl_xor_sync(0xffffffffu, mx1, 2));
        float mn0 = fmaxf(mrow0, mx0), mn1 = fmaxf(mrow1, mx1);
        float al0 = ex2f(mrow0 - mn0), al1 = ex2f(mrow1 - mn1);
        mrow0 = mn0; mrow1 = mn1;
#pragma unroll
        for (int dt = 0; dt < 8; dt++) {
            acc_o[dt][0] *= al0; acc_o[dt][1] *= al0;
            acc_o[dt][2] *= al1; acc_o[dt][3] *= al1;
        }
        lacc[0] *= al0; lacc[1] *= al0;
        lacc[2] *= al1; lacc[3] *= al1;

        uint32_t p0[8], p1[8];
#pragma unroll
        for (int nt = 0; nt < 8; nt++) {
            p0[nt] = ex2h2(packh(s[nt][0] - mn0, s[nt][1] - mn0));
            p1[nt] = ex2h2(packh(s[nt][2] - mn1, s[nt][3] - mn1));
        }

        // ---- l += P x ones, O += P V^T ----
#pragma unroll
        for (int kk = 0; kk < 4; kk++) {
            uint32_t aph[4];
            aph[0] = p0[2 * kk];     aph[1] = p1[2 * kk];
            aph[2] = p0[2 * kk + 1]; aph[3] = p1[2 * kk + 1];
            mma_f16(lacc, aph, ONES2);
            int vcol = jw * 64 + kk * 16 + kcol_b;
#pragma unroll
            for (int dt = 0; dt < 4; dt++) {
                uint32_t bvh[4];
                uint32_t off = (uint32_t)((dt * 16 + krow_l) * VROWB + vcol * 2);
                LDSM_X4(bvh, vH + off);
                mma_f16(acc_o[2 * dt],     aph, bvh);
                mma_f16(acc_o[2 * dt + 1], aph, bvh + 2);
            }
        }

        BAR_GROUP(barid);                       // group done reading stage jt&1
        if (jt + 2 < 8)      { ld_KV(jt + 2, jt & 1); CP_WAIT1(); }
        else if (jt + 1 < 8) { CP_WAIT0(); }
        BAR_GROUP(barid);                       // next stage visible in group
    }

    float lrow0 = lacc[0], lrow1 = lacc[2];

    // ---- merge the two j-halves via smem ----
    __syncthreads();
    float* mo = (float*)smem;
    float* ml = (float*)(smem + 64 * 68 * 4);
    float* ll = ml + 64;
    int r0 = wr + (lane >> 2);
    int cb = (lane & 3) * 2;

    if (jw == 1) {
#pragma unroll
        for (int dt = 0; dt < 8; dt++) {
            mo[r0 * 68 + dt * 8 + cb]           = acc_o[dt][0];
            mo[r0 * 68 + dt * 8 + cb + 1]       = acc_o[dt][1];
            mo[(r0 + 8) * 68 + dt * 8 + cb]     = acc_o[dt][2];
            mo[(r0 + 8) * 68 + dt * 8 + cb + 1] = acc_o[dt][3];
        }
        if ((lane & 3) == 0) {
            ml[r0] = mrow0; ml[r0 + 8] = mrow1;
            ll[r0] = lrow0; ll[r0 + 8] = lrow1;
        }
    }
    __syncthreads();
    if (jw == 0) {
        float mB0 = ml[r0],     lB0 = ll[r0];
        float mB1 = ml[r0 + 8], lB1 = ll[r0 + 8];
        float m0 = fmaxf(mrow0, mB0), m1 = fmaxf(mrow1, mB1);
        float a0 = ex2f(mrow0 - m0), b0 = ex2f(mB0 - m0);
        float a1 = ex2f(mrow1 - m1), b1 = ex2f(mB1 - m1);
        float inv0 = 1.f / (lrow0 * a0 + lB0 * b0);
        float inv1 = 1.f / (lrow1 * a1 + lB1 * b1);
        int cbase = h * DH + cb;
#pragma unroll
        for (int dt = 0; dt < 8; dt++) {
            float ox = (acc_o[dt][0] * a0 + mo[r0 * 68 + dt * 8 + cb]     * b0) * inv0;
            float oy = (acc_o[dt][1] * a0 + mo[r0 * 68 + dt * 8 + cb + 1] * b0) * inv0;
            size_t o0 = ((size_t)b * HW + i0 + r0) * C + cbase + dt * 8;
            *(uint32_t*)&g_AOTh[o0] = packh(ox, oy);
            ox = (acc_o[dt][2] * a1 + mo[(r0 + 8) * 68 + dt * 8 + cb]     * b1) * inv1;
            oy = (acc_o[dt][3] * a1 + mo[(r0 + 8) * 68 + dt * 8 + cb + 1] * b1) * inv1;
            size_t o1 = ((size_t)b * HW + i0 + r0 + 8) * C + cbase + dt * 8;
            *(uint32_t*)&g_AOTh[o1] = packh(ox, oy);
        }
    }
}

// =================== proj GEMM ================================================
__global__ __launch_bounds__(256, 2) void proj_gemm(const float* __restrict__ bias,
                                                    const float* __restrict__ resid,
                                                    float* __restrict__ out) {
    constexpr int BM = 128;
    extern __shared__ char smem[];

    const int tid = threadIdx.x;
    const int lane = tid & 31, wid = tid >> 5;
    const int wm = wid & 1, wn = wid >> 1;
    const int n0 = blockIdx.x * 128, m0 = blockIdx.y * 128;
    const int z = blockIdx.z;

    const __half* pA = g_WhP + (size_t)m0 * C;
    const __half* pB = g_AOTh + ((size_t)z * HW + n0) * C;

    auto load_chunk = [&](int stage, int k0) {
        char* sb = smem + stage * DSTG;
#pragma unroll
        for (int it = 0; it < 4; it++) {
            int idx = tid + it * 256;
            int row = idx >> 2, seg = idx & 3;
            const __half* src; int toff; int r;
            if (row < BM) { src = pA; toff = 0;     r = row; }
            else          { src = pB; toff = DTILE; r = row - BM; }
            CP_ASYNC16(smem_u32(sb + toff + r * ROWB + seg * 16),
                       src + (size_t)r * C + k0 + seg * 8);
        }
        CP_COMMIT();
    };

    float acc[4][4][4];
#pragma unroll
    for (int mi = 0; mi < 4; mi++)
#pragma unroll
        for (int ni = 0; ni < 4; ni++)
#pragma unroll
            for (int j = 0; j < 4; j++) acc[mi][ni][j] = 0.f;

    const int NCH = C / KC;
    load_chunk(0, 0);
    load_chunk(1, KC);
    load_chunk(2, 2 * KC);
#pragma unroll 1
    for (int c = 0; c < NCH; c++) {
        if (c <= NCH - 3)      CP_WAIT2();
        else if (c == NCH - 2) CP_WAIT1();
        else                   CP_WAIT0();
        __syncthreads();
        if (c + 3 < NCH) load_chunk((c + 3) & 3, (c + 3) * KC);
        char* sb = smem + (c & 3) * DSTG;
        uint32_t aH = smem_u32(sb);
        uint32_t bH = aH + DTILE;
#pragma unroll
        for (int ks = 0; ks < 2; ks++) {
            uint32_t ah[4][4], bh[4][2];
            int acol = ks * 16 + (lane >> 4) * 8;
#pragma unroll
            for (int mi = 0; mi < 4; mi++) {
                uint32_t off = (uint32_t)((wm * 64 + mi * 16 + (lane & 15)) * ROWB + acol * 2);
                LDSM_X4(ah[mi], aH + off);
            }
            int l = lane & 15;
            int bcol = ks * 16 + (l >> 3) * 8;
#pragma unroll
            for (int ni = 0; ni < 4; ni++) {
                uint32_t off = (uint32_t)((wn * 32 + ni * 8 + (l & 7)) * ROWB + bcol * 2);
                LDSM_X2(bh[ni], bH + off);
            }
#pragma unroll
            for (int mi = 0; mi < 4; mi++)
#pragma unroll
                for (int ni = 0; ni < 4; ni++)
                    mma_f16(acc[mi][ni], ah[mi], bh[ni]);
        }
    }

    float* po = out + (size_t)z * C * HW;
#pragma unroll
    for (int mi = 0; mi < 4; mi++)
#pragma unroll
        for (int ni = 0; ni < 4; ni++) {
            int col = n0 + wn * 32 + ni * 8 + (lane & 3) * 2;
#pragma unroll
            for (int hrow = 0; hrow < 2; hrow++) {
                int r = m0 + wm * 64 + mi * 16 + (lane >> 2) + hrow * 8;
                float bm = bias[r];
                size_t off = (size_t)r * HW + col;
                float2 rx = *(const float2*)&resid[(size_t)z * C * HW + off];
                float2 v;
                v.x = acc[mi][ni][hrow * 2 + 0] + bm + rx.x;
                v.y = acc[mi][ni][hrow * 2 + 1] + bm + rx.y;
                *(float2*)&po[off] = v;
            }
        }
}

// =================== launch ===================================================
extern "C" void kernel_launch(void* const* d_in, const int* in_sizes, int n_in,
                              void* d_out, int out_size) {
    const float* x      = (const float*)d_in[0];
    const float* gn_w   = (const float*)d_in[1];
    const float* gn_b   = (const float*)d_in[2];
    const float* qkv_w  = (const float*)d_in[3];
    const float* qkv_b  = (const float*)d_in[4];
    const float* proj_w = (const float*)d_in[5];
    const float* proj_b = (const float*)d_in[6];
    float* out = (float*)d_out;

    static bool init = false;
    if (!init) {
        cudaFuncSetAttribute(qkv_gemm, cudaFuncAttributeMaxDynamicSharedMemorySize, SMQKV);
        cudaFuncSetAttribute(proj_gemm, cudaFuncAttributeMaxDynamicSharedMemorySize, SMPROJ);
        cudaFuncSetAttribute(flash_kernel, cudaFuncAttributeMaxDynamicSharedMemorySize, FL_SMEM);
        init = true;
    }

    prep_kernel<<<1280, 256>>>(x, qkv_w, proj_w);
    convT_kernel<<<dim3(HW / 32, C / 32, B), dim3(32, 8)>>>(x, gn_w, gn_b);

    qkv_gemm<<<dim3(HW / 128, 3 * C / 128, B), 256, SMQKV>>>(qkv_b);

    flash_kernel<<<dim3(HW / 64, B * HEADS), 256, FL_SMEM>>>();

    proj_gemm<<<dim3(HW / 128, C / 128, B), 256, SMPROJ>>>(proj_b, x, out);
}

// round 12
// speedup vs baseline: 6.5214x; 1.0337x over previous
#include <cuda_runtime.h>
#include <cuda_fp16.h>
#include <cstdint>
#include <math.h>

#define B    8
#define C    512
#define HW   1024
#define G    32
#define CPG  16
#define HEADS 8
#define DH   64
#define EPS  1e-5f
#define QSCALE 0.1803368867f   // 0.125 * log2(e)

// ---------------- scratch (device globals) ----------------------------------
__device__ float2 g_stats[B * G];

__device__ __half g_WhQ[3 * C * C];
__device__ __half g_WhP[C * C];
__device__ __half g_XTh [B * HW * C];          // [b][n][c]
__device__ __half g_AOTh[B * HW * C];          // [b][i][c]
__device__ __half g_qTh [B * HEADS * HW * DH]; // [bh][i][d] (log2-scaled)
__device__ __half g_kTh [B * HEADS * HW * DH]; // [bh][j][d]
__device__ __half g_Vh  [B * HEADS * DH * HW]; // [bh][d][j]

// =================== helpers ==================================================
__device__ __forceinline__ uint32_t smem_u32(const void* p) {
    uint32_t r;
    asm("{ .reg .u64 t; cvta.to.shared.u64 t, %1; cvt.u32.u64 %0, t; }"
        : "=r"(r) : "l"(p));
    return r;
}
#define CP_ASYNC16(dst, src) \
    asm volatile("cp.async.cg.shared.global [%0], [%1], 16;" :: "r"(dst), "l"(src) : "memory")
#define CP_COMMIT() asm volatile("cp.async.commit_group;" ::: "memory")
#define CP_WAIT2()  asm volatile("cp.async.wait_group 2;" ::: "memory")
#define CP_WAIT1()  asm volatile("cp.async.wait_group 1;" ::: "memory")
#define CP_WAIT0()  asm volatile("cp.async.wait_group 0;" ::: "memory")
#define BAR_GROUP(id) asm volatile("bar.sync %0, %1;" :: "r"(id), "r"(128) : "memory")

#define LDSM_X4(r, addr) \
    asm volatile("ldmatrix.sync.aligned.m8n8.x4.shared.b16 {%0,%1,%2,%3}, [%4];" \
        : "=r"((r)[0]), "=r"((r)[1]), "=r"((r)[2]), "=r"((r)[3]) : "r"(addr))
#define LDSM_X2(r, addr) \
    asm volatile("ldmatrix.sync.aligned.m8n8.x2.shared.b16 {%0,%1}, [%2];" \
        : "=r"((r)[0]), "=r"((r)[1]) : "r"(addr))

__device__ __forceinline__ void mma_f16(float* c, const uint32_t* a, const uint32_t* b) {
    asm volatile(
        "mma.sync.aligned.m16n8k16.row.col.f32.f16.f16.f32 "
        "{%0,%1,%2,%3}, {%4,%5,%6,%7}, {%8,%9}, {%0,%1,%2,%3};"
        : "+f"(c[0]), "+f"(c[1]), "+f"(c[2]), "+f"(c[3])
        : "r"(a[0]), "r"(a[1]), "r"(a[2]), "r"(a[3]), "r"(b[0]), "r"(b[1]));
}
// f16-accumulate MMA: D,C packed half2 (2 regs)
__device__ __forceinline__ void mma_h16(uint32_t* c, const uint32_t* a, const uint32_t* b) {
    asm volatile(
        "mma.sync.aligned.m16n8k16.row.col.f16.f16.f16.f16 "
        "{%0,%1}, {%2,%3,%4,%5}, {%6,%7}, {%0,%1};"
        : "+r"(c[0]), "+r"(c[1])
        : "r"(a[0]), "r"(a[1]), "r"(a[2]), "r"(a[3]), "r"(b[0]), "r"(b[1]));
}
__device__ __forceinline__ uint32_t packh(float x, float y) {
    __half2 h = __floats2half2_rn(x, y);
    return *(uint32_t*)&h;
}
__device__ __forceinline__ float ex2f(float x) {
    float y;
    asm("ex2.approx.f32 %0, %1;" : "=f"(y) : "f"(x));
    return y;
}
__device__ __forceinline__ uint32_t ex2h2(uint32_t x) {
    uint32_t y;
    asm("ex2.approx.f16x2 %0, %1;" : "=r"(y) : "r"(x));
    return y;
}
__device__ __forceinline__ uint32_t hmax2u(uint32_t a, uint32_t b) {
    __half2 r = __hmax2(*(__half2*)&a, *(__half2*)&b);
    return *(uint32_t*)&r;
}
__device__ __forceinline__ uint32_t hmul2u(uint32_t a, uint32_t b) {
    __half2 r = __hmul2(*(__half2*)&a, *(__half2*)&b);
    return *(uint32_t*)&r;
}
__device__ __forceinline__ uint32_t hsub2u(uint32_t a, uint32_t b) {
    __half2 r = __hsub2(*(__half2*)&a, *(__half2*)&b);
    return *(uint32_t*)&r;
}

// =========== fused prologue: gn stats + both weight converts ==================
__global__ __launch_bounds__(256) void prep_kernel(const float* __restrict__ x,
                                                   const float* __restrict__ qkv_w,
                                                   const float* __restrict__ proj_w) {
    int blk = blockIdx.x;
    if (blk < 256) {
        const float4* xp = (const float4*)(x + (size_t)blk * CPG * HW);
        const int N4 = CPG * HW / 4;
        float s = 0.f, s2 = 0.f;
        for (int i = threadIdx.x; i < N4; i += 256) {
            float4 v = xp[i];
            s  += v.x + v.y + v.z + v.w;
            s2 += v.x * v.x + v.y * v.y + v.z * v.z + v.w * v.w;
        }
        __shared__ float sh1[8], sh2[8];
        int lane = threadIdx.x & 31, wid = threadIdx.x >> 5;
        for (int o = 16; o; o >>= 1) {
            s  += __shfl_down_sync(0xffffffffu, s,  o);
            s2 += __shfl_down_sync(0xffffffffu, s2, o);
        }
        if (lane == 0) { sh1[wid] = s; sh2[wid] = s2; }
        __syncthreads();
        if (threadIdx.x == 0) {
            for (int i = 1; i < 8; i++) { sh1[0] += sh1[i]; sh2[0] += sh2[i]; }
            const float N = CPG * HW;
            float mean = sh1[0] * (1.f / N);
            float var  = sh2[0] * (1.f / N) - mean * mean;
            g_stats[blk] = make_float2(mean, rsqrtf(var + EPS));
        }
    } else if (blk < 1024) {
        int i = (blk - 256) * 1024 + threadIdx.x * 4;
        float4 v = *(const float4*)&qkv_w[i];
        *(uint32_t*)&g_WhQ[i]     = packh(v.x, v.y);
        *(uint32_t*)&g_WhQ[i + 2] = packh(v.z, v.w);
    } else {
        int i = (blk - 1024) * 1024 + threadIdx.x * 4;
        float4 v = *(const float4*)&proj_w[i];
        *(uint32_t*)&g_WhP[i]     = packh(v.x, v.y);
        *(uint32_t*)&g_WhP[i + 2] = packh(v.z, v.w);
    }
}

// ===== fused GN-apply + transpose + convert ===================================
__global__ __launch_bounds__(256) void convT_kernel(const float* __restrict__ x,
                                                    const float* __restrict__ gw,
                                                    const float* __restrict__ gb) {
    __shared__ float t[32][33];
    int n0 = blockIdx.x * 32, c0 = blockIdx.y * 32, b = blockIdx.z;
    const float* ip = x + (size_t)b * C * HW;
    int tx = threadIdx.x, ty = threadIdx.y;
#pragma unroll
    for (int k = 0; k < 4; k++) {
        int ch = c0 + ty + k * 8;
        float2 st = g_stats[b * G + (ch >> 4)];
        float v = ip[(size_t)ch * HW + n0 + tx];
        t[ty + k * 8][tx] = (v - st.x) * st.y * gw[ch] + gb[ch];
    }
    __syncthreads();
#pragma unroll
    for (int k = 0; k < 4; k++) {
        int ni = ty + k * 8;
        size_t o = (size_t)b * HW * C + (size_t)(n0 + ni) * C + c0 + tx;
        g_XTh[o] = __float2half(t[tx][ni]);
    }
}

// =================== dense GEMM config (4-stage, 2 CTA/SM) ====================
#define KC    32
#define ROWB  80
#define DTILE (128 * ROWB)
#define DSTG  (2 * DTILE)
#define SMQKV 81920
#define SMPROJ 81920

// =================== QKV GEMM =================================================
__global__ __launch_bounds__(256, 2) void qkv_gemm(const float* __restrict__ bias) {
    constexpr int BM = 128;
    extern __shared__ char smem[];

    const int tid = threadIdx.x;
    const int lane = tid & 31, wid = tid >> 5;
    const int wm = wid & 1, wn = wid >> 1;
    const int n0 = blockIdx.x * 128, m0 = blockIdx.y * 128;
    const int z = blockIdx.z;

    const __half* pA = g_WhQ + (size_t)m0 * C;
    const __half* pB = g_XTh + ((size_t)z * HW + n0) * C;

    auto load_chunk = [&](int stage, int k0) {
        char* sb = smem + stage * DSTG;
#pragma unroll
        for (int it = 0; it < 4; it++) {
            int idx = tid + it * 256;
            int row = idx >> 2, seg = idx & 3;
            const __half* src; int toff; int r;
            if (row < BM) { src = pA; toff = 0;     r = row; }
            else          { src = pB; toff = DTILE; r = row - BM; }
            CP_ASYNC16(smem_u32(sb + toff + r * ROWB + seg * 16),
                       src + (size_t)r * C + k0 + seg * 8);
        }
        CP_COMMIT();
    };

    float acc[4][4][4];
#pragma unroll
    for (int mi = 0; mi < 4; mi++)
#pragma unroll
        for (int ni = 0; ni < 4; ni++)
#pragma unroll
            for (int j = 0; j < 4; j++) acc[mi][ni][j] = 0.f;

    const int NCH = C / KC;
    load_chunk(0, 0);
    load_chunk(1, KC);
    load_chunk(2, 2 * KC);
#pragma unroll 1
    for (int c = 0; c < NCH; c++) {
        if (c <= NCH - 3)      CP_WAIT2();
        else if (c == NCH - 2) CP_WAIT1();
        else                   CP_WAIT0();
        __syncthreads();
        if (c + 3 < NCH) load_chunk((c + 3) & 3, (c + 3) * KC);
        char* sb = smem + (c & 3) * DSTG;
        uint32_t aH = smem_u32(sb);
        uint32_t bH = aH + DTILE;
#pragma unroll
        for (int ks = 0; ks < 2; ks++) {
            uint32_t ah[4][4], bh[4][2];
            int acol = ks * 16 + (lane >> 4) * 8;
#pragma unroll
            for (int mi = 0; mi < 4; mi++) {
                uint32_t off = (uint32_t)((wm * 64 + mi * 16 + (lane & 15)) * ROWB + acol * 2);
                LDSM_X4(ah[mi], aH + off);
            }
            int l = lane & 15;
            int bcol = ks * 16 + (l >> 3) * 8;
#pragma unroll
            for (int ni = 0; ni < 4; ni++) {
                uint32_t off = (uint32_t)((wn * 32 + ni * 8 + (l & 7)) * ROWB + bcol * 2);
                LDSM_X2(bh[ni], bH + off);
            }
#pragma unroll
            for (int mi = 0; mi < 4; mi++)
#pragma unroll
                for (int ni = 0; ni < 4; ni++)
                    mma_f16(acc[mi][ni], ah[mi], bh[ni]);
        }
    }

    const int sec = m0 >> 9;
    const float scale = (sec == 0) ? QSCALE : 1.0f;

    __syncthreads();
    if (sec == 2) {
#pragma unroll
        for (int mi = 0; mi < 4; mi++)
#pragma unroll
            for (int ni = 0; ni < 4; ni++) {
                int col = wn * 32 + ni * 8 + (lane & 3) * 2;
#pragma unroll
                for (int hrow = 0; hrow < 2; hrow++) {
                    int r = wm * 64 + mi * 16 + (lane >> 2) + hrow * 8;
                    int mC = (m0 - 1024) + r;
                    float bm = bias[m0 + r];
                    size_t o = ((size_t)(z * HEADS + (mC >> 6)) * DH + (mC & 63)) * HW + n0 + col;
                    *(uint32_t*)&g_Vh[o] = packh(acc[mi][ni][hrow * 2 + 0] + bm,
                                                 acc[mi][ni][hrow * 2 + 1] + bm);
                }
            }
    } else {
        float* ts = (float*)smem;
#pragma unroll
        for (int mi = 0; mi < 4; mi++)
#pragma unroll
            for (int ni = 0; ni < 4; ni++) {
                int col = wn * 32 + ni * 8 + (lane & 3) * 2;
#pragma unroll
                for (int hrow = 0; hrow < 2; hrow++) {
                    int r = wm * 64 + mi * 16 + (lane >> 2) + hrow * 8;
                    float bm = bias[m0 + r];
                    ts[r * 132 + col]     = (acc[mi][ni][hrow * 2 + 0] + bm) * scale;
                    ts[r * 132 + col + 1] = (acc[mi][ni][hrow * 2 + 1] + bm) * scale;
                }
            }
        __syncthreads();
        __half* oh = sec ? g_kTh : g_qTh;
        int h0 = (m0 & 511) >> 6;
#pragma unroll
        for (int it = 0; it < 32; it++) {
            int e = tid + it * 256;
            int i = e & 127;
            int rest = e >> 7;
            int hh = rest & 1, dp = rest >> 1;
            float a  = ts[(hh * 64 + dp * 2)     * 132 + i];
            float bb = ts[(hh * 64 + dp * 2 + 1) * 132 + i];
            size_t o = ((size_t)(z * HEADS + h0 + hh) * HW + n0 + i) * DH + dp * 2;
            *(uint32_t*)&oh[o] = packh(a, bb);
        }
    }
}

// =================== flash attention (f16 accumulators) =======================
#define QROWB   144
#define VROWB   272
#define FQ_TILE 9216
#define FK_TILE 18432
#define FV_TILE 17408
#define FL_STAGEB (FK_TILE + FV_TILE)
#define FL_SMEM (FQ_TILE + 2 * FL_STAGEB) // 80896

__global__ __launch_bounds__(256, 2) void flash_kernel() {
    extern __shared__ char smem[];
    const int tid = threadIdx.x, lane = tid & 31, wid = tid >> 5;
    const int wm = wid & 3;
    const int jw = wid >> 2;
    const int gtid = tid & 127;
    const int barid = 1 + jw;
    const int i0 = blockIdx.x * 64;
    const int bh = blockIdx.y;
    const int b = bh >> 3, h = bh & 7;
    const int wr = wm * 16;
    const uint32_t ONES2[2] = {0x3C003C00u, 0x3C003C00u};

    auto ld_Q = [&]() {
#pragma unroll
        for (int it = 0; it < 2; it++) {
            int idx = tid + it * 256;
            int r = idx >> 3, seg = idx & 7;
            const __half* src = g_qTh + ((size_t)bh * HW + i0 + r) * DH + seg * 8;
            CP_ASYNC16(smem_u32(smem + r * QROWB + seg * 16), src);
        }
    };
    auto ld_KV = [&](int jt, int st) {
        char* sb = smem + FQ_TILE + st * FL_STAGEB;
        int j0 = jt * 128;
#pragma unroll
        for (int it = 0; it < 4; it++) {
            int idx = gtid + it * 128;
            int r = jw * 64 + (idx >> 3), seg = idx & 7;
            const __half* src = g_kTh + ((size_t)bh * HW + j0 + r) * DH + seg * 8;
            CP_ASYNC16(smem_u32(sb + r * QROWB + seg * 16), src);
        }
#pragma unroll
        for (int it = 0; it < 4; it++) {
            int idx = gtid + it * 128;
            int r = idx >> 3, seg = jw * 8 + (idx & 7);
            const __half* src = g_Vh + ((size_t)bh * DH + r) * HW + j0 + seg * 8;
            CP_ASYNC16(smem_u32(sb + FK_TILE + r * VROWB + seg * 16), src);
        }
        CP_COMMIT();
    };

    uint32_t acc_o[8][2];     // O accum, half2: [0]=rows lo, [1]=rows hi
#pragma unroll
    for (int dt = 0; dt < 8; dt++) { acc_o[dt][0] = 0u; acc_o[dt][1] = 0u; }
    uint32_t lacc[2] = {0u, 0u};
    float mrow0 = -INFINITY, mrow1 = -INFINITY;

    const uint32_t qH = smem_u32(smem);

    ld_Q(); ld_KV(0, 0); CP_COMMIT();
    ld_KV(1, 1);
    CP_WAIT1();
    __syncthreads();

    uint32_t qa[4][4];
#pragma unroll
    for (int ks = 0; ks < 4; ks++) {
        uint32_t aoff = (uint32_t)((wr + (lane & 15)) * QROWB +
                                   (ks * 16 + (lane >> 4) * 8) * 2);
        LDSM_X4(qa[ks], qH + aoff);
    }

    const int krow_l = ((lane >> 4) << 3) + (lane & 7);
    const int kcol_b = ((lane >> 3) & 1) * 8;

#pragma unroll 1
    for (int jt = 0; jt < 8; jt++) {
        uint32_t kb = smem_u32(smem + FQ_TILE + (jt & 1) * FL_STAGEB);
        uint32_t kH = kb;
        uint32_t vH = kb + FK_TILE;

        // ---- S = q k^T, f16 accum: s[nt][0]=rows lo, [1]=rows hi (half2 cols)
        uint32_t s[8][2];
#pragma unroll
        for (int nt = 0; nt < 8; nt++) { s[nt][0] = 0u; s[nt][1] = 0u; }

#pragma unroll
        for (int ks = 0; ks < 4; ks++) {
            int kcol = ks * 16 + kcol_b;
#pragma unroll
            for (int ntp = 0; ntp < 4; ntp++) {
                uint32_t bh_[4];
                uint32_t boff = (uint32_t)((jw * 64 + ntp * 16 + krow_l) * QROWB + kcol * 2);
                LDSM_X4(bh_, kH + boff);
                // two n8 halves -> D rows lo/hi each packed
                uint32_t a0[4] = {qa[ks][0], qa[ks][1], qa[ks][2], qa[ks][3]};
                // n8 group 0
                {
                    uint32_t d0[2] = {s[2 * ntp][0], s[2 * ntp][1]};
                    mma_h16(d0, a0, bh_);
                    s[2 * ntp][0] = d0[0]; s[2 * ntp][1] = d0[1];
                }
                // n8 group 1
                {
                    uint32_t d1[2] = {s[2 * ntp + 1][0], s[2 * ntp + 1][1]};
                    mma_h16(d1, a0, bh_ + 2);
                    s[2 * ntp + 1][0] = d1[0]; s[2 * ntp + 1][1] = d1[1];
                }
            }
        }

        // ---- online softmax (log2 domain, half2) ----
        uint32_t m0p = s[0][0], m1p = s[0][1];
#pragma unroll
        for (int nt = 1; nt < 8; nt++) {
            m0p = hmax2u(m0p, s[nt][0]);
            m1p = hmax2u(m1p, s[nt][1]);
        }
        m0p = hmax2u(m0p, __shfl_xor_sync(0xffffffffu, m0p, 1));
        m0p = hmax2u(m0p, __shfl_xor_sync(0xffffffffu, m0p, 2));
        m1p = hmax2u(m1p, __shfl_xor_sync(0xffffffffu, m1p, 1));
        m1p = hmax2u(m1p, __shfl_xor_sync(0xffffffffu, m1p, 2));
        __half2 m0h = *(__half2*)&m0p, m1h = *(__half2*)&m1p;
        float mx0 = __half2float(__hmax(__low2half(m0h), __high2half(m0h)));
        float mx1 = __half2float(__hmax(__low2half(m1h), __high2half(m1h)));
        float mn0 = fmaxf(mrow0, mx0), mn1 = fmaxf(mrow1, mx1);
        float al0 = ex2f(mrow0 - mn0), al1 = ex2f(mrow1 - mn1);
        mrow0 = mn0; mrow1 = mn1;
        uint32_t al02 = packh(al0, al0), al12 = packh(al1, al1);
#pragma unroll
        for (int dt = 0; dt < 8; dt++) {
            acc_o[dt][0] = hmul2u(acc_o[dt][0], al02);
            acc_o[dt][1] = hmul2u(acc_o[dt][1], al12);
        }
        lacc[0] = hmul2u(lacc[0], al02);
        lacc[1] = hmul2u(lacc[1], al12);

        // exp in place: p = 2^(s - mn)
        uint32_t mn02 = packh(mn0, mn0), mn12 = packh(mn1, mn1);
#pragma unroll
        for (int nt = 0; nt < 8; nt++) {
            s[nt][0] = ex2h2(hsub2u(s[nt][0], mn02));
            s[nt][1] = ex2h2(hsub2u(s[nt][1], mn12));
        }

        // ---- l += P x ones, O += P V^T (f16 accum) ----
#pragma unroll
        for (int kk = 0; kk < 4; kk++) {
            uint32_t aph[4];
            aph[0] = s[2 * kk][0];     aph[1] = s[2 * kk][1];
            aph[2] = s[2 * kk + 1][0]; aph[3] = s[2 * kk + 1][1];
            mma_h16(lacc, aph, ONES2);
            int vcol = jw * 64 + kk * 16 + kcol_b;
#pragma unroll
            for (int dt = 0; dt < 4; dt++) {
                uint32_t bvh[4];
                uint32_t off = (uint32_t)((dt * 16 + krow_l) * VROWB + vcol * 2);
                LDSM_X4(bvh, vH + off);
                mma_h16(acc_o[2 * dt],     aph, bvh);
                mma_h16(acc_o[2 * dt + 1], aph, bvh + 2);
            }
        }

        BAR_GROUP(barid);
        if (jt + 2 < 8)      { ld_KV(jt + 2, jt & 1); CP_WAIT1(); }
        else if (jt + 1 < 8) { CP_WAIT0(); }
        BAR_GROUP(barid);
    }

    float lrow0 = __half2float(__low2half(*(__half2*)&lacc[0]));
    float lrow1 = __half2float(__low2half(*(__half2*)&lacc[1]));

    // unpack O accum to fp32 for the merge
    float ao[8][4];
#pragma unroll
    for (int dt = 0; dt < 8; dt++) {
        float2 lo = __half22float2(*(__half2*)&acc_o[dt][0]);
        float2 hi = __half22float2(*(__half2*)&acc_o[dt][1]);
        ao[dt][0] = lo.x; ao[dt][1] = lo.y;
        ao[dt][2] = hi.x; ao[dt][3] = hi.y;
    }

    // ---- merge the two j-halves via smem ----
    __syncthreads();
    float* mo = (float*)smem;
    float* ml = (float*)(smem + 64 * 68 * 4);
    float* ll = ml + 64;
    int r0 = wr + (lane >> 2);
    int cb = (lane & 3) * 2;

    if (jw == 1) {
#pragma unroll
        for (int dt = 0; dt < 8; dt++) {
            mo[r0 * 68 + dt * 8 + cb]           = ao[dt][0];
            mo[r0 * 68 + dt * 8 + cb + 1]       = ao[dt][1];
            mo[(r0 + 8) * 68 + dt * 8 + cb]     = ao[dt][2];
            mo[(r0 + 8) * 68 + dt * 8 + cb + 1] = ao[dt][3];
        }
        if ((lane & 3) == 0) {
            ml[r0] = mrow0; ml[r0 + 8] = mrow1;
            ll[r0] = lrow0; ll[r0 + 8] = lrow1;
        }
    }
    __syncthreads();
    if (jw == 0) {
        float mB0 = ml[r0],     lB0 = ll[r0];
        float mB1 = ml[r0 + 8], lB1 = ll[r0 + 8];
        float m0 = fmaxf(mrow0, mB0), m1 = fmaxf(mrow1, mB1);
        float a0 = ex2f(mrow0 - m0), b0 = ex2f(mB0 - m0);
        float a1 = ex2f(mrow1 - m1), b1 = ex2f(mB1 - m1);
        float inv0 = 1.f / (lrow0 * a0 + lB0 * b0);
        float inv1 = 1.f / (lrow1 * a1 + lB1 * b1);
        int cbase = h * DH + cb;
#pragma unroll
        for (int dt = 0; dt < 8; dt++) {
            float ox = (ao[dt][0] * a0 + mo[r0 * 68 + dt * 8 + cb]     * b0) * inv0;
            float oy = (ao[dt][1] * a0 + mo[r0 * 68 + dt * 8 + cb + 1] * b0) * inv0;
            size_t o0 = ((size_t)b * HW + i0 + r0) * C + cbase + dt * 8;
            *(uint32_t*)&g_AOTh[o0] = packh(ox, oy);
            ox = (ao[dt][2] * a1 + mo[(r0 + 8) * 68 + dt * 8 + cb]     * b1) * inv1;
            oy = (ao[dt][3] * a1 + mo[(r0 + 8) * 68 + dt * 8 + cb + 1] * b1) * inv1;
            size_t o1 = ((size_t)b * HW + i0 + r0 + 8) * C + cbase + dt * 8;
            *(uint32_t*)&g_AOTh[o1] = packh(ox, oy);
        }
    }
}

// =================== proj GEMM ================================================
__global__ __launch_bounds__(256, 2) void proj_gemm(const float* __restrict__ bias,
                                                    const float* __restrict__ resid,
                                                    float* __restrict__ out) {
    constexpr int BM = 128;
    extern __shared__ char smem[];

    const int tid = threadIdx.x;
    const int lane = tid & 31, wid = tid >> 5;
    const int wm = wid & 1, wn = wid >> 1;
    const int n0 = blockIdx.x * 128, m0 = blockIdx.y * 128;
    const int z = blockIdx.z;

    const __half* pA = g_WhP + (size_t)m0 * C;
    const __half* pB = g_AOTh + ((size_t)z * HW + n0) * C;

    auto load_chunk = [&](int stage, int k0) {
        char* sb = smem + stage * DSTG;
#pragma unroll
        for (int it = 0; it < 4; it++) {
            int idx = tid + it * 256;
            int row = idx >> 2, seg = idx & 3;
            const __half* src; int toff; int r;
            if (row < BM) { src = pA; toff = 0;     r = row; }
            else          { src = pB; toff = DTILE; r = row - BM; }
            CP_ASYNC16(smem_u32(sb + toff + r * ROWB + seg * 16),
                       src + (size_t)r * C + k0 + seg * 8);
        }
        CP_COMMIT();
    };

    float acc[4][4][4];
#pragma unroll
    for (int mi = 0; mi < 4; mi++)
#pragma unroll
        for (int ni = 0; ni < 4; ni++)
#pragma unroll
            for (int j = 0; j < 4; j++) acc[mi][ni][j] = 0.f;

    const int NCH = C / KC;
    load_chunk(0, 0);
    load_chunk(1, KC);
    load_chunk(2, 2 * KC);
#pragma unroll 1
    for (int c = 0; c < NCH; c++) {
        if (c <= NCH - 3)      CP_WAIT2();
        else if (c == NCH - 2) CP_WAIT1();
        else                   CP_WAIT0();
        __syncthreads();
        if (c + 3 < NCH) load_chunk((c + 3) & 3, (c + 3) * KC);
        char* sb = smem + (c & 3) * DSTG;
        uint32_t aH = smem_u32(sb);
        uint32_t bH = aH + DTILE;
#pragma unroll
        for (int ks = 0; ks < 2; ks++) {
            uint32_t ah[4][4], bh[4][2];
            int acol = ks * 16 + (lane >> 4) * 8;
#pragma unroll
            for (int mi = 0; mi < 4; mi++) {
                uint32_t off = (uint32_t)((wm * 64 + mi * 16 + (lane & 15)) * ROWB + acol * 2);
                LDSM_X4(ah[mi], aH + off);
            }
            int l = lane & 15;
            int bcol = ks * 16 + (l >> 3) * 8;
#pragma unroll
            for (int ni = 0; ni < 4; ni++) {
                uint32_t off = (uint32_t)((wn * 32 + ni * 8 + (l & 7)) * ROWB + bcol * 2);
                LDSM_X2(bh[ni], bH + off);
            }
#pragma unroll
            for (int mi = 0; mi < 4; mi++)
#pragma unroll
                for (int ni = 0; ni < 4; ni++)
                    mma_f16(acc[mi][ni], ah[mi], bh[ni]);
        }
    }

    float* po = out + (size_t)z * C * HW;
#pragma unroll
    for (int mi = 0; mi < 4; mi++)
#pragma unroll
        for (int ni = 0; ni < 4; ni++) {
            int col = n0 + wn * 32 + ni * 8 + (lane & 3) * 2;
#pragma unroll
            for (int hrow = 0; hrow < 2; hrow++) {
                int r = m0 + wm * 64 + mi * 16 + (lane >> 2) + hrow * 8;
                float bm = bias[r];
                size_t off = (size_t)r * HW + col;
                float2 rx = *(const float2*)&resid[(size_t)z * C * HW + off];
                float2 v;
                v.x = acc[mi][ni][hrow * 2 + 0] + bm + rx.x;
                v.y = acc[mi][ni][hrow * 2 + 1] + bm + rx.y;
                *(float2*)&po[off] = v;
            }
        }
}

// =================== launch ===================================================
extern "C" void kernel_launch(void* const* d_in, const int* in_sizes, int n_in,
                              void* d_out, int out_size) {
    const float* x      = (const float*)d_in[0];
    const float* gn_w   = (const float*)d_in[1];
    const float* gn_b   = (const float*)d_in[2];
    const float* qkv_w  = (const float*)d_in[3];
    const float* qkv_b  = (const float*)d_in[4];
    const float* proj_w = (const float*)d_in[5];
    const float* proj_b = (const float*)d_in[6];
    float* out = (float*)d_out;

    static bool init = false;
    if (!init) {
        cudaFuncSetAttribute(qkv_gemm, cudaFuncAttributeMaxDynamicSharedMemorySize, SMQKV);
        cudaFuncSetAttribute(proj_gemm, cudaFuncAttributeMaxDynamicSharedMemorySize, SMPROJ);
        cudaFuncSetAttribute(flash_kernel, cudaFuncAttributeMaxDynamicSharedMemorySize, FL_SMEM);
        init = true;
    }

    prep_kernel<<<1280, 256>>>(x, qkv_w, proj_w);
    convT_kernel<<<dim3(HW / 32, C / 32, B), dim3(32, 8)>>>(x, gn_w, gn_b);

    qkv_gemm<<<dim3(HW / 128, 3 * C / 128, B), 256, SMQKV>>>(qkv_b);

    flash_kernel<<<dim3(HW / 64, B * HEADS), 256, FL_SMEM>>>();

    proj_gemm<<<dim3(HW / 128, C / 128, B), 256, SMPROJ>>>(proj_b, x, out);
}